// round 1
// baseline (speedup 1.0000x reference)
#include <cuda_runtime.h>
#include <math.h>

// ---------------- problem constants ----------------
#define BATCH 4
#define DM    192          // d_model
#define DI    384          // d_inner
#define DS    16           // d_state
#define DR    12           // dt_rank
#define NSEQ  1024         // H*W
#define LROWS 4096         // BATCH*NSEQ
#define NDIR  4
#define DBL_W 44           // DR + 2*DS

// ---------------- scratch (static device memory: allocation-free) ----------------
__device__ float g_xs  [LROWS*DM];            // layernormed input (also residual)
__device__ float g_xp  [LROWS*DM];            // after in_proj
__device__ float g_seqs[NDIR*LROWS*DM];       // 4 direction-ordered sequences
__device__ float g_xz  [(long)NDIR*LROWS*2*DI]; // in_proj per direction (xh | z)
__device__ float g_xsm [NDIR*LROWS*DI];       // silu(conv(xh))
__device__ float g_dbl [NDIR*LROWS*DBL_W];    // x_proj output (dt_raw | B | C)
__device__ float g_dt  [NDIR*LROWS*DI];       // softplus(dt_proj)
__device__ float g_y   [NDIR*LROWS*DI];       // scan output (gated)
__device__ float g_yo  [NDIR*LROWS*DM];       // out_proj per direction
__device__ float g_fused[LROWS*4*DM];         // concat of 4 directions (re-aligned)
__device__ float g_hdn [LROWS*2*DM];
__device__ float g_h2  [LROWS*DM];
__device__ float g_h3  [LROWS*DM];

// ---------------- generic fp32 GEMM:  C = act(A @ W^T + bias) ----------------
// A: M x K (row stride lda), W: Nn x K (row-major), C: M x Nn (row stride ldc)
// batched over blockIdx.z with element strides sA/sW/sB/sC.
// act: 0 = none, 1 = softplus, 2 = exact gelu
__global__ __launch_bounds__(256) void gemm_kernel(
    const float* __restrict__ A, const float* __restrict__ W,
    const float* __restrict__ bias, float* __restrict__ C,
    int M, int Nn, int K, int lda, int ldc,
    long sA, long sW, long sB, long sC, int act)
{
    const int z = blockIdx.z;
    A += z * sA; W += z * sW; C += z * sC;
    const float* bz = bias ? (bias + z * sB) : (const float*)0;

    __shared__ float As[16][68];
    __shared__ float Ws[16][68];

    const int bm = blockIdx.y << 6, bn = blockIdx.x << 6;
    const int tid = threadIdx.x;
    const int tx = tid & 15, ty = tid >> 4;

    float acc[4][4];
#pragma unroll
    for (int i = 0; i < 4; i++)
#pragma unroll
        for (int j = 0; j < 4; j++) acc[i][j] = 0.f;

    const int nkt = (K + 15) >> 4;
    for (int kt = 0; kt < nkt; kt++) {
        const int k0 = kt << 4;
#pragma unroll
        for (int i = 0; i < 4; i++) {
            int idx = tid + (i << 8);          // 0..1023
            int r = idx >> 4, kk = idx & 15;
            int gk = k0 + kk;
            // M is always a multiple of 64 here, no gm guard needed
            As[kk][r] = (gk < K) ? A[(long)(bm + r) * lda + gk] : 0.f;
            int gn = bn + r;
            Ws[kk][r] = (gn < Nn && gk < K) ? W[(long)gn * K + gk] : 0.f;
        }
        __syncthreads();
#pragma unroll
        for (int kk = 0; kk < 16; kk++) {
            float a0 = As[kk][(ty<<2)+0], a1 = As[kk][(ty<<2)+1];
            float a2 = As[kk][(ty<<2)+2], a3 = As[kk][(ty<<2)+3];
            float w0 = Ws[kk][(tx<<2)+0], w1 = Ws[kk][(tx<<2)+1];
            float w2 = Ws[kk][(tx<<2)+2], w3 = Ws[kk][(tx<<2)+3];
            acc[0][0] = fmaf(a0,w0,acc[0][0]); acc[0][1] = fmaf(a0,w1,acc[0][1]);
            acc[0][2] = fmaf(a0,w2,acc[0][2]); acc[0][3] = fmaf(a0,w3,acc[0][3]);
            acc[1][0] = fmaf(a1,w0,acc[1][0]); acc[1][1] = fmaf(a1,w1,acc[1][1]);
            acc[1][2] = fmaf(a1,w2,acc[1][2]); acc[1][3] = fmaf(a1,w3,acc[1][3]);
            acc[2][0] = fmaf(a2,w0,acc[2][0]); acc[2][1] = fmaf(a2,w1,acc[2][1]);
            acc[2][2] = fmaf(a2,w2,acc[2][2]); acc[2][3] = fmaf(a2,w3,acc[2][3]);
            acc[3][0] = fmaf(a3,w0,acc[3][0]); acc[3][1] = fmaf(a3,w1,acc[3][1]);
            acc[3][2] = fmaf(a3,w2,acc[3][2]); acc[3][3] = fmaf(a3,w3,acc[3][3]);
        }
        __syncthreads();
    }

#pragma unroll
    for (int i = 0; i < 4; i++) {
        const int gm = bm + (ty << 2) + i;
#pragma unroll
        for (int j = 0; j < 4; j++) {
            const int gn = bn + (tx << 2) + j;
            if (gn < Nn) {
                float v = acc[i][j];
                if (bz) v += bz[gn];
                if (act == 1) {                 // softplus
                    v = (v > 20.f) ? v : log1pf(__expf(v));
                } else if (act == 2) {          // exact gelu
                    v = 0.5f * v * (1.f + erff(v * 0.70710678118654752f));
                }
                C[(long)gm * ldc + gn] = v;
            }
        }
    }
}

// ---------------- kernel 1: transpose + layernorm (x: (B,192,1024) -> xs: (B,1024,192)) ----------------
__global__ __launch_bounds__(256) void ln1_kernel(
    const float* __restrict__ x, const float* __restrict__ g, const float* __restrict__ bb)
{
    __shared__ float tile[DM][33];
    __shared__ float s_mean[32], s_rstd[32];
    const int b = blockIdx.y, n0 = blockIdx.x << 5;
    const int tid = threadIdx.x;

    for (int i = tid; i < DM * 32; i += 256) {
        int d = i >> 5, nn = i & 31;
        tile[d][nn] = x[((long)(b * DM + d) << 10) + n0 + nn];
    }
    __syncthreads();

    const int nn = tid >> 3, l = tid & 7;       // 8 lanes reduce one n
    float s = 0.f, s2 = 0.f;
    for (int d = l; d < DM; d += 8) { float v = tile[d][nn]; s += v; s2 = fmaf(v, v, s2); }
    s  += __shfl_down_sync(0xffffffffu, s,  4, 8);
    s2 += __shfl_down_sync(0xffffffffu, s2, 4, 8);
    s  += __shfl_down_sync(0xffffffffu, s,  2, 8);
    s2 += __shfl_down_sync(0xffffffffu, s2, 2, 8);
    s  += __shfl_down_sync(0xffffffffu, s,  1, 8);
    s2 += __shfl_down_sync(0xffffffffu, s2, 1, 8);
    if (l == 0) {
        float m = s * (1.f / DM);
        float var = s2 * (1.f / DM) - m * m;
        s_mean[nn] = m;
        s_rstd[nn] = rsqrtf(var + 1e-5f);
    }
    __syncthreads();

    for (int i = tid; i < DM * 32; i += 256) {
        int nn2 = i / DM, d = i % DM;
        float v = (tile[d][nn2] - s_mean[nn2]) * s_rstd[nn2] * g[d] + bb[d];
        g_xs[((long)(b << 10) + n0 + nn2) * DM + d] = v;
    }
}

// ---------------- direction index maps ----------------
__device__ __forceinline__ int seq_src_n(int d, int t) {
    // n in the (b,n) row-major layout that produced sequence position t of direction d
    if (d == 0) return t;
    if (d == 1) return NSEQ - 1 - t;
    if (d == 2) return ((t & 31) << 5) + (t >> 5);
    int u = NSEQ - 1 - t;
    return ((u & 31) << 5) + (u >> 5);
}
__device__ __forceinline__ int fused_src_t(int d, int n) {
    // sequence position t of direction d that lands at spatial position n of the output
    if (d == 0) return n;
    if (d == 1) return NSEQ - 1 - n;
    if (d == 2) return ((n & 31) << 5) + (n >> 5);
    return NSEQ - 1 - (((n & 31) << 5) + (n >> 5));
}

__global__ __launch_bounds__(256) void build_seqs_kernel() {
    long i = (long)blockIdx.x * 256 + threadIdx.x;
    if (i >= (long)NDIR * LROWS * DM) return;
    int cc = (int)(i % DM);
    long r = i / DM;
    int t = (int)(r % NSEQ);
    long db = r / NSEQ;
    int d = (int)(db >> 2), b = (int)(db & 3);
    int n = seq_src_n(d, t);
    g_seqs[i] = g_xp[((long)(b << 10) + n) * DM + cc];
}

__global__ __launch_bounds__(256) void build_fused_kernel() {
    long i = (long)blockIdx.x * 256 + threadIdx.x;
    if (i >= (long)LROWS * 4 * DM) return;
    int col = (int)(i % (4 * DM));
    long row = i / (4 * DM);                 // b*1024 + n
    int d = col / DM, cc = col % DM;
    int n = (int)(row % NSEQ);
    int b = (int)(row / NSEQ);
    int t = fused_src_t(d, n);
    g_fused[i] = g_yo[((long)((d << 2) + b) * NSEQ + t) * DM + cc];
}

// ---------------- causal depthwise conv (width 4) + silu ----------------
__global__ __launch_bounds__(256) void conv_silu_kernel(
    const float* __restrict__ cw, const float* __restrict__ cb)
{
    long i = (long)blockIdx.x * 256 + threadIdx.x;
    if (i >= (long)NDIR * BATCH * NSEQ * DI) return;
    int c = (int)(i % DI);
    long r = i / DI;                         // (d*4+b)*1024 + t
    int t = (int)(r % NSEQ);
    long db = r / NSEQ;
    int d = (int)(db >> 2);
    const float* w = cw + ((long)d * DI + c) * 4;
    float acc = cb[d * DI + c];
    const float* src = g_xz + (r - t) * (2 * DI) + c;   // start of this (d,b) sequence, channel c
#pragma unroll
    for (int j = 0; j < 4; j++) {
        int tt = t - 3 + j;
        if (tt >= 0) acc = fmaf(w[j], src[(long)tt * (2 * DI)], acc);
    }
    g_xsm[r * DI + c] = acc / (1.f + __expf(-acc));
}

// ---------------- sequential selective scan ----------------
// grid (3, BATCH, NDIR), 128 threads: one thread per channel; 16 states in registers.
#define CH 16   // timesteps staged per chunk
__global__ __launch_bounds__(128) void scan_kernel(
    const float* __restrict__ Alog, const float* __restrict__ Dp)
{
    const int d = blockIdx.z, b = blockIdx.y;
    const int c0 = blockIdx.x << 7;
    const int tid = threadIdx.x;
    const int c = c0 + tid;
    const long db = d * BATCH + b;
    const long baseI = db * NSEQ;

    const float* dtb  = g_dt  + baseI * DI       + c0;
    const float* xb   = g_xsm + baseI * DI       + c0;
    const float* zb   = g_xz  + baseI * (2 * DI) + DI + c0;
    const float* dblp = g_dbl + baseI * DBL_W;
    float* yb         = g_y   + baseI * DI       + c0;

    float Aa[DS];
#pragma unroll
    for (int s = 0; s < DS; s++)
        Aa[s] = -expf(Alog[((long)(d * DI + c)) * DS + s]);
    const float Dv = Dp[d * DI + c];

    float h[DS];
#pragma unroll
    for (int s = 0; s < DS; s++) h[s] = 0.f;

    __shared__ float s_bc[CH * 32];
    __shared__ float s_dt[CH * 128];
    __shared__ float s_x [CH * 128];
    __shared__ float s_z [CH * 128];

    for (int t0 = 0; t0 < NSEQ; t0 += CH) {
        __syncthreads();
#pragma unroll
        for (int i = 0; i < (CH * 32) / 128; i++) {     // B,C values for the chunk
            int idx = tid + (i << 7);
            int st = idx >> 5, col = idx & 31;
            s_bc[idx] = dblp[(long)(t0 + st) * DBL_W + DR + col];
        }
#pragma unroll
        for (int i = 0; i < CH; i++) {
            s_dt[(i << 7) + tid] = dtb[(long)(t0 + i) * DI + tid];
            s_x [(i << 7) + tid] = xb [(long)(t0 + i) * DI + tid];
            s_z [(i << 7) + tid] = zb [(long)(t0 + i) * (2 * DI) + tid];
        }
        __syncthreads();

        for (int tt = 0; tt < CH; tt++) {
            const float dt_v = s_dt[(tt << 7) + tid];
            const float x_v  = s_x [(tt << 7) + tid];
            const float z_v  = s_z [(tt << 7) + tid];
            const float* bc = s_bc + (tt << 5);
            const float dtx = dt_v * x_v;
            float accv = 0.f;
#pragma unroll
            for (int s = 0; s < DS; s++) {
                float dA = __expf(dt_v * Aa[s]);
                h[s] = fmaf(dA, h[s], dtx * bc[s]);
                accv = fmaf(h[s], bc[DS + s], accv);
            }
            float yv = fmaf(x_v, Dv, accv);
            yv *= z_v / (1.f + __expf(-z_v));        // silu(z) gate
            yb[(long)(t0 + tt) * DI + tid] = yv;
        }
    }
}

// ---------------- final layernorm + residual + transpose-out ----------------
__global__ __launch_bounds__(256) void ln2_kernel(
    const float* __restrict__ g, const float* __restrict__ bb, float* __restrict__ out)
{
    __shared__ float t1[16][193];  // h3 tile [nn][d]
    __shared__ float t2[16][193];  // xs residual tile
    __shared__ float s_mean[16], s_rstd[16];
    const int b = blockIdx.y, n0 = blockIdx.x << 4;
    const int tid = threadIdx.x;

    for (int i = tid; i < 16 * DM; i += 256) {
        int nn = i / DM, dd = i % DM;
        long adr = ((long)(b << 10) + n0 + nn) * DM + dd;
        t1[nn][dd] = g_h3[adr];
        t2[nn][dd] = g_xs[adr];
    }
    __syncthreads();

    const int nn = tid >> 4, l = tid & 15;     // 16 lanes reduce one n
    float s = 0.f, s2 = 0.f;
    for (int dd = l; dd < DM; dd += 16) { float v = t1[nn][dd]; s += v; s2 = fmaf(v, v, s2); }
    s  += __shfl_down_sync(0xffffffffu, s,  8, 16);
    s2 += __shfl_down_sync(0xffffffffu, s2, 8, 16);
    s  += __shfl_down_sync(0xffffffffu, s,  4, 16);
    s2 += __shfl_down_sync(0xffffffffu, s2, 4, 16);
    s  += __shfl_down_sync(0xffffffffu, s,  2, 16);
    s2 += __shfl_down_sync(0xffffffffu, s2, 2, 16);
    s  += __shfl_down_sync(0xffffffffu, s,  1, 16);
    s2 += __shfl_down_sync(0xffffffffu, s2, 1, 16);
    if (l == 0) {
        float m = s * (1.f / DM);
        float var = s2 * (1.f / DM) - m * m;
        s_mean[nn] = m;
        s_rstd[nn] = rsqrtf(var + 1e-5f);
    }
    __syncthreads();

    for (int i = tid; i < DM * 16; i += 256) {
        int dd = i >> 4, nn2 = i & 15;
        float v = (t1[nn2][dd] - s_mean[nn2]) * s_rstd[nn2] * g[dd] + bb[dd] + t2[nn2][dd];
        out[((long)(b * DM + dd) << 10) + n0 + nn2] = v;
    }
}

// ---------------- launcher ----------------
extern "C" void kernel_launch(void* const* d_in, const int* in_sizes, int n_in,
                              void* d_out, int out_size)
{
    const float* x        = (const float*)d_in[0];
    const float* norm_g   = (const float*)d_in[1];
    const float* norm_b   = (const float*)d_in[2];
    const float* in_w     = (const float*)d_in[3];
    const float* in_b     = (const float*)d_in[4];
    const float* m_in_w   = (const float*)d_in[5];
    const float* m_conv_w = (const float*)d_in[6];
    const float* m_conv_b = (const float*)d_in[7];
    const float* m_xp_w   = (const float*)d_in[8];
    const float* m_dt_w   = (const float*)d_in[9];
    const float* m_dt_b   = (const float*)d_in[10];
    const float* m_Alog   = (const float*)d_in[11];
    const float* m_D      = (const float*)d_in[12];
    const float* m_out_w  = (const float*)d_in[13];
    const float* f_w1     = (const float*)d_in[14];
    const float* f_b1     = (const float*)d_in[15];
    const float* f_w2     = (const float*)d_in[16];
    const float* f_b2     = (const float*)d_in[17];
    const float* o_w      = (const float*)d_in[18];
    const float* o_b      = (const float*)d_in[19];
    const float* on_g     = (const float*)d_in[20];
    const float* on_b     = (const float*)d_in[21];
    float* out = (float*)d_out;

    float *p_xs, *p_xp, *p_seqs, *p_xz, *p_xsm, *p_dbl, *p_dt, *p_y, *p_yo, *p_fused, *p_hdn, *p_h2, *p_h3;
    cudaGetSymbolAddress((void**)&p_xs, g_xs);
    cudaGetSymbolAddress((void**)&p_xp, g_xp);
    cudaGetSymbolAddress((void**)&p_seqs, g_seqs);
    cudaGetSymbolAddress((void**)&p_xz, g_xz);
    cudaGetSymbolAddress((void**)&p_xsm, g_xsm);
    cudaGetSymbolAddress((void**)&p_dbl, g_dbl);
    cudaGetSymbolAddress((void**)&p_dt, g_dt);
    cudaGetSymbolAddress((void**)&p_y, g_y);
    cudaGetSymbolAddress((void**)&p_yo, g_yo);
    cudaGetSymbolAddress((void**)&p_fused, g_fused);
    cudaGetSymbolAddress((void**)&p_hdn, g_hdn);
    cudaGetSymbolAddress((void**)&p_h2, g_h2);
    cudaGetSymbolAddress((void**)&p_h3, g_h3);

    // 1) layernorm + transpose
    ln1_kernel<<<dim3(32, 4), 256>>>(x, norm_g, norm_b);

    // 2) xp = xs @ in_w^T + in_b
    gemm_kernel<<<dim3(3, 64, 1), 256>>>(p_xs, in_w, in_b, p_xp,
        LROWS, DM, DM, DM, DM, 0, 0, 0, 0, 0);

    // 3) gather 4 direction sequences
    build_seqs_kernel<<<(NDIR * LROWS * DM + 255) / 256, 256>>>();

    // 4) xz[d] = seqs[d] @ m_in_w[d]^T
    gemm_kernel<<<dim3(12, 64, 4), 256>>>(p_seqs, m_in_w, nullptr, p_xz,
        LROWS, 2 * DI, DM, DM, 2 * DI,
        (long)LROWS * DM, (long)2 * DI * DM, 0, (long)LROWS * 2 * DI, 0);

    // 5) causal depthwise conv + silu
    conv_silu_kernel<<<((long)NDIR * BATCH * NSEQ * DI + 255) / 256, 256>>>(m_conv_w, m_conv_b);

    // 6) dbl[d] = xsm[d] @ m_xp_w[d]^T
    gemm_kernel<<<dim3(1, 64, 4), 256>>>(p_xsm, m_xp_w, nullptr, p_dbl,
        LROWS, DBL_W, DI, DI, DBL_W,
        (long)LROWS * DI, (long)DBL_W * DI, 0, (long)LROWS * DBL_W, 0);

    // 7) dt[d] = softplus(dbl[d][:, :12] @ m_dt_w[d]^T + m_dt_b[d])
    gemm_kernel<<<dim3(6, 64, 4), 256>>>(p_dbl, m_dt_w, m_dt_b, p_dt,
        LROWS, DI, DR, DBL_W, DI,
        (long)LROWS * DBL_W, (long)DI * DR, DI, (long)LROWS * DI, 1);

    // 8) selective scan (+ D skip + silu(z) gate)
    scan_kernel<<<dim3(3, BATCH, NDIR), 128>>>(m_Alog, m_D);

    // 9) yo[d] = y[d] @ m_out_w[d]^T
    gemm_kernel<<<dim3(3, 64, 4), 256>>>(p_y, m_out_w, nullptr, p_yo,
        LROWS, DM, DI, DI, DM,
        (long)LROWS * DI, (long)DM * DI, 0, (long)LROWS * DM, 0);

    // 10) re-align directions + concat
    build_fused_kernel<<<((long)LROWS * 4 * DM + 255) / 256, 256>>>();

    // 11) hdn = gelu(fused @ f_w1^T + f_b1)
    gemm_kernel<<<dim3(6, 64, 1), 256>>>(p_fused, f_w1, f_b1, p_hdn,
        LROWS, 2 * DM, 4 * DM, 4 * DM, 2 * DM, 0, 0, 0, 0, 2);

    // 12) h2 = hdn @ f_w2^T + f_b2
    gemm_kernel<<<dim3(3, 64, 1), 256>>>(p_hdn, f_w2, f_b2, p_h2,
        LROWS, DM, 2 * DM, 2 * DM, DM, 0, 0, 0, 0, 0);

    // 13) h3 = h2 @ o_w^T + o_b
    gemm_kernel<<<dim3(3, 64, 1), 256>>>(p_h2, o_w, o_b, p_h3,
        LROWS, DM, DM, DM, DM, 0, 0, 0, 0, 0);

    // 14) final layernorm + residual + transpose out
    ln2_kernel<<<dim3(64, 4), 256>>>(on_g, on_b, out);
}

// round 2
// speedup vs baseline: 1.1331x; 1.1331x over previous
#include <cuda_runtime.h>
#include <math.h>

// ---------------- problem constants ----------------
#define BATCH 4
#define DM    192          // d_model
#define DI    384          // d_inner
#define DS    16           // d_state
#define DR    12           // dt_rank
#define NSEQ  1024         // H*W
#define LROWS 4096         // BATCH*NSEQ
#define NDIR  4
#define DBL_W 44           // DR + 2*DS

// ---------------- scratch (static device memory: allocation-free) ----------------
__device__ float g_xs  [LROWS*DM];            // layernormed input (also residual)
__device__ float g_xp  [LROWS*DM];            // after in_proj
__device__ float g_seqs[NDIR*LROWS*DM];       // 4 direction-ordered sequences
__device__ float g_xz  [(long)NDIR*LROWS*2*DI]; // in_proj per direction (xh | z)
__device__ float g_xsm [NDIR*LROWS*DI];       // silu(conv(xh))
__device__ float g_dbl [NDIR*LROWS*DBL_W];    // x_proj output (dt_raw | B | C)
__device__ float g_dt  [NDIR*LROWS*DI];       // softplus(dt_proj)
__device__ float g_y   [NDIR*LROWS*DI];       // scan output (gated)
__device__ float g_yo  [NDIR*LROWS*DM];       // out_proj per direction
__device__ float g_fused[LROWS*4*DM];         // concat of 4 directions (re-aligned)
__device__ float g_hdn [LROWS*2*DM];
__device__ float g_h2  [LROWS*DM];
__device__ float g_h3  [LROWS*DM];

// ---------------- activation helper ----------------
__device__ __forceinline__ float apply_act(float v, int act) {
    if (act == 1) {                  // softplus
        v = (v > 20.f) ? v : log1pf(__expf(v));
    } else if (act == 2) {           // exact gelu
        v = 0.5f * v * (1.f + erff(v * 0.70710678118654752f));
    }
    return v;
}

// ---------------- big-tile fp32 GEMM:  C = act(A @ W^T + bias) ----------------
// 128x128 tile, 256 threads, 8x8 microtile (split 4+4 halves for conflict-free LDS.128).
// A: M x K (row stride lda, M % 128 == 0), W: Nn x K row-major, C: M x Nn.
// Requires lda, ldc, K multiples of 4 (true for every call here). Guards on Nn and K tail.
__global__ __launch_bounds__(256) void gemm128_kernel(
    const float* __restrict__ A, const float* __restrict__ W,
    const float* __restrict__ bias, float* __restrict__ C,
    int M, int Nn, int K, int lda, int ldc,
    long sA, long sW, long sB, long sC, int act)
{
    const int z = blockIdx.z;
    A += z * sA; W += z * sW; C += z * sC;
    const float* bz = bias ? (bias + z * sB) : (const float*)0;

    __shared__ float As[8][128];
    __shared__ float Ws[8][128];

    const int bm = blockIdx.y << 7, bn = blockIdx.x << 7;
    const int tid = threadIdx.x;
    const int tx = tid & 15;          // n-dim micro position
    const int ty = tid >> 4;          // m-dim micro position
    const int lr = tid >> 1;          // 0..127: tile row loaded by this thread
    const int lc = (tid & 1) << 2;    // 0 or 4: k offset within 8-wide k-tile

    float acc[8][8];
#pragma unroll
    for (int i = 0; i < 8; i++)
#pragma unroll
        for (int j = 0; j < 8; j++) acc[i][j] = 0.f;

    const long aRow = (long)(bm + lr) * lda;   // M % 128 == 0 -> always valid
    const int  gw_n = bn + lr;
    const long wRow = (long)gw_n * K;
    const int nkt = (K + 7) >> 3;

    // ---- prefetch tile 0 ----
    float4 pa, pw;
    {
        int gk = lc;
        if (gk + 3 < K) pa = *(const float4*)(A + aRow + gk);
        else {
            pa.x = (gk + 0 < K) ? A[aRow + gk + 0] : 0.f;
            pa.y = (gk + 1 < K) ? A[aRow + gk + 1] : 0.f;
            pa.z = (gk + 2 < K) ? A[aRow + gk + 2] : 0.f;
            pa.w = 0.f;
        }
        if (gw_n < Nn) {
            if (gk + 3 < K) pw = *(const float4*)(W + wRow + gk);
            else {
                pw.x = (gk + 0 < K) ? W[wRow + gk + 0] : 0.f;
                pw.y = (gk + 1 < K) ? W[wRow + gk + 1] : 0.f;
                pw.z = (gk + 2 < K) ? W[wRow + gk + 2] : 0.f;
                pw.w = 0.f;
            }
        } else { pw.x = pw.y = pw.z = pw.w = 0.f; }
    }

    for (int kt = 0; kt < nkt; kt++) {
        // stage current tile to smem (transpose to [k][m] / [k][n])
        As[lc + 0][lr] = pa.x;
        As[lc + 1][lr] = pa.y;
        As[lc + 2][lr] = pa.z;
        As[lc + 3][lr] = pa.w;
        Ws[lc + 0][lr] = pw.x;
        Ws[lc + 1][lr] = pw.y;
        Ws[lc + 2][lr] = pw.z;
        Ws[lc + 3][lr] = pw.w;
        __syncthreads();

        // prefetch next tile while computing
        if (kt + 1 < nkt) {
            int gk = ((kt + 1) << 3) + lc;
            if (gk + 3 < K) pa = *(const float4*)(A + aRow + gk);
            else {
                pa.x = (gk + 0 < K) ? A[aRow + gk + 0] : 0.f;
                pa.y = (gk + 1 < K) ? A[aRow + gk + 1] : 0.f;
                pa.z = (gk + 2 < K) ? A[aRow + gk + 2] : 0.f;
                pa.w = 0.f;
            }
            if (gw_n < Nn) {
                if (gk + 3 < K) pw = *(const float4*)(W + wRow + gk);
                else {
                    pw.x = (gk + 0 < K) ? W[wRow + gk + 0] : 0.f;
                    pw.y = (gk + 1 < K) ? W[wRow + gk + 1] : 0.f;
                    pw.z = (gk + 2 < K) ? W[wRow + gk + 2] : 0.f;
                    pw.w = 0.f;
                }
            } else { pw.x = pw.y = pw.z = pw.w = 0.f; }
        }

#pragma unroll
        for (int kk = 0; kk < 8; kk++) {
            float4 a0 = *(const float4*)&As[kk][ty << 2];
            float4 a1 = *(const float4*)&As[kk][64 + (ty << 2)];
            float4 w0 = *(const float4*)&Ws[kk][tx << 2];
            float4 w1 = *(const float4*)&Ws[kk][64 + (tx << 2)];
            float av[8] = {a0.x, a0.y, a0.z, a0.w, a1.x, a1.y, a1.z, a1.w};
            float wv[8] = {w0.x, w0.y, w0.z, w0.w, w1.x, w1.y, w1.z, w1.w};
#pragma unroll
            for (int i = 0; i < 8; i++)
#pragma unroll
                for (int j = 0; j < 8; j++)
                    acc[i][j] = fmaf(av[i], wv[j], acc[i][j]);
        }
        __syncthreads();
    }

    // ---- epilogue ----
#pragma unroll
    for (int ih = 0; ih < 2; ih++)
#pragma unroll
        for (int i = 0; i < 4; i++) {
            const int gm = bm + (ih << 6) + (ty << 2) + i;
#pragma unroll
            for (int jh = 0; jh < 2; jh++)
#pragma unroll
                for (int j = 0; j < 4; j++) {
                    const int gn = bn + (jh << 6) + (tx << 2) + j;
                    if (gn < Nn) {
                        float v = acc[(ih << 2) + i][(jh << 2) + j];
                        if (bz) v += bz[gn];
                        C[(long)gm * ldc + gn] = apply_act(v, act);
                    }
                }
        }
}

// ---------------- small-N fp32 GEMM (64x64 tile, 4x4 micro) ----------------
__global__ __launch_bounds__(256) void gemm_kernel(
    const float* __restrict__ A, const float* __restrict__ W,
    const float* __restrict__ bias, float* __restrict__ C,
    int M, int Nn, int K, int lda, int ldc,
    long sA, long sW, long sB, long sC, int act)
{
    const int z = blockIdx.z;
    A += z * sA; W += z * sW; C += z * sC;
    const float* bz = bias ? (bias + z * sB) : (const float*)0;

    __shared__ float As[16][68];
    __shared__ float Ws[16][68];

    const int bm = blockIdx.y << 6, bn = blockIdx.x << 6;
    const int tid = threadIdx.x;
    const int tx = tid & 15, ty = tid >> 4;

    float acc[4][4];
#pragma unroll
    for (int i = 0; i < 4; i++)
#pragma unroll
        for (int j = 0; j < 4; j++) acc[i][j] = 0.f;

    const int nkt = (K + 15) >> 4;
    for (int kt = 0; kt < nkt; kt++) {
        const int k0 = kt << 4;
#pragma unroll
        for (int i = 0; i < 4; i++) {
            int idx = tid + (i << 8);
            int r = idx >> 4, kk = idx & 15;
            int gk = k0 + kk;
            As[kk][r] = (gk < K) ? A[(long)(bm + r) * lda + gk] : 0.f;
            int gn = bn + r;
            Ws[kk][r] = (gn < Nn && gk < K) ? W[(long)gn * K + gk] : 0.f;
        }
        __syncthreads();
#pragma unroll
        for (int kk = 0; kk < 16; kk++) {
            float a0 = As[kk][(ty<<2)+0], a1 = As[kk][(ty<<2)+1];
            float a2 = As[kk][(ty<<2)+2], a3 = As[kk][(ty<<2)+3];
            float w0 = Ws[kk][(tx<<2)+0], w1 = Ws[kk][(tx<<2)+1];
            float w2 = Ws[kk][(tx<<2)+2], w3 = Ws[kk][(tx<<2)+3];
            acc[0][0] = fmaf(a0,w0,acc[0][0]); acc[0][1] = fmaf(a0,w1,acc[0][1]);
            acc[0][2] = fmaf(a0,w2,acc[0][2]); acc[0][3] = fmaf(a0,w3,acc[0][3]);
            acc[1][0] = fmaf(a1,w0,acc[1][0]); acc[1][1] = fmaf(a1,w1,acc[1][1]);
            acc[1][2] = fmaf(a1,w2,acc[1][2]); acc[1][3] = fmaf(a1,w3,acc[1][3]);
            acc[2][0] = fmaf(a2,w0,acc[2][0]); acc[2][1] = fmaf(a2,w1,acc[2][1]);
            acc[2][2] = fmaf(a2,w2,acc[2][2]); acc[2][3] = fmaf(a2,w3,acc[2][3]);
            acc[3][0] = fmaf(a3,w0,acc[3][0]); acc[3][1] = fmaf(a3,w1,acc[3][1]);
            acc[3][2] = fmaf(a3,w2,acc[3][2]); acc[3][3] = fmaf(a3,w3,acc[3][3]);
        }
        __syncthreads();
    }

#pragma unroll
    for (int i = 0; i < 4; i++) {
        const int gm = bm + (ty << 2) + i;
#pragma unroll
        for (int j = 0; j < 4; j++) {
            const int gn = bn + (tx << 2) + j;
            if (gn < Nn) {
                float v = acc[i][j];
                if (bz) v += bz[gn];
                C[(long)gm * ldc + gn] = apply_act(v, act);
            }
        }
    }
}

// ---------------- kernel 1: transpose + layernorm (x: (B,192,1024) -> xs: (B,1024,192)) ----------------
__global__ __launch_bounds__(256) void ln1_kernel(
    const float* __restrict__ x, const float* __restrict__ g, const float* __restrict__ bb)
{
    __shared__ float tile[DM][33];
    __shared__ float s_mean[32], s_rstd[32];
    const int b = blockIdx.y, n0 = blockIdx.x << 5;
    const int tid = threadIdx.x;

    for (int i = tid; i < DM * 32; i += 256) {
        int d = i >> 5, nn = i & 31;
        tile[d][nn] = x[((long)(b * DM + d) << 10) + n0 + nn];
    }
    __syncthreads();

    const int nn = tid >> 3, l = tid & 7;
    float s = 0.f, s2 = 0.f;
    for (int d = l; d < DM; d += 8) { float v = tile[d][nn]; s += v; s2 = fmaf(v, v, s2); }
    s  += __shfl_down_sync(0xffffffffu, s,  4, 8);
    s2 += __shfl_down_sync(0xffffffffu, s2, 4, 8);
    s  += __shfl_down_sync(0xffffffffu, s,  2, 8);
    s2 += __shfl_down_sync(0xffffffffu, s2, 2, 8);
    s  += __shfl_down_sync(0xffffffffu, s,  1, 8);
    s2 += __shfl_down_sync(0xffffffffu, s2, 1, 8);
    if (l == 0) {
        float m = s * (1.f / DM);
        float var = s2 * (1.f / DM) - m * m;
        s_mean[nn] = m;
        s_rstd[nn] = rsqrtf(var + 1e-5f);
    }
    __syncthreads();

    for (int i = tid; i < DM * 32; i += 256) {
        int nn2 = i / DM, d = i % DM;
        float v = (tile[d][nn2] - s_mean[nn2]) * s_rstd[nn2] * g[d] + bb[d];
        g_xs[((long)(b << 10) + n0 + nn2) * DM + d] = v;
    }
}

// ---------------- direction index maps ----------------
__device__ __forceinline__ int seq_src_n(int d, int t) {
    if (d == 0) return t;
    if (d == 1) return NSEQ - 1 - t;
    if (d == 2) return ((t & 31) << 5) + (t >> 5);
    int u = NSEQ - 1 - t;
    return ((u & 31) << 5) + (u >> 5);
}
__device__ __forceinline__ int fused_src_t(int d, int n) {
    if (d == 0) return n;
    if (d == 1) return NSEQ - 1 - n;
    if (d == 2) return ((n & 31) << 5) + (n >> 5);
    return NSEQ - 1 - (((n & 31) << 5) + (n >> 5));
}

__global__ __launch_bounds__(256) void build_seqs_kernel() {
    long i = (long)blockIdx.x * 256 + threadIdx.x;
    if (i >= (long)NDIR * LROWS * DM) return;
    int cc = (int)(i % DM);
    long r = i / DM;
    int t = (int)(r % NSEQ);
    long db = r / NSEQ;
    int d = (int)(db >> 2), b = (int)(db & 3);
    int n = seq_src_n(d, t);
    g_seqs[i] = g_xp[((long)(b << 10) + n) * DM + cc];
}

__global__ __launch_bounds__(256) void build_fused_kernel() {
    long i = (long)blockIdx.x * 256 + threadIdx.x;
    if (i >= (long)LROWS * 4 * DM) return;
    int col = (int)(i % (4 * DM));
    long row = i / (4 * DM);
    int d = col / DM, cc = col % DM;
    int n = (int)(row % NSEQ);
    int b = (int)(row / NSEQ);
    int t = fused_src_t(d, n);
    g_fused[i] = g_yo[((long)((d << 2) + b) * NSEQ + t) * DM + cc];
}

// ---------------- causal depthwise conv (width 4) + silu ----------------
__global__ __launch_bounds__(256) void conv_silu_kernel(
    const float* __restrict__ cw, const float* __restrict__ cb)
{
    long i = (long)blockIdx.x * 256 + threadIdx.x;
    if (i >= (long)NDIR * BATCH * NSEQ * DI) return;
    int c = (int)(i % DI);
    long r = i / DI;
    int t = (int)(r % NSEQ);
    long db = r / NSEQ;
    int d = (int)(db >> 2);
    const float* w = cw + ((long)d * DI + c) * 4;
    float acc = cb[d * DI + c];
    const float* src = g_xz + (r - t) * (2 * DI) + c;
#pragma unroll
    for (int j = 0; j < 4; j++) {
        int tt = t - 3 + j;
        if (tt >= 0) acc = fmaf(w[j], src[(long)tt * (2 * DI)], acc);
    }
    g_xsm[r * DI + c] = acc / (1.f + __expf(-acc));
}

// ---------------- sequential selective scan ----------------
#define CH 16
__global__ __launch_bounds__(128) void scan_kernel(
    const float* __restrict__ Alog, const float* __restrict__ Dp)
{
    const int d = blockIdx.z, b = blockIdx.y;
    const int c0 = blockIdx.x << 7;
    const int tid = threadIdx.x;
    const int c = c0 + tid;
    const long db = d * BATCH + b;
    const long baseI = db * NSEQ;

    const float* dtb  = g_dt  + baseI * DI       + c0;
    const float* xb   = g_xsm + baseI * DI       + c0;
    const float* zb   = g_xz  + baseI * (2 * DI) + DI + c0;
    const float* dblp = g_dbl + baseI * DBL_W;
    float* yb         = g_y   + baseI * DI       + c0;

    float Aa[DS];
#pragma unroll
    for (int s = 0; s < DS; s++)
        Aa[s] = -expf(Alog[((long)(d * DI + c)) * DS + s]);
    const float Dv = Dp[d * DI + c];

    float h[DS];
#pragma unroll
    for (int s = 0; s < DS; s++) h[s] = 0.f;

    __shared__ float s_bc[CH * 32];
    __shared__ float s_dt[CH * 128];
    __shared__ float s_x [CH * 128];
    __shared__ float s_z [CH * 128];

    for (int t0 = 0; t0 < NSEQ; t0 += CH) {
        __syncthreads();
#pragma unroll
        for (int i = 0; i < (CH * 32) / 128; i++) {
            int idx = tid + (i << 7);
            int st = idx >> 5, col = idx & 31;
            s_bc[idx] = dblp[(long)(t0 + st) * DBL_W + DR + col];
        }
#pragma unroll
        for (int i = 0; i < CH; i++) {
            s_dt[(i << 7) + tid] = dtb[(long)(t0 + i) * DI + tid];
            s_x [(i << 7) + tid] = xb [(long)(t0 + i) * DI + tid];
            s_z [(i << 7) + tid] = zb [(long)(t0 + i) * (2 * DI) + tid];
        }
        __syncthreads();

        for (int tt = 0; tt < CH; tt++) {
            const float dt_v = s_dt[(tt << 7) + tid];
            const float x_v  = s_x [(tt << 7) + tid];
            const float z_v  = s_z [(tt << 7) + tid];
            const float* bc = s_bc + (tt << 5);
            const float dtx = dt_v * x_v;
            float accv = 0.f;
#pragma unroll
            for (int s = 0; s < DS; s++) {
                float dA = __expf(dt_v * Aa[s]);
                h[s] = fmaf(dA, h[s], dtx * bc[s]);
                accv = fmaf(h[s], bc[DS + s], accv);
            }
            float yv = fmaf(x_v, Dv, accv);
            yv *= z_v / (1.f + __expf(-z_v));
            yb[(long)(t0 + tt) * DI + tid] = yv;
        }
    }
}

// ---------------- final layernorm + residual + transpose-out ----------------
__global__ __launch_bounds__(256) void ln2_kernel(
    const float* __restrict__ g, const float* __restrict__ bb, float* __restrict__ out)
{
    __shared__ float t1[16][193];
    __shared__ float t2[16][193];
    __shared__ float s_mean[16], s_rstd[16];
    const int b = blockIdx.y, n0 = blockIdx.x << 4;
    const int tid = threadIdx.x;

    for (int i = tid; i < 16 * DM; i += 256) {
        int nn = i / DM, dd = i % DM;
        long adr = ((long)(b << 10) + n0 + nn) * DM + dd;
        t1[nn][dd] = g_h3[adr];
        t2[nn][dd] = g_xs[adr];
    }
    __syncthreads();

    const int nn = tid >> 4, l = tid & 15;
    float s = 0.f, s2 = 0.f;
    for (int dd = l; dd < DM; dd += 16) { float v = t1[nn][dd]; s += v; s2 = fmaf(v, v, s2); }
    s  += __shfl_down_sync(0xffffffffu, s,  8, 16);
    s2 += __shfl_down_sync(0xffffffffu, s2, 8, 16);
    s  += __shfl_down_sync(0xffffffffu, s,  4, 16);
    s2 += __shfl_down_sync(0xffffffffu, s2, 4, 16);
    s  += __shfl_down_sync(0xffffffffu, s,  2, 16);
    s2 += __shfl_down_sync(0xffffffffu, s2, 2, 16);
    s  += __shfl_down_sync(0xffffffffu, s,  1, 16);
    s2 += __shfl_down_sync(0xffffffffu, s2, 1, 16);
    if (l == 0) {
        float m = s * (1.f / DM);
        float var = s2 * (1.f / DM) - m * m;
        s_mean[nn] = m;
        s_rstd[nn] = rsqrtf(var + 1e-5f);
    }
    __syncthreads();

    for (int i = tid; i < DM * 16; i += 256) {
        int dd = i >> 4, nn2 = i & 15;
        float v = (t1[nn2][dd] - s_mean[nn2]) * s_rstd[nn2] * g[dd] + bb[dd] + t2[nn2][dd];
        out[((long)(b * DM + dd) << 10) + n0 + nn2] = v;
    }
}

// ---------------- launcher ----------------
extern "C" void kernel_launch(void* const* d_in, const int* in_sizes, int n_in,
                              void* d_out, int out_size)
{
    const float* x        = (const float*)d_in[0];
    const float* norm_g   = (const float*)d_in[1];
    const float* norm_b   = (const float*)d_in[2];
    const float* in_w     = (const float*)d_in[3];
    const float* in_b     = (const float*)d_in[4];
    const float* m_in_w   = (const float*)d_in[5];
    const float* m_conv_w = (const float*)d_in[6];
    const float* m_conv_b = (const float*)d_in[7];
    const float* m_xp_w   = (const float*)d_in[8];
    const float* m_dt_w   = (const float*)d_in[9];
    const float* m_dt_b   = (const float*)d_in[10];
    const float* m_Alog   = (const float*)d_in[11];
    const float* m_D      = (const float*)d_in[12];
    const float* m_out_w  = (const float*)d_in[13];
    const float* f_w1     = (const float*)d_in[14];
    const float* f_b1     = (const float*)d_in[15];
    const float* f_w2     = (const float*)d_in[16];
    const float* f_b2     = (const float*)d_in[17];
    const float* o_w      = (const float*)d_in[18];
    const float* o_b      = (const float*)d_in[19];
    const float* on_g     = (const float*)d_in[20];
    const float* on_b     = (const float*)d_in[21];
    float* out = (float*)d_out;

    float *p_xs, *p_xp, *p_seqs, *p_xz, *p_xsm, *p_dbl, *p_dt, *p_y, *p_yo, *p_fused, *p_hdn, *p_h2, *p_h3;
    cudaGetSymbolAddress((void**)&p_xs, g_xs);
    cudaGetSymbolAddress((void**)&p_xp, g_xp);
    cudaGetSymbolAddress((void**)&p_seqs, g_seqs);
    cudaGetSymbolAddress((void**)&p_xz, g_xz);
    cudaGetSymbolAddress((void**)&p_xsm, g_xsm);
    cudaGetSymbolAddress((void**)&p_dbl, g_dbl);
    cudaGetSymbolAddress((void**)&p_dt, g_dt);
    cudaGetSymbolAddress((void**)&p_y, g_y);
    cudaGetSymbolAddress((void**)&p_yo, g_yo);
    cudaGetSymbolAddress((void**)&p_fused, g_fused);
    cudaGetSymbolAddress((void**)&p_hdn, g_hdn);
    cudaGetSymbolAddress((void**)&p_h2, g_h2);
    cudaGetSymbolAddress((void**)&p_h3, g_h3);

    // 1) layernorm + transpose
    ln1_kernel<<<dim3(32, 4), 256>>>(x, norm_g, norm_b);

    // 2) xp = xs @ in_w^T + in_b   (4096 x 192 x 192)
    gemm128_kernel<<<dim3(2, 32, 1), 256>>>(p_xs, in_w, in_b, p_xp,
        LROWS, DM, DM, DM, DM, 0, 0, 0, 0, 0);

    // 3) gather 4 direction sequences
    build_seqs_kernel<<<(NDIR * LROWS * DM + 255) / 256, 256>>>();

    // 4) xz[d] = seqs[d] @ m_in_w[d]^T   (4 x 4096 x 768 x 192)
    gemm128_kernel<<<dim3(6, 32, 4), 256>>>(p_seqs, m_in_w, nullptr, p_xz,
        LROWS, 2 * DI, DM, DM, 2 * DI,
        (long)LROWS * DM, (long)2 * DI * DM, 0, (long)LROWS * 2 * DI, 0);

    // 5) causal depthwise conv + silu
    conv_silu_kernel<<<((long)NDIR * BATCH * NSEQ * DI + 255) / 256, 256>>>(m_conv_w, m_conv_b);

    // 6) dbl[d] = xsm[d] @ m_xp_w[d]^T   (N=44 -> small-tile kernel)
    gemm_kernel<<<dim3(1, 64, 4), 256>>>(p_xsm, m_xp_w, nullptr, p_dbl,
        LROWS, DBL_W, DI, DI, DBL_W,
        (long)LROWS * DI, (long)DBL_W * DI, 0, (long)LROWS * DBL_W, 0);

    // 7) dt[d] = softplus(dbl[d][:, :12] @ m_dt_w[d]^T + m_dt_b[d])   (K=12)
    gemm128_kernel<<<dim3(3, 32, 4), 256>>>(p_dbl, m_dt_w, m_dt_b, p_dt,
        LROWS, DI, DR, DBL_W, DI,
        (long)LROWS * DBL_W, (long)DI * DR, DI, (long)LROWS * DI, 1);

    // 8) selective scan (+ D skip + silu(z) gate)
    scan_kernel<<<dim3(3, BATCH, NDIR), 128>>>(m_Alog, m_D);

    // 9) yo[d] = y[d] @ m_out_w[d]^T   (4 x 4096 x 192 x 384)
    gemm128_kernel<<<dim3(2, 32, 4), 256>>>(p_y, m_out_w, nullptr, p_yo,
        LROWS, DM, DI, DI, DM,
        (long)LROWS * DI, (long)DM * DI, 0, (long)LROWS * DM, 0);

    // 10) re-align directions + concat
    build_fused_kernel<<<((long)LROWS * 4 * DM + 255) / 256, 256>>>();

    // 11) hdn = gelu(fused @ f_w1^T + f_b1)   (4096 x 384 x 768)
    gemm128_kernel<<<dim3(3, 32, 1), 256>>>(p_fused, f_w1, f_b1, p_hdn,
        LROWS, 2 * DM, 4 * DM, 4 * DM, 2 * DM, 0, 0, 0, 0, 2);

    // 12) h2 = hdn @ f_w2^T + f_b2   (4096 x 192 x 384)
    gemm128_kernel<<<dim3(2, 32, 1), 256>>>(p_hdn, f_w2, f_b2, p_h2,
        LROWS, DM, 2 * DM, 2 * DM, DM, 0, 0, 0, 0, 0);

    // 13) h3 = h2 @ o_w^T + o_b   (4096 x 192 x 192)
    gemm128_kernel<<<dim3(2, 32, 1), 256>>>(p_h2, o_w, o_b, p_h3,
        LROWS, DM, DM, DM, DM, 0, 0, 0, 0, 0);

    // 14) final layernorm + residual + transpose out
    ln2_kernel<<<dim3(64, 4), 256>>>(on_g, on_b, out);
}

// round 3
// speedup vs baseline: 1.4774x; 1.3038x over previous
#include <cuda_runtime.h>
#include <math.h>
#include <stdint.h>

// ---------------- problem constants ----------------
#define BATCH 4
#define DM    192          // d_model
#define DI    384          // d_inner
#define DS    16           // d_state
#define DR    12           // dt_rank
#define NSEQ  1024         // H*W
#define LROWS 4096         // BATCH*NSEQ
#define NDIR  4
#define DBL_W 44           // DR + 2*DS

// ---------------- scratch (static device memory: allocation-free) ----------------
__device__ float g_xs  [LROWS*DM];            // layernormed input (also residual)
__device__ float g_xp  [LROWS*DM];            // after in_proj
__device__ float g_xz  [(long)NDIR*LROWS*2*DI]; // in_proj per direction (xh | z)
__device__ float g_xsm [NDIR*LROWS*DI];       // silu(conv(xh))
__device__ float g_dbl [NDIR*LROWS*DBL_W];    // x_proj output (dt_raw | B | C)
__device__ float g_dt  [NDIR*LROWS*DI];       // softplus(dt_proj)
__device__ float g_y   [NDIR*LROWS*DI];       // scan output (gated)
__device__ float g_fused[LROWS*4*DM];         // concat of 4 directions (spatial-aligned)
__device__ float g_hdn [LROWS*2*DM];
__device__ float g_h2  [LROWS*DM];
__device__ float g_h3  [LROWS*DM];

// ---------------- helpers ----------------
__device__ __forceinline__ float apply_act(float v, int act) {
    if (act == 1) {                  // softplus
        v = (v > 20.f) ? v : log1pf(__expf(v));
    } else if (act == 2) {           // exact gelu
        v = 0.5f * v * (1.f + erff(v * 0.70710678118654752f));
    }
    return v;
}

// direction index map: spatial n that feeds sequence position t of direction d
// (also the inverse map: output seq position t of dir d lands at spatial n)
__device__ __forceinline__ int seq_src_n(int d, int t) {
    if (d == 0) return t;
    if (d == 1) return NSEQ - 1 - t;
    if (d == 2) return ((t & 31) << 5) + (t >> 5);
    int u = NSEQ - 1 - t;
    return ((u & 31) << 5) + (u >> 5);
}

__device__ __forceinline__ unsigned f2tf(float f) {
    unsigned u;
    asm("cvt.rna.tf32.f32 %0, %1;" : "=r"(u) : "f"(f));
    return u;
}

__device__ __forceinline__ void mma_tf32(float4& c, const uint4& a, const uint2& b) {
    asm volatile(
        "mma.sync.aligned.m16n8k8.row.col.f32.tf32.tf32.f32 "
        "{%0,%1,%2,%3}, {%4,%5,%6,%7}, {%8,%9}, {%0,%1,%2,%3};\n"
        : "+f"(c.x), "+f"(c.y), "+f"(c.z), "+f"(c.w)
        : "r"(a.x), "r"(a.y), "r"(a.z), "r"(a.w), "r"(b.x), "r"(b.y));
}

// ---------------- tf32 tensor-core GEMM:  C = act(A @ W^T + bias) ----------------
// 128x128 tile, BK=8, 256 threads (8 warps as 2x4, warp tile 64x32 = 4x4 m16n8k8).
// Requirements: M % 128 == 0, K % 8 == 0, lda/ldc % 2 == 0, Nn even.
// mode: 0 = plain, 1 = gather A rows via seq_src_n(z, .), 2 = scatter C rows via seq_src_n(z, .)
__global__ __launch_bounds__(256) void gemm_tf32_kernel(
    const float* __restrict__ A, const float* __restrict__ W,
    const float* __restrict__ bias, float* __restrict__ C,
    int M, int Nn, int K, int lda, int ldc,
    long sA, long sW, long sB, long sC, int act, int mode)
{
    const int z = blockIdx.z;
    A += z * sA; W += z * sW; C += z * sC;
    const float* bz = bias ? (bias + z * sB) : (const float*)0;

    // fragment-permuted smem: A tile = 8 m16-tiles x [32 lanes][4 regs]; B = 16 n8-tiles x [32][2]
    __shared__ unsigned sAs[2][1024];
    __shared__ unsigned sBs[2][1024];

    const int bm = blockIdx.y << 7, bn = blockIdx.x << 7;
    const int tid = threadIdx.x;

    // ---- staging geometry (thread-constant) ----
    const int r  = tid >> 1;           // 0..127: tile row this thread loads
    const int lc = (tid & 1) << 2;     // 0 or 4: k offset
    long arow;
    if (mode == 1) {
        int gm = bm + r;
        arow = (long)(((gm >> 10) << 10) + seq_src_n(z, gm & 1023)) * lda;
    } else {
        arow = (long)(bm + r) * lda;
    }
    const int gw_n = bn + r;
    const bool wv = (gw_n < Nn);
    const long wrow = (long)gw_n * K;
    // A perm: idx(i) = (r>>4)*128 + ((r&7)*4+i)*4 + reg;  reg = ((r>>3)&1) + ((lc>>2)<<1)
    const int a_base = ((r >> 4) << 7) + ((r & 7) << 4) + ((r >> 3) & 1) + ((lc >> 2) << 1);
    // B perm: idx(i) = (r>>3)*64 + ((r&7)*4+i)*2 + (lc>>2)
    const int b_base = ((r >> 3) << 6) + ((r & 7) << 3) + (lc >> 2);

    float4 acc[4][4];
#pragma unroll
    for (int i = 0; i < 4; i++)
#pragma unroll
        for (int j = 0; j < 4; j++) acc[i][j] = make_float4(0.f, 0.f, 0.f, 0.f);

    const int lane = tid & 31, wid = tid >> 5;
    const int wm = wid >> 2, wn = wid & 3;

    const int nkt = K >> 3;

    float4 fa, fw;
    fa = *(const float4*)(A + arow + lc);
    if (wv) fw = *(const float4*)(W + wrow + lc);
    else    fw = make_float4(0.f, 0.f, 0.f, 0.f);

    // store stage 0
    {
        unsigned* pa = sAs[0]; unsigned* pb = sBs[0];
        pa[a_base + 0]  = f2tf(fa.x); pa[a_base + 4]  = f2tf(fa.y);
        pa[a_base + 8]  = f2tf(fa.z); pa[a_base + 12] = f2tf(fa.w);
        pb[b_base + 0]  = f2tf(fw.x); pb[b_base + 2]  = f2tf(fw.y);
        pb[b_base + 4]  = f2tf(fw.z); pb[b_base + 6]  = f2tf(fw.w);
    }
    __syncthreads();

    for (int kt = 0; kt < nkt; kt++) {
        const int cur = kt & 1;
        if (kt + 1 < nkt) {
            const int gk = ((kt + 1) << 3) + lc;
            fa = *(const float4*)(A + arow + gk);
            if (wv) fw = *(const float4*)(W + wrow + gk);
            else    fw = make_float4(0.f, 0.f, 0.f, 0.f);
        }
        // compute from current stage
        const unsigned* pA = &sAs[cur][(wm << 2) * 128 + (lane << 2)];
        const unsigned* pB = &sBs[cur][(wn << 2) * 64 + (lane << 1)];
        uint4 av[4]; uint2 bv[4];
#pragma unroll
        for (int i = 0; i < 4; i++) av[i] = *(const uint4*)(pA + (i << 7));
#pragma unroll
        for (int j = 0; j < 4; j++) bv[j] = *(const uint2*)(pB + (j << 6));
#pragma unroll
        for (int i = 0; i < 4; i++)
#pragma unroll
            for (int j = 0; j < 4; j++)
                mma_tf32(acc[i][j], av[i], bv[j]);

        if (kt + 1 < nkt) {
            const int nxt = cur ^ 1;
            unsigned* pa = sAs[nxt]; unsigned* pb = sBs[nxt];
            pa[a_base + 0]  = f2tf(fa.x); pa[a_base + 4]  = f2tf(fa.y);
            pa[a_base + 8]  = f2tf(fa.z); pa[a_base + 12] = f2tf(fa.w);
            pb[b_base + 0]  = f2tf(fw.x); pb[b_base + 2]  = f2tf(fw.y);
            pb[b_base + 4]  = f2tf(fw.z); pb[b_base + 6]  = f2tf(fw.w);
            __syncthreads();
        }
    }

    // ---- epilogue ----
    const int row0 = lane >> 2;           // 0..7
    const int col0 = (lane & 3) << 1;     // 0,2,4,6
#pragma unroll
    for (int i = 0; i < 4; i++) {
        const int gmA = bm + (wm << 6) + (i << 4) + row0;
        const int gmB = gmA + 8;
        long rA, rB;
        if (mode == 2) {
            rA = ((gmA >> 10) << 10) + seq_src_n(z, gmA & 1023);
            rB = ((gmB >> 10) << 10) + seq_src_n(z, gmB & 1023);
        } else { rA = gmA; rB = gmB; }
#pragma unroll
        for (int j = 0; j < 4; j++) {
            const int gn = bn + (wn << 5) + (j << 3) + col0;
            if (gn < Nn) {
                float4 v = acc[i][j];
                if (bz) {
                    const float b0 = bz[gn], b1 = bz[gn + 1];
                    v.x += b0; v.y += b1; v.z += b0; v.w += b1;
                }
                if (act) {
                    v.x = apply_act(v.x, act); v.y = apply_act(v.y, act);
                    v.z = apply_act(v.z, act); v.w = apply_act(v.w, act);
                }
                *(float2*)&C[rA * (long)ldc + gn] = make_float2(v.x, v.y);
                *(float2*)&C[rB * (long)ldc + gn] = make_float2(v.z, v.w);
            }
        }
    }
}

// ---------------- small fp32 GEMM (64x64 tile, 4x4 micro) — used for K=12 dt proj ----------------
__global__ __launch_bounds__(256) void gemm_kernel(
    const float* __restrict__ A, const float* __restrict__ W,
    const float* __restrict__ bias, float* __restrict__ C,
    int M, int Nn, int K, int lda, int ldc,
    long sA, long sW, long sB, long sC, int act)
{
    const int z = blockIdx.z;
    A += z * sA; W += z * sW; C += z * sC;
    const float* bz = bias ? (bias + z * sB) : (const float*)0;

    __shared__ float As[16][68];
    __shared__ float Ws[16][68];

    const int bm = blockIdx.y << 6, bn = blockIdx.x << 6;
    const int tid = threadIdx.x;
    const int tx = tid & 15, ty = tid >> 4;

    float acc[4][4];
#pragma unroll
    for (int i = 0; i < 4; i++)
#pragma unroll
        for (int j = 0; j < 4; j++) acc[i][j] = 0.f;

    const int nkt = (K + 15) >> 4;
    for (int kt = 0; kt < nkt; kt++) {
        const int k0 = kt << 4;
#pragma unroll
        for (int i = 0; i < 4; i++) {
            int idx = tid + (i << 8);
            int rr = idx >> 4, kk = idx & 15;
            int gk = k0 + kk;
            As[kk][rr] = (gk < K) ? A[(long)(bm + rr) * lda + gk] : 0.f;
            int gn = bn + rr;
            Ws[kk][rr] = (gn < Nn && gk < K) ? W[(long)gn * K + gk] : 0.f;
        }
        __syncthreads();
#pragma unroll
        for (int kk = 0; kk < 16; kk++) {
            float a0 = As[kk][(ty<<2)+0], a1 = As[kk][(ty<<2)+1];
            float a2 = As[kk][(ty<<2)+2], a3 = As[kk][(ty<<2)+3];
            float w0 = Ws[kk][(tx<<2)+0], w1 = Ws[kk][(tx<<2)+1];
            float w2 = Ws[kk][(tx<<2)+2], w3 = Ws[kk][(tx<<2)+3];
            acc[0][0] = fmaf(a0,w0,acc[0][0]); acc[0][1] = fmaf(a0,w1,acc[0][1]);
            acc[0][2] = fmaf(a0,w2,acc[0][2]); acc[0][3] = fmaf(a0,w3,acc[0][3]);
            acc[1][0] = fmaf(a1,w0,acc[1][0]); acc[1][1] = fmaf(a1,w1,acc[1][1]);
            acc[1][2] = fmaf(a1,w2,acc[1][2]); acc[1][3] = fmaf(a1,w3,acc[1][3]);
            acc[2][0] = fmaf(a2,w0,acc[2][0]); acc[2][1] = fmaf(a2,w1,acc[2][1]);
            acc[2][2] = fmaf(a2,w2,acc[2][2]); acc[2][3] = fmaf(a2,w3,acc[2][3]);
            acc[3][0] = fmaf(a3,w0,acc[3][0]); acc[3][1] = fmaf(a3,w1,acc[3][1]);
            acc[3][2] = fmaf(a3,w2,acc[3][2]); acc[3][3] = fmaf(a3,w3,acc[3][3]);
        }
        __syncthreads();
    }

#pragma unroll
    for (int i = 0; i < 4; i++) {
        const int gm = bm + (ty << 2) + i;
#pragma unroll
        for (int j = 0; j < 4; j++) {
            const int gn = bn + (tx << 2) + j;
            if (gn < Nn) {
                float v = acc[i][j];
                if (bz) v += bz[gn];
                C[(long)gm * ldc + gn] = apply_act(v, act);
            }
        }
    }
}

// ---------------- kernel 1: transpose + layernorm (x: (B,192,1024) -> xs: (B,1024,192)) ----------------
__global__ __launch_bounds__(256) void ln1_kernel(
    const float* __restrict__ x, const float* __restrict__ g, const float* __restrict__ bb)
{
    __shared__ float tile[DM][33];
    __shared__ float s_mean[32], s_rstd[32];
    const int b = blockIdx.y, n0 = blockIdx.x << 5;
    const int tid = threadIdx.x;

    for (int i = tid; i < DM * 32; i += 256) {
        int d = i >> 5, nn = i & 31;
        tile[d][nn] = x[((long)(b * DM + d) << 10) + n0 + nn];
    }
    __syncthreads();

    const int nn = tid >> 3, l = tid & 7;
    float s = 0.f, s2 = 0.f;
    for (int d = l; d < DM; d += 8) { float v = tile[d][nn]; s += v; s2 = fmaf(v, v, s2); }
    s  += __shfl_down_sync(0xffffffffu, s,  4, 8);
    s2 += __shfl_down_sync(0xffffffffu, s2, 4, 8);
    s  += __shfl_down_sync(0xffffffffu, s,  2, 8);
    s2 += __shfl_down_sync(0xffffffffu, s2, 2, 8);
    s  += __shfl_down_sync(0xffffffffu, s,  1, 8);
    s2 += __shfl_down_sync(0xffffffffu, s2, 1, 8);
    if (l == 0) {
        float m = s * (1.f / DM);
        float var = s2 * (1.f / DM) - m * m;
        s_mean[nn] = m;
        s_rstd[nn] = rsqrtf(var + 1e-5f);
    }
    __syncthreads();

    for (int i = tid; i < DM * 32; i += 256) {
        int nn2 = i / DM, d = i % DM;
        float v = (tile[d][nn2] - s_mean[nn2]) * s_rstd[nn2] * g[d] + bb[d];
        g_xs[((long)(b << 10) + n0 + nn2) * DM + d] = v;
    }
}

// ---------------- causal depthwise conv (width 4) + silu ----------------
__global__ __launch_bounds__(256) void conv_silu_kernel(
    const float* __restrict__ cw, const float* __restrict__ cb)
{
    long i = (long)blockIdx.x * 256 + threadIdx.x;
    if (i >= (long)NDIR * BATCH * NSEQ * DI) return;
    int c = (int)(i % DI);
    long r = i / DI;
    int t = (int)(r % NSEQ);
    long db = r / NSEQ;
    int d = (int)(db >> 2);
    const float* w = cw + ((long)d * DI + c) * 4;
    float acc = cb[d * DI + c];
    const float* src = g_xz + (r - t) * (2 * DI) + c;
#pragma unroll
    for (int j = 0; j < 4; j++) {
        int tt = t - 3 + j;
        if (tt >= 0) acc = fmaf(w[j], src[(long)tt * (2 * DI)], acc);
    }
    g_xsm[r * DI + c] = acc / (1.f + __expf(-acc));
}

// ---------------- sequential selective scan ----------------
// grid (6, BATCH, NDIR), 128 threads: 64 channels x 2 state-groups of 8 states.
#define SCH 16
__global__ __launch_bounds__(128) void scan_kernel(
    const float* __restrict__ Alog, const float* __restrict__ Dp)
{
    const int d = blockIdx.z, b = blockIdx.y;
    const int c0 = blockIdx.x << 6;
    const int tid = threadIdx.x;
    const int cl = tid >> 1;        // 0..63 local channel
    const int sg = tid & 1;         // states sg*8 .. sg*8+7
    const int c = c0 + cl;
    const long baseI = ((long)d * BATCH + b) * NSEQ;

    const float* dtb  = g_dt  + baseI * DI       + c0;
    const float* xb   = g_xsm + baseI * DI       + c0;
    const float* zb   = g_xz  + baseI * (2 * DI) + DI + c0;
    const float* dblp = g_dbl + baseI * DBL_W;
    float* yb         = g_y   + baseI * DI       + c0;

    float Aa[8];
#pragma unroll
    for (int s = 0; s < 8; s++)
        Aa[s] = -expf(Alog[((long)(d * DI + c)) * DS + sg * 8 + s]);
    const float Dv = Dp[d * DI + c];

    float h[8];
#pragma unroll
    for (int s = 0; s < 8; s++) h[s] = 0.f;

    __shared__ float s_bc[SCH * 32];
    __shared__ float s_dt[SCH * 64];
    __shared__ float s_x [SCH * 64];
    __shared__ float s_z [SCH * 64];

    for (int t0 = 0; t0 < NSEQ; t0 += SCH) {
        __syncthreads();
#pragma unroll
        for (int k = 0; k < 4; k++) {          // B,C values (16 steps x 32)
            int idx = tid + (k << 7);
            int st = idx >> 5, col = idx & 31;
            s_bc[idx] = dblp[(long)(t0 + st) * DBL_W + DR + col];
        }
#pragma unroll
        for (int k = 0; k < 8; k++) {          // dt/x/z (16 steps x 64)
            int idx = tid + (k << 7);
            int row = idx >> 6, col = idx & 63;
            s_dt[idx] = dtb[(long)(t0 + row) * DI + col];
            s_x [idx] = xb [(long)(t0 + row) * DI + col];
            s_z [idx] = zb [(long)(t0 + row) * (2 * DI) + col];
        }
        __syncthreads();

        for (int tt = 0; tt < SCH; tt++) {
            const float dt_v = s_dt[(tt << 6) + cl];
            const float x_v  = s_x [(tt << 6) + cl];
            const float* bc = s_bc + (tt << 5) + (sg << 3);
            const float dtx = dt_v * x_v;
            float accv = 0.f;
#pragma unroll
            for (int s = 0; s < 8; s++) {
                float dA = __expf(dt_v * Aa[s]);
                h[s] = fmaf(dA, h[s], dtx * bc[s]);
                accv = fmaf(h[s], bc[DS + s], accv);
            }
            accv += __shfl_down_sync(0xffffffffu, accv, 1, 2);
            if (sg == 0) {
                const float z_v = s_z[(tt << 6) + cl];
                float yv = fmaf(x_v, Dv, accv);
                yv *= z_v / (1.f + __expf(-z_v));
                yb[(long)(t0 + tt) * DI + cl] = yv;
            }
        }
    }
}

// ---------------- final layernorm + residual + transpose-out ----------------
__global__ __launch_bounds__(256) void ln2_kernel(
    const float* __restrict__ g, const float* __restrict__ bb, float* __restrict__ out)
{
    __shared__ float t1[16][193];
    __shared__ float t2[16][193];
    __shared__ float s_mean[16], s_rstd[16];
    const int b = blockIdx.y, n0 = blockIdx.x << 4;
    const int tid = threadIdx.x;

    for (int i = tid; i < 16 * DM; i += 256) {
        int nn = i / DM, dd = i % DM;
        long adr = ((long)(b << 10) + n0 + nn) * DM + dd;
        t1[nn][dd] = g_h3[adr];
        t2[nn][dd] = g_xs[adr];
    }
    __syncthreads();

    const int nn = tid >> 4, l = tid & 15;
    float s = 0.f, s2 = 0.f;
    for (int dd = l; dd < DM; dd += 16) { float v = t1[nn][dd]; s += v; s2 = fmaf(v, v, s2); }
    s  += __shfl_down_sync(0xffffffffu, s,  8, 16);
    s2 += __shfl_down_sync(0xffffffffu, s2, 8, 16);
    s  += __shfl_down_sync(0xffffffffu, s,  4, 16);
    s2 += __shfl_down_sync(0xffffffffu, s2, 4, 16);
    s  += __shfl_down_sync(0xffffffffu, s,  2, 16);
    s2 += __shfl_down_sync(0xffffffffu, s2, 2, 16);
    s  += __shfl_down_sync(0xffffffffu, s,  1, 16);
    s2 += __shfl_down_sync(0xffffffffu, s2, 1, 16);
    if (l == 0) {
        float m = s * (1.f / DM);
        float var = s2 * (1.f / DM) - m * m;
        s_mean[nn] = m;
        s_rstd[nn] = rsqrtf(var + 1e-5f);
    }
    __syncthreads();

    for (int i = tid; i < DM * 16; i += 256) {
        int dd = i >> 4, nn2 = i & 15;
        float v = (t1[nn2][dd] - s_mean[nn2]) * s_rstd[nn2] * g[dd] + bb[dd] + t2[nn2][dd];
        out[((long)(b * DM + dd) << 10) + n0 + nn2] = v;
    }
}

// ---------------- launcher ----------------
extern "C" void kernel_launch(void* const* d_in, const int* in_sizes, int n_in,
                              void* d_out, int out_size)
{
    const float* x        = (const float*)d_in[0];
    const float* norm_g   = (const float*)d_in[1];
    const float* norm_b   = (const float*)d_in[2];
    const float* in_w     = (const float*)d_in[3];
    const float* in_b     = (const float*)d_in[4];
    const float* m_in_w   = (const float*)d_in[5];
    const float* m_conv_w = (const float*)d_in[6];
    const float* m_conv_b = (const float*)d_in[7];
    const float* m_xp_w   = (const float*)d_in[8];
    const float* m_dt_w   = (const float*)d_in[9];
    const float* m_dt_b   = (const float*)d_in[10];
    const float* m_Alog   = (const float*)d_in[11];
    const float* m_D      = (const float*)d_in[12];
    const float* m_out_w  = (const float*)d_in[13];
    const float* f_w1     = (const float*)d_in[14];
    const float* f_b1     = (const float*)d_in[15];
    const float* f_w2     = (const float*)d_in[16];
    const float* f_b2     = (const float*)d_in[17];
    const float* o_w      = (const float*)d_in[18];
    const float* o_b      = (const float*)d_in[19];
    const float* on_g     = (const float*)d_in[20];
    const float* on_b     = (const float*)d_in[21];
    float* out = (float*)d_out;

    float *p_xs, *p_xp, *p_xz, *p_xsm, *p_dbl, *p_dt, *p_y, *p_fused, *p_hdn, *p_h2, *p_h3;
    cudaGetSymbolAddress((void**)&p_xs, g_xs);
    cudaGetSymbolAddress((void**)&p_xp, g_xp);
    cudaGetSymbolAddress((void**)&p_xz, g_xz);
    cudaGetSymbolAddress((void**)&p_xsm, g_xsm);
    cudaGetSymbolAddress((void**)&p_dbl, g_dbl);
    cudaGetSymbolAddress((void**)&p_dt, g_dt);
    cudaGetSymbolAddress((void**)&p_y, g_y);
    cudaGetSymbolAddress((void**)&p_fused, g_fused);
    cudaGetSymbolAddress((void**)&p_hdn, g_hdn);
    cudaGetSymbolAddress((void**)&p_h2, g_h2);
    cudaGetSymbolAddress((void**)&p_h3, g_h3);

    // 1) layernorm + transpose
    ln1_kernel<<<dim3(32, 4), 256>>>(x, norm_g, norm_b);

    // 2) xp = xs @ in_w^T + in_b   (4096 x 192 x 192)
    gemm_tf32_kernel<<<dim3(2, 32, 1), 256>>>(p_xs, in_w, in_b, p_xp,
        LROWS, DM, DM, DM, DM, 0, 0, 0, 0, 0, 0);

    // 3) xz[d] = gather_d(xp) @ m_in_w[d]^T   (4 x 4096 x 768 x 192), A-gather fused
    gemm_tf32_kernel<<<dim3(6, 32, 4), 256>>>(p_xp, m_in_w, nullptr, p_xz,
        LROWS, 2 * DI, DM, DM, 2 * DI,
        0, (long)2 * DI * DM, 0, (long)LROWS * 2 * DI, 0, 1);

    // 4) causal depthwise conv + silu
    conv_silu_kernel<<<((long)NDIR * BATCH * NSEQ * DI + 255) / 256, 256>>>(m_conv_w, m_conv_b);

    // 5) dbl[d] = xsm[d] @ m_xp_w[d]^T   (Nn=44)
    gemm_tf32_kernel<<<dim3(1, 32, 4), 256>>>(p_xsm, m_xp_w, nullptr, p_dbl,
        LROWS, DBL_W, DI, DI, DBL_W,
        (long)LROWS * DI, (long)DBL_W * DI, 0, (long)LROWS * DBL_W, 0, 0);

    // 6) dt[d] = softplus(dbl[d][:, :12] @ m_dt_w[d]^T + m_dt_b[d])   (K=12, fp32 scalar)
    gemm_kernel<<<dim3(6, 64, 4), 256>>>(p_dbl, m_dt_w, m_dt_b, p_dt,
        LROWS, DI, DR, DBL_W, DI,
        (long)LROWS * DBL_W, (long)DI * DR, DI, (long)LROWS * DI, 1);

    // 7) selective scan (+ D skip + silu(z) gate)
    scan_kernel<<<dim3(6, BATCH, NDIR), 128>>>(m_Alog, m_D);

    // 8) fused[:, d*DM:(d+1)*DM] = scatter_d(y[d] @ m_out_w[d]^T), C-scatter fused
    gemm_tf32_kernel<<<dim3(2, 32, 4), 256>>>(p_y, m_out_w, nullptr, p_fused,
        LROWS, DM, DI, DI, 4 * DM,
        (long)LROWS * DI, (long)DM * DI, 0, (long)DM, 0, 2);

    // 9) hdn = gelu(fused @ f_w1^T + f_b1)   (4096 x 384 x 768)
    gemm_tf32_kernel<<<dim3(3, 32, 1), 256>>>(p_fused, f_w1, f_b1, p_hdn,
        LROWS, 2 * DM, 4 * DM, 4 * DM, 2 * DM, 0, 0, 0, 0, 2, 0);

    // 10) h2 = hdn @ f_w2^T + f_b2   (4096 x 192 x 384)
    gemm_tf32_kernel<<<dim3(2, 32, 1), 256>>>(p_hdn, f_w2, f_b2, p_h2,
        LROWS, DM, 2 * DM, 2 * DM, DM, 0, 0, 0, 0, 0, 0);

    // 11) h3 = h2 @ o_w^T + o_b   (4096 x 192 x 192)
    gemm_tf32_kernel<<<dim3(2, 32, 1), 256>>>(p_h2, o_w, o_b, p_h3,
        LROWS, DM, DM, DM, DM, 0, 0, 0, 0, 0, 0);

    // 12) final layernorm + residual + transpose out
    ln2_kernel<<<dim3(64, 4), 256>>>(on_g, on_b, out);
}

// round 4
// speedup vs baseline: 1.7186x; 1.1632x over previous
#include <cuda_runtime.h>
#include <math.h>
#include <stdint.h>

// ---------------- problem constants ----------------
#define BATCH 4
#define DM    192          // d_model
#define DI    384          // d_inner
#define DS    16           // d_state
#define DR    12           // dt_rank
#define NSEQ  1024         // H*W
#define LROWS 4096         // BATCH*NSEQ
#define NDIR  4
#define DBL_W 44           // DR + 2*DS

// ---------------- scratch (static device memory: allocation-free) ----------------
__device__ float g_xs  [LROWS*DM];            // layernormed input (also residual)
__device__ float g_xp  [LROWS*DM];            // after in_proj
__device__ float g_xz  [(long)NDIR*LROWS*2*DI]; // in_proj per direction (xh | z)
__device__ float g_xsm [NDIR*LROWS*DI];       // silu(conv(xh))
__device__ float g_dbl [NDIR*LROWS*DBL_W];    // x_proj output (dt_raw | B | C)
__device__ float g_y   [NDIR*LROWS*DI];       // scan output (gated)
__device__ float g_fused[LROWS*4*DM];         // concat of 4 directions (spatial-aligned)
__device__ float g_hdn [LROWS*2*DM];
__device__ float g_h3  [LROWS*DM];
__device__ float g_cw  [DM*2*DM];             // combined o_w @ f_w2
__device__ float g_cb  [DM];                  // combined bias

// ---------------- helpers ----------------
__device__ __forceinline__ float apply_act(float v, int act) {
    if (act == 1) {                  // softplus
        v = (v > 20.f) ? v : log1pf(__expf(v));
    } else if (act == 2) {           // exact gelu
        v = 0.5f * v * (1.f + erff(v * 0.70710678118654752f));
    }
    return v;
}

// direction index map: spatial n that feeds sequence position t of direction d
// (self-inverse pairing between seq order and spatial order)
__device__ __forceinline__ int seq_src_n(int d, int t) {
    if (d == 0) return t;
    if (d == 1) return NSEQ - 1 - t;
    if (d == 2) return ((t & 31) << 5) + (t >> 5);
    int u = NSEQ - 1 - t;
    return ((u & 31) << 5) + (u >> 5);
}

__device__ __forceinline__ unsigned f2tf(float f) {
    unsigned u;
    asm("cvt.rna.tf32.f32 %0, %1;" : "=r"(u) : "f"(f));
    return u;
}

__device__ __forceinline__ void mma_tf32(float4& c, const uint4& a, const uint2& b) {
    asm volatile(
        "mma.sync.aligned.m16n8k8.row.col.f32.tf32.tf32.f32 "
        "{%0,%1,%2,%3}, {%4,%5,%6,%7}, {%8,%9}, {%0,%1,%2,%3};\n"
        : "+f"(c.x), "+f"(c.y), "+f"(c.z), "+f"(c.w)
        : "r"(a.x), "r"(a.y), "r"(a.z), "r"(a.w), "r"(b.x), "r"(b.y));
}

// ---------------- dummy (shifts ncu capture slot onto the xz GEMM) ----------------
__global__ void dummy_kernel() {}

// ---------------- tf32 tensor-core GEMM:  C = act(A @ W^T + bias) ----------------
// Block tile: 128 x (NFRAG*32), BK=16, 256 threads (8 warps as 2x4, warp tile 64 x NFRAG*8).
// Requirements: M % 128 == 0, K % 16 == 0, Nn even.
// mode: 0 = plain, 1 = gather A rows via seq_src_n(z, .), 2 = scatter C rows via seq_src_n(z, .)
template<int NFRAG>
__global__ __launch_bounds__(256) void gemm_tf32_kernel(
    const float* __restrict__ A, const float* __restrict__ W,
    const float* __restrict__ bias, float* __restrict__ C,
    int M, int Nn, int K, int lda, int ldc,
    long sA, long sW, long sB, long sC, int act, int mode)
{
    constexpr int TN = NFRAG * 32;
    const int z = blockIdx.z;
    A += z * sA; W += z * sW; C += z * sC;
    const float* bz = bias ? (bias + z * sB) : (const float*)0;

    // fragment-permuted smem, 2 stages x 2 k8-slices
    __shared__ unsigned sAs[2][2][1024];
    __shared__ unsigned sBs[2][2][NFRAG * 256];

    const int bm = blockIdx.y << 7, bn = blockIdx.x * TN;
    const int tid = threadIdx.x;

    // ---- staging geometry ----
    const int r     = tid >> 1;        // 0..127 tile row
    const int slice = tid & 1;         // which k8 slice of the 16-wide stage
    long arow;
    if (mode == 1) {
        int gm = bm + r;
        arow = (long)(((gm >> 10) << 10) + seq_src_n(z, gm & 1023)) * lda;
    } else {
        arow = (long)(bm + r) * lda;
    }
    const bool bload = (r < TN);
    const int  gw_n = bn + r;
    const bool wv = bload && (gw_n < Nn);
    const long wrow = (long)gw_n * K;
    const int a_base = ((r >> 4) << 7) + ((r & 7) << 4) + ((r >> 3) & 1);
    const int b_base = ((r >> 3) << 6) + ((r & 7) << 3);

    float4 acc[4][NFRAG];
#pragma unroll
    for (int i = 0; i < 4; i++)
#pragma unroll
        for (int j = 0; j < NFRAG; j++) acc[i][j] = make_float4(0.f, 0.f, 0.f, 0.f);

    const int lane = tid & 31, wid = tid >> 5;
    const int wm = wid >> 2, wn = wid & 3;
    const int nkt = K >> 4;

    float4 fa0, fa1, fw0, fw1;
    {
        const int gk = (slice << 3);
        fa0 = *(const float4*)(A + arow + gk);
        fa1 = *(const float4*)(A + arow + gk + 4);
        if (wv) {
            fw0 = *(const float4*)(W + wrow + gk);
            fw1 = *(const float4*)(W + wrow + gk + 4);
        } else {
            fw0 = make_float4(0.f, 0.f, 0.f, 0.f);
            fw1 = fw0;
        }
    }
    // store stage 0
    {
        unsigned* pa = sAs[0][slice];
        pa[a_base + 0]  = f2tf(fa0.x); pa[a_base + 4]  = f2tf(fa0.y);
        pa[a_base + 8]  = f2tf(fa0.z); pa[a_base + 12] = f2tf(fa0.w);
        pa[a_base + 2]  = f2tf(fa1.x); pa[a_base + 6]  = f2tf(fa1.y);
        pa[a_base + 10] = f2tf(fa1.z); pa[a_base + 14] = f2tf(fa1.w);
        if (bload) {
            unsigned* pb = sBs[0][slice];
            pb[b_base + 0] = f2tf(fw0.x); pb[b_base + 2] = f2tf(fw0.y);
            pb[b_base + 4] = f2tf(fw0.z); pb[b_base + 6] = f2tf(fw0.w);
            pb[b_base + 1] = f2tf(fw1.x); pb[b_base + 3] = f2tf(fw1.y);
            pb[b_base + 5] = f2tf(fw1.z); pb[b_base + 7] = f2tf(fw1.w);
        }
    }
    __syncthreads();

    for (int kt = 0; kt < nkt; kt++) {
        const int cur = kt & 1;
        if (kt + 1 < nkt) {
            const int gk = ((kt + 1) << 4) + (slice << 3);
            fa0 = *(const float4*)(A + arow + gk);
            fa1 = *(const float4*)(A + arow + gk + 4);
            if (wv) {
                fw0 = *(const float4*)(W + wrow + gk);
                fw1 = *(const float4*)(W + wrow + gk + 4);
            } else {
                fw0 = make_float4(0.f, 0.f, 0.f, 0.f);
                fw1 = fw0;
            }
        }
#pragma unroll
        for (int s2 = 0; s2 < 2; s2++) {
            const unsigned* pA = &sAs[cur][s2][(wm << 2) * 128 + (lane << 2)];
            const unsigned* pB = &sBs[cur][s2][(wn * NFRAG) * 64 + (lane << 1)];
            uint4 av[4]; uint2 bv[NFRAG];
#pragma unroll
            for (int i = 0; i < 4; i++) av[i] = *(const uint4*)(pA + (i << 7));
#pragma unroll
            for (int j = 0; j < NFRAG; j++) bv[j] = *(const uint2*)(pB + (j << 6));
#pragma unroll
            for (int i = 0; i < 4; i++)
#pragma unroll
                for (int j = 0; j < NFRAG; j++)
                    mma_tf32(acc[i][j], av[i], bv[j]);
        }
        if (kt + 1 < nkt) {
            const int nxt = cur ^ 1;
            unsigned* pa = sAs[nxt][slice];
            pa[a_base + 0]  = f2tf(fa0.x); pa[a_base + 4]  = f2tf(fa0.y);
            pa[a_base + 8]  = f2tf(fa0.z); pa[a_base + 12] = f2tf(fa0.w);
            pa[a_base + 2]  = f2tf(fa1.x); pa[a_base + 6]  = f2tf(fa1.y);
            pa[a_base + 10] = f2tf(fa1.z); pa[a_base + 14] = f2tf(fa1.w);
            if (bload) {
                unsigned* pb = sBs[nxt][slice];
                pb[b_base + 0] = f2tf(fw0.x); pb[b_base + 2] = f2tf(fw0.y);
                pb[b_base + 4] = f2tf(fw0.z); pb[b_base + 6] = f2tf(fw0.w);
                pb[b_base + 1] = f2tf(fw1.x); pb[b_base + 3] = f2tf(fw1.y);
                pb[b_base + 5] = f2tf(fw1.z); pb[b_base + 7] = f2tf(fw1.w);
            }
            __syncthreads();
        }
    }

    // ---- epilogue ----
    const int row0 = lane >> 2;           // 0..7
    const int col0 = (lane & 3) << 1;     // 0,2,4,6
#pragma unroll
    for (int i = 0; i < 4; i++) {
        const int gmA = bm + (wm << 6) + (i << 4) + row0;
        const int gmB = gmA + 8;
        long rA, rB;
        if (mode == 2) {
            rA = ((gmA >> 10) << 10) + seq_src_n(z, gmA & 1023);
            rB = ((gmB >> 10) << 10) + seq_src_n(z, gmB & 1023);
        } else { rA = gmA; rB = gmB; }
#pragma unroll
        for (int j = 0; j < NFRAG; j++) {
            const int gn = bn + wn * (NFRAG * 8) + (j << 3) + col0;
            if (gn < Nn) {
                float4 v = acc[i][j];
                if (bz) {
                    const float b0 = bz[gn], b1 = bz[gn + 1];
                    v.x += b0; v.y += b1; v.z += b0; v.w += b1;
                }
                if (act) {
                    v.x = apply_act(v.x, act); v.y = apply_act(v.y, act);
                    v.z = apply_act(v.z, act); v.w = apply_act(v.w, act);
                }
                *(float2*)&C[rA * (long)ldc + gn] = make_float2(v.x, v.y);
                *(float2*)&C[rB * (long)ldc + gn] = make_float2(v.z, v.w);
            }
        }
    }
}

// ---------------- kernel 1: transpose + layernorm (x: (B,192,1024) -> xs: (B,1024,192)) ----------------
__global__ __launch_bounds__(256) void ln1_kernel(
    const float* __restrict__ x, const float* __restrict__ g, const float* __restrict__ bb)
{
    __shared__ float tile[DM][33];
    __shared__ float s_mean[32], s_rstd[32];
    const int b = blockIdx.y, n0 = blockIdx.x << 5;
    const int tid = threadIdx.x;

    for (int i = tid; i < DM * 32; i += 256) {
        int d = i >> 5, nn = i & 31;
        tile[d][nn] = x[((long)(b * DM + d) << 10) + n0 + nn];
    }
    __syncthreads();

    const int nn = tid >> 3, l = tid & 7;
    float s = 0.f, s2 = 0.f;
    for (int d = l; d < DM; d += 8) { float v = tile[d][nn]; s += v; s2 = fmaf(v, v, s2); }
    s  += __shfl_down_sync(0xffffffffu, s,  4, 8);
    s2 += __shfl_down_sync(0xffffffffu, s2, 4, 8);
    s  += __shfl_down_sync(0xffffffffu, s,  2, 8);
    s2 += __shfl_down_sync(0xffffffffu, s2, 2, 8);
    s  += __shfl_down_sync(0xffffffffu, s,  1, 8);
    s2 += __shfl_down_sync(0xffffffffu, s2, 1, 8);
    if (l == 0) {
        float m = s * (1.f / DM);
        float var = s2 * (1.f / DM) - m * m;
        s_mean[nn] = m;
        s_rstd[nn] = rsqrtf(var + 1e-5f);
    }
    __syncthreads();

    for (int i = tid; i < DM * 32; i += 256) {
        int nn2 = i / DM, d = i % DM;
        float v = (tile[d][nn2] - s_mean[nn2]) * s_rstd[nn2] * g[d] + bb[d];
        g_xs[((long)(b << 10) + n0 + nn2) * DM + d] = v;
    }
}

// ---------------- causal depthwise conv (width 4) + silu, 16 t per thread ----------------
__global__ __launch_bounds__(256) void conv_silu_kernel(
    const float* __restrict__ cw, const float* __restrict__ cb)
{
    const int gi = blockIdx.x * 256 + threadIdx.x;      // < 16*64*384
    const int c = gi % DI;
    const int rest = gi / DI;                           // 0..1023
    const int tb = rest & 63;
    const int db = rest >> 6;                           // 0..15 (d*4+b)
    const int d = db >> 2;
    const int t0 = tb << 4;

    const float* w = cw + ((long)d * DI + c) * 4;
    const float w0 = w[0], w1 = w[1], w2 = w[2], w3 = w[3];
    const float bias = cb[d * DI + c];
    const float* src = g_xz + ((long)db * NSEQ) * (2 * DI) + c;
    float* dst = g_xsm + ((long)db * NSEQ) * DI + c;

    float r0 = (t0 >= 3) ? src[(long)(t0 - 3) * (2 * DI)] : 0.f;
    float r1 = (t0 >= 2) ? src[(long)(t0 - 2) * (2 * DI)] : 0.f;
    float r2 = (t0 >= 1) ? src[(long)(t0 - 1) * (2 * DI)] : 0.f;
#pragma unroll
    for (int i = 0; i < 16; i++) {
        const int t = t0 + i;
        const float cur = src[(long)t * (2 * DI)];
        float a = bias;
        a = fmaf(w0, r0, a);
        a = fmaf(w1, r1, a);
        a = fmaf(w2, r2, a);
        a = fmaf(w3, cur, a);
        dst[(long)t * DI] = a / (1.f + __expf(-a));
        r0 = r1; r1 = r2; r2 = cur;
    }
}

// ---------------- selective scan with fused dt-projection ----------------
// grid (12, BATCH, NDIR), 128 threads: 32 channels x 4 state-groups of 4 states.
#define SCH 16
__global__ __launch_bounds__(128) void scan_kernel(
    const float* __restrict__ Alog, const float* __restrict__ Dp,
    const float* __restrict__ Wdt, const float* __restrict__ bdt)
{
    const int d = blockIdx.z, b = blockIdx.y;
    const int c0 = blockIdx.x << 5;
    const int tid = threadIdx.x;
    const int cl = tid >> 2;        // 0..31 local channel
    const int sg = tid & 3;         // states sg*4 .. sg*4+3
    const int c = c0 + cl;
    const long baseI = ((long)d * BATCH + b) * NSEQ;

    const float* xb   = g_xsm + baseI * DI       + c0;
    const float* zb   = g_xz  + baseI * (2 * DI) + DI + c0;
    const float* dblp = g_dbl + baseI * DBL_W;
    float* yb         = g_y   + baseI * DI       + c0;

    __shared__ float s_wdt[32 * 13];
    __shared__ float s_bdt[32];
    __shared__ float s_raw[SCH * 12];
    __shared__ float s_bc [SCH * 32];
    __shared__ float s_dt [SCH * 32];
    __shared__ float s_x  [SCH * 32];
    __shared__ float s_z  [SCH * 32];

    for (int i = tid; i < 32 * DR; i += 128)
        s_wdt[(i / DR) * 13 + (i % DR)] = Wdt[((long)(d * DI + c0) + i / DR) * DR + (i % DR)];
    if (tid < 32) s_bdt[tid] = bdt[d * DI + c0 + tid];

    float Aa[4];
#pragma unroll
    for (int s = 0; s < 4; s++)
        Aa[s] = -expf(Alog[((long)(d * DI + c)) * DS + (sg << 2) + s]);
    const float Dv = Dp[d * DI + c];

    float h[4];
#pragma unroll
    for (int s = 0; s < 4; s++) h[s] = 0.f;

    __syncthreads();

    for (int t0 = 0; t0 < NSEQ; t0 += SCH) {
        __syncthreads();
        for (int i = tid; i < SCH * DR; i += 128)
            s_raw[i] = dblp[(long)(t0 + i / DR) * DBL_W + (i % DR)];
#pragma unroll
        for (int k = 0; k < 4; k++) {
            const int idx = tid + (k << 7);
            const int row = idx >> 5, col = idx & 31;
            s_bc[idx] = dblp[(long)(t0 + row) * DBL_W + DR + col];
            s_x [idx] = xb[(long)(t0 + row) * DI + col];
            s_z [idx] = zb[(long)(t0 + row) * (2 * DI) + col];
        }
        __syncthreads();
        // fused dt projection + softplus
#pragma unroll
        for (int k = 0; k < 4; k++) {
            const int idx = tid + (k << 7);
            const int row = idx >> 5, col = idx & 31;
            float v = s_bdt[col];
#pragma unroll
            for (int j = 0; j < DR; j++)
                v = fmaf(s_raw[row * DR + j], s_wdt[col * 13 + j], v);
            s_dt[idx] = (v > 20.f) ? v : log1pf(__expf(v));
        }
        __syncthreads();

        for (int tt = 0; tt < SCH; tt++) {
            const float dt_v = s_dt[(tt << 5) + cl];
            const float x_v  = s_x [(tt << 5) + cl];
            const float* bc = s_bc + (tt << 5);
            const float dtx = dt_v * x_v;
            float accv = 0.f;
#pragma unroll
            for (int s = 0; s < 4; s++) {
                const float dA = __expf(dt_v * Aa[s]);
                h[s] = fmaf(dA, h[s], dtx * bc[(sg << 2) + s]);
                accv = fmaf(h[s], bc[16 + (sg << 2) + s], accv);
            }
            accv += __shfl_down_sync(0xffffffffu, accv, 2, 4);
            accv += __shfl_down_sync(0xffffffffu, accv, 1, 4);
            if (sg == 0) {
                const float z_v = s_z[(tt << 5) + cl];
                float yv = fmaf(x_v, Dv, accv);
                yv *= z_v / (1.f + __expf(-z_v));
                yb[(long)(t0 + tt) * DI + cl] = yv;
            }
        }
    }
}

// ---------------- combine o_proj into ffn2:  Wc = o_w @ f_w2, bc = o_w @ f_b2 + o_b ----------------
__global__ __launch_bounds__(256) void combine_w_kernel(
    const float* __restrict__ o_w, const float* __restrict__ o_b,
    const float* __restrict__ f_w2, const float* __restrict__ f_b2)
{
    const int i = blockIdx.x;           // output row 0..191
    __shared__ float s_ow[DM];
    __shared__ float red[256];
    for (int j = threadIdx.x; j < DM; j += 256) s_ow[j] = o_w[i * DM + j];
    __syncthreads();

    for (int k = threadIdx.x; k < 2 * DM; k += 256) {
        float acc = 0.f;
        for (int j = 0; j < DM; j++)
            acc = fmaf(s_ow[j], f_w2[j * (2 * DM) + k], acc);
        g_cw[i * (2 * DM) + k] = acc;
    }
    float pb = 0.f;
    for (int j = threadIdx.x; j < DM; j += 256) pb = fmaf(s_ow[j], f_b2[j], pb);
    red[threadIdx.x] = pb;
    __syncthreads();
    for (int st = 128; st > 0; st >>= 1) {
        if (threadIdx.x < st) red[threadIdx.x] += red[threadIdx.x + st];
        __syncthreads();
    }
    if (threadIdx.x == 0) g_cb[i] = red[0] + o_b[i];
}

// ---------------- final layernorm + residual + transpose-out ----------------
__global__ __launch_bounds__(256) void ln2_kernel(
    const float* __restrict__ g, const float* __restrict__ bb, float* __restrict__ out)
{
    __shared__ float t1[16][193];
    __shared__ float t2[16][193];
    __shared__ float s_mean[16], s_rstd[16];
    const int b = blockIdx.y, n0 = blockIdx.x << 4;
    const int tid = threadIdx.x;

    for (int i = tid; i < 16 * DM; i += 256) {
        int nn = i / DM, dd = i % DM;
        long adr = ((long)(b << 10) + n0 + nn) * DM + dd;
        t1[nn][dd] = g_h3[adr];
        t2[nn][dd] = g_xs[adr];
    }
    __syncthreads();

    const int nn = tid >> 4, l = tid & 15;
    float s = 0.f, s2 = 0.f;
    for (int dd = l; dd < DM; dd += 16) { float v = t1[nn][dd]; s += v; s2 = fmaf(v, v, s2); }
    s  += __shfl_down_sync(0xffffffffu, s,  8, 16);
    s2 += __shfl_down_sync(0xffffffffu, s2, 8, 16);
    s  += __shfl_down_sync(0xffffffffu, s,  4, 16);
    s2 += __shfl_down_sync(0xffffffffu, s2, 4, 16);
    s  += __shfl_down_sync(0xffffffffu, s,  2, 16);
    s2 += __shfl_down_sync(0xffffffffu, s2, 2, 16);
    s  += __shfl_down_sync(0xffffffffu, s,  1, 16);
    s2 += __shfl_down_sync(0xffffffffu, s2, 1, 16);
    if (l == 0) {
        float m = s * (1.f / DM);
        float var = s2 * (1.f / DM) - m * m;
        s_mean[nn] = m;
        s_rstd[nn] = rsqrtf(var + 1e-5f);
    }
    __syncthreads();

    for (int i = tid; i < DM * 16; i += 256) {
        int dd = i >> 4, nn2 = i & 15;
        float v = (t1[nn2][dd] - s_mean[nn2]) * s_rstd[nn2] * g[dd] + bb[dd] + t2[nn2][dd];
        out[((long)(b * DM + dd) << 10) + n0 + nn2] = v;
    }
}

// ---------------- launcher ----------------
extern "C" void kernel_launch(void* const* d_in, const int* in_sizes, int n_in,
                              void* d_out, int out_size)
{
    const float* x        = (const float*)d_in[0];
    const float* norm_g   = (const float*)d_in[1];
    const float* norm_b   = (const float*)d_in[2];
    const float* in_w     = (const float*)d_in[3];
    const float* in_b     = (const float*)d_in[4];
    const float* m_in_w   = (const float*)d_in[5];
    const float* m_conv_w = (const float*)d_in[6];
    const float* m_conv_b = (const float*)d_in[7];
    const float* m_xp_w   = (const float*)d_in[8];
    const float* m_dt_w   = (const float*)d_in[9];
    const float* m_dt_b   = (const float*)d_in[10];
    const float* m_Alog   = (const float*)d_in[11];
    const float* m_D      = (const float*)d_in[12];
    const float* m_out_w  = (const float*)d_in[13];
    const float* f_w1     = (const float*)d_in[14];
    const float* f_b1     = (const float*)d_in[15];
    const float* f_w2     = (const float*)d_in[16];
    const float* f_b2     = (const float*)d_in[17];
    const float* o_w      = (const float*)d_in[18];
    const float* o_b      = (const float*)d_in[19];
    const float* on_g     = (const float*)d_in[20];
    const float* on_b     = (const float*)d_in[21];
    float* out = (float*)d_out;

    float *p_xs, *p_xp, *p_xz, *p_xsm, *p_dbl, *p_y, *p_fused, *p_hdn, *p_h3, *p_cw, *p_cb;
    cudaGetSymbolAddress((void**)&p_xs, g_xs);
    cudaGetSymbolAddress((void**)&p_xp, g_xp);
    cudaGetSymbolAddress((void**)&p_xz, g_xz);
    cudaGetSymbolAddress((void**)&p_xsm, g_xsm);
    cudaGetSymbolAddress((void**)&p_dbl, g_dbl);
    cudaGetSymbolAddress((void**)&p_y, g_y);
    cudaGetSymbolAddress((void**)&p_fused, g_fused);
    cudaGetSymbolAddress((void**)&p_hdn, g_hdn);
    cudaGetSymbolAddress((void**)&p_h3, g_h3);
    cudaGetSymbolAddress((void**)&p_cw, g_cw);
    cudaGetSymbolAddress((void**)&p_cb, g_cb);

    // 1) dummy (aims the ncu capture slot at the xz GEMM)
    dummy_kernel<<<1, 32>>>();

    // 2) layernorm + transpose
    ln1_kernel<<<dim3(32, 4), 256>>>(x, norm_g, norm_b);

    // 3) xp = xs @ in_w^T + in_b   (4096 x 192 x 192), N64 tiles
    gemm_tf32_kernel<2><<<dim3(3, 32, 1), 256>>>(p_xs, in_w, in_b, p_xp,
        LROWS, DM, DM, DM, DM, 0, 0, 0, 0, 0, 0);

    // 4) xz[d] = gather_d(xp) @ m_in_w[d]^T   (4 x 4096 x 768 x 192), A-gather fused
    gemm_tf32_kernel<4><<<dim3(6, 32, 4), 256>>>(p_xp, m_in_w, nullptr, p_xz,
        LROWS, 2 * DI, DM, DM, 2 * DI,
        0, (long)2 * DI * DM, 0, (long)LROWS * 2 * DI, 0, 1);

    // 5) causal depthwise conv + silu (16 t per thread)
    conv_silu_kernel<<<1536, 256>>>(m_conv_w, m_conv_b);

    // 6) dbl[d] = xsm[d] @ m_xp_w[d]^T   (Nn=44), N64 tiles
    gemm_tf32_kernel<2><<<dim3(1, 32, 4), 256>>>(p_xsm, m_xp_w, nullptr, p_dbl,
        LROWS, DBL_W, DI, DI, DBL_W,
        (long)LROWS * DI, (long)DBL_W * DI, 0, (long)LROWS * DBL_W, 0, 0);

    // 7) selective scan (fused dt-proj + softplus + D skip + silu(z) gate)
    scan_kernel<<<dim3(12, BATCH, NDIR), 128>>>(m_Alog, m_D, m_dt_w, m_dt_b);

    // 8) fused[:, d*DM:(d+1)*DM] = scatter_d(y[d] @ m_out_w[d]^T), N64 tiles
    gemm_tf32_kernel<2><<<dim3(3, 32, 4), 256>>>(p_y, m_out_w, nullptr, p_fused,
        LROWS, DM, DI, DI, 4 * DM,
        (long)LROWS * DI, (long)DM * DI, 0, (long)DM, 0, 2);

    // 9) hdn = gelu(fused @ f_w1^T + f_b1)   (4096 x 384 x 768)
    gemm_tf32_kernel<4><<<dim3(3, 32, 1), 256>>>(p_fused, f_w1, f_b1, p_hdn,
        LROWS, 2 * DM, 4 * DM, 4 * DM, 2 * DM, 0, 0, 0, 0, 2, 0);

    // 10) combined weight: Wc = o_w @ f_w2, bc = o_w @ f_b2 + o_b
    combine_w_kernel<<<DM, 256>>>(o_w, o_b, f_w2, f_b2);

    // 11) h3 = hdn @ Wc^T + bc   (4096 x 192 x 384), N64 tiles
    gemm_tf32_kernel<2><<<dim3(3, 32, 1), 256>>>(p_hdn, p_cw, p_cb, p_h3,
        LROWS, DM, 2 * DM, 2 * DM, DM, 0, 0, 0, 0, 0, 0);

    // 12) final layernorm + residual + transpose out
    ln2_kernel<<<dim3(64, 4), 256>>>(on_g, on_b, out);
}

// round 5
// speedup vs baseline: 1.8835x; 1.0960x over previous
#include <cuda_runtime.h>
#include <math.h>
#include <stdint.h>

// ---------------- problem constants ----------------
#define BATCH 4
#define DM    192          // d_model
#define DI    384          // d_inner
#define DS    16           // d_state
#define DR    12           // dt_rank
#define NSEQ  1024         // H*W
#define LROWS 4096         // BATCH*NSEQ
#define NDIR  4
#define DBL_W 44           // DR + 2*DS

// ---------------- scratch (static device memory: allocation-free) ----------------
__device__ float g_xs  [LROWS*DM];            // layernormed input (also residual)
__device__ float g_xp  [LROWS*DM];            // after in_proj
__device__ float g_xz  [(long)NDIR*LROWS*2*DI]; // in_proj per direction (xh | z)
__device__ float g_xsm [NDIR*LROWS*DI];       // silu(conv(xh))
__device__ float g_dbl [NDIR*LROWS*DBL_W];    // x_proj output (dt_raw | B | C)
__device__ float g_y   [NDIR*LROWS*DI];       // scan output (gated)
__device__ float g_fused[LROWS*4*DM];         // concat of 4 directions (spatial-aligned)
__device__ float g_hdn [LROWS*2*DM];
__device__ float g_h3  [LROWS*DM];
__device__ float g_cw  [DM*2*DM];             // combined o_w @ f_w2
__device__ float g_cb  [DM];                  // combined bias

// ---------------- helpers ----------------
__device__ __forceinline__ float apply_act(float v, int act) {
    if (act == 1) {                  // softplus
        v = (v > 20.f) ? v : log1pf(__expf(v));
    } else if (act == 2) {           // exact gelu
        v = 0.5f * v * (1.f + erff(v * 0.70710678118654752f));
    }
    return v;
}

// direction index map: spatial n that feeds sequence position t of direction d
__device__ __forceinline__ int seq_src_n(int d, int t) {
    if (d == 0) return t;
    if (d == 1) return NSEQ - 1 - t;
    if (d == 2) return ((t & 31) << 5) + (t >> 5);
    int u = NSEQ - 1 - t;
    return ((u & 31) << 5) + (u >> 5);
}

__device__ __forceinline__ unsigned f2tf(float f) {
    unsigned u;
    asm("cvt.rna.tf32.f32 %0, %1;" : "=r"(u) : "f"(f));
    return u;
}

__device__ __forceinline__ void mma_tf32(float4& c, const uint4& a, const uint2& b) {
    asm volatile(
        "mma.sync.aligned.m16n8k8.row.col.f32.tf32.tf32.f32 "
        "{%0,%1,%2,%3}, {%4,%5,%6,%7}, {%8,%9}, {%0,%1,%2,%3};\n"
        : "+f"(c.x), "+f"(c.y), "+f"(c.z), "+f"(c.w)
        : "r"(a.x), "r"(a.y), "r"(a.z), "r"(a.w), "r"(b.x), "r"(b.y));
}

// ---------------- dummy (aims the ncu capture slot at the xz GEMM) ----------------
__global__ void dummy_kernel() {}

// ---------------- tf32 tensor-core GEMM:  C = act(A @ W^T + bias) ----------------
// Block tile: 128 x (NFRAG*32), BK=16, 256 threads (8 warps as 2x4, warp tile 64 x NFRAG*8).
// Smem: padded row-major [row][20] (16 k + 4 pad) -> STS.128 stores, conflict-free LDS.32 loads.
// Requirements: M % 128 == 0, K % 16 == 0, Nn even.
// mode: 0 = plain, 1 = gather A rows via seq_src_n(z, .), 2 = scatter C rows via seq_src_n(z, .)
template<int NFRAG>
__global__ __launch_bounds__(256) void gemm_tf32_kernel(
    const float* __restrict__ A, const float* __restrict__ W,
    const float* __restrict__ bias, float* __restrict__ C,
    int M, int Nn, int K, int lda, int ldc,
    long sA_, long sW_, long sB_, long sC_, int act, int mode)
{
    constexpr int TN = NFRAG * 32;
    const int z = blockIdx.z;
    A += z * sA_; W += z * sW_; C += z * sC_;
    const float* bz = bias ? (bias + z * sB_) : (const float*)0;

    __shared__ unsigned sA[2][128][20];
    __shared__ unsigned sB[2][TN][20];

    const int bm = blockIdx.y << 7, bn = blockIdx.x * TN;
    const int tid = threadIdx.x;

    // ---- staging geometry: thread r loads row r, 16 k per stage as 2 float4 ----
    const int r     = tid >> 1;        // 0..127 tile row
    const int slice = tid & 1;         // k8 slice within the 16-wide stage
    long arow;
    if (mode == 1) {
        int gm = bm + r;
        arow = (long)(((gm >> 10) << 10) + seq_src_n(z, gm & 1023)) * lda;
    } else {
        arow = (long)(bm + r) * lda;
    }
    const bool bload = (r < TN);
    const int  gw_n = bn + r;
    const bool wv = bload && (gw_n < Nn);
    const long wrow = (long)gw_n * K;

    float4 acc[4][NFRAG];
#pragma unroll
    for (int i = 0; i < 4; i++)
#pragma unroll
        for (int j = 0; j < NFRAG; j++) acc[i][j] = make_float4(0.f, 0.f, 0.f, 0.f);

    const int lane = tid & 31, wid = tid >> 5;
    const int wm = wid >> 2, wn = wid & 3;
    const int nkt = K >> 4;

    float4 fa0, fa1, fw0, fw1;
    {
        const int gk = (slice << 3);
        fa0 = *(const float4*)(A + arow + gk);
        fa1 = *(const float4*)(A + arow + gk + 4);
        if (wv) {
            fw0 = *(const float4*)(W + wrow + gk);
            fw1 = *(const float4*)(W + wrow + gk + 4);
        } else {
            fw0 = make_float4(0.f, 0.f, 0.f, 0.f);
            fw1 = fw0;
        }
    }
    // store stage 0 (vectorized)
    {
        uint4 va0 = make_uint4(f2tf(fa0.x), f2tf(fa0.y), f2tf(fa0.z), f2tf(fa0.w));
        uint4 va1 = make_uint4(f2tf(fa1.x), f2tf(fa1.y), f2tf(fa1.z), f2tf(fa1.w));
        *(uint4*)&sA[0][r][(slice << 3) + 0] = va0;
        *(uint4*)&sA[0][r][(slice << 3) + 4] = va1;
        if (bload) {
            uint4 vb0 = make_uint4(f2tf(fw0.x), f2tf(fw0.y), f2tf(fw0.z), f2tf(fw0.w));
            uint4 vb1 = make_uint4(f2tf(fw1.x), f2tf(fw1.y), f2tf(fw1.z), f2tf(fw1.w));
            *(uint4*)&sB[0][r][(slice << 3) + 0] = vb0;
            *(uint4*)&sB[0][r][(slice << 3) + 4] = vb1;
        }
    }
    __syncthreads();

    const int a_r0 = (wm << 6) + (lane >> 2);      // A base row for this lane
    const int b_r0 = wn * (NFRAG * 8) + (lane >> 2); // B base row
    const int k_l  = lane & 3;

    for (int kt = 0; kt < nkt; kt++) {
        const int cur = kt & 1;
        if (kt + 1 < nkt) {
            const int gk = ((kt + 1) << 4) + (slice << 3);
            fa0 = *(const float4*)(A + arow + gk);
            fa1 = *(const float4*)(A + arow + gk + 4);
            if (wv) {
                fw0 = *(const float4*)(W + wrow + gk);
                fw1 = *(const float4*)(W + wrow + gk + 4);
            } else {
                fw0 = make_float4(0.f, 0.f, 0.f, 0.f);
                fw1 = fw0;
            }
        }
#pragma unroll
        for (int s2 = 0; s2 < 2; s2++) {
            const int ak = (s2 << 3) + k_l;
            uint4 av[4];
#pragma unroll
            for (int i = 0; i < 4; i++) {
                const int m0 = a_r0 + (i << 4);
                av[i].x = sA[cur][m0][ak];
                av[i].y = sA[cur][m0 + 8][ak];
                av[i].z = sA[cur][m0][ak + 4];
                av[i].w = sA[cur][m0 + 8][ak + 4];
            }
            uint2 bv[NFRAG];
#pragma unroll
            for (int j = 0; j < NFRAG; j++) {
                const int n0 = b_r0 + (j << 3);
                bv[j].x = sB[cur][n0][ak];
                bv[j].y = sB[cur][n0][ak + 4];
            }
#pragma unroll
            for (int i = 0; i < 4; i++)
#pragma unroll
                for (int j = 0; j < NFRAG; j++)
                    mma_tf32(acc[i][j], av[i], bv[j]);
        }
        if (kt + 1 < nkt) {
            const int nxt = cur ^ 1;
            uint4 va0 = make_uint4(f2tf(fa0.x), f2tf(fa0.y), f2tf(fa0.z), f2tf(fa0.w));
            uint4 va1 = make_uint4(f2tf(fa1.x), f2tf(fa1.y), f2tf(fa1.z), f2tf(fa1.w));
            *(uint4*)&sA[nxt][r][(slice << 3) + 0] = va0;
            *(uint4*)&sA[nxt][r][(slice << 3) + 4] = va1;
            if (bload) {
                uint4 vb0 = make_uint4(f2tf(fw0.x), f2tf(fw0.y), f2tf(fw0.z), f2tf(fw0.w));
                uint4 vb1 = make_uint4(f2tf(fw1.x), f2tf(fw1.y), f2tf(fw1.z), f2tf(fw1.w));
                *(uint4*)&sB[nxt][r][(slice << 3) + 0] = vb0;
                *(uint4*)&sB[nxt][r][(slice << 3) + 4] = vb1;
            }
            __syncthreads();
        }
    }

    // ---- epilogue ----
    const int row0 = lane >> 2;           // 0..7
    const int col0 = (lane & 3) << 1;     // 0,2,4,6
#pragma unroll
    for (int i = 0; i < 4; i++) {
        const int gmA = bm + (wm << 6) + (i << 4) + row0;
        const int gmB = gmA + 8;
        long rA, rB;
        if (mode == 2) {
            rA = ((gmA >> 10) << 10) + seq_src_n(z, gmA & 1023);
            rB = ((gmB >> 10) << 10) + seq_src_n(z, gmB & 1023);
        } else { rA = gmA; rB = gmB; }
#pragma unroll
        for (int j = 0; j < NFRAG; j++) {
            const int gn = bn + wn * (NFRAG * 8) + (j << 3) + col0;
            if (gn < Nn) {
                float4 v = acc[i][j];
                if (bz) {
                    const float b0 = bz[gn], b1 = bz[gn + 1];
                    v.x += b0; v.y += b1; v.z += b0; v.w += b1;
                }
                if (act) {
                    v.x = apply_act(v.x, act); v.y = apply_act(v.y, act);
                    v.z = apply_act(v.z, act); v.w = apply_act(v.w, act);
                }
                *(float2*)&C[rA * (long)ldc + gn] = make_float2(v.x, v.y);
                *(float2*)&C[rB * (long)ldc + gn] = make_float2(v.z, v.w);
            }
        }
    }
}

// ---------------- kernel 1: transpose + layernorm (x: (B,192,1024) -> xs: (B,1024,192)) ----------------
__global__ __launch_bounds__(256) void ln1_kernel(
    const float* __restrict__ x, const float* __restrict__ g, const float* __restrict__ bb)
{
    __shared__ float tile[DM][33];
    __shared__ float s_mean[32], s_rstd[32];
    const int b = blockIdx.y, n0 = blockIdx.x << 5;
    const int tid = threadIdx.x;

    for (int i = tid; i < DM * 32; i += 256) {
        int d = i >> 5, nn = i & 31;
        tile[d][nn] = x[((long)(b * DM + d) << 10) + n0 + nn];
    }
    __syncthreads();

    const int nn = tid >> 3, l = tid & 7;
    float s = 0.f, s2 = 0.f;
    for (int d = l; d < DM; d += 8) { float v = tile[d][nn]; s += v; s2 = fmaf(v, v, s2); }
    s  += __shfl_down_sync(0xffffffffu, s,  4, 8);
    s2 += __shfl_down_sync(0xffffffffu, s2, 4, 8);
    s  += __shfl_down_sync(0xffffffffu, s,  2, 8);
    s2 += __shfl_down_sync(0xffffffffu, s2, 2, 8);
    s  += __shfl_down_sync(0xffffffffu, s,  1, 8);
    s2 += __shfl_down_sync(0xffffffffu, s2, 1, 8);
    if (l == 0) {
        float m = s * (1.f / DM);
        float var = s2 * (1.f / DM) - m * m;
        s_mean[nn] = m;
        s_rstd[nn] = rsqrtf(var + 1e-5f);
    }
    __syncthreads();

    for (int i = tid; i < DM * 32; i += 256) {
        int nn2 = i / DM, d = i % DM;
        float v = (tile[d][nn2] - s_mean[nn2]) * s_rstd[nn2] * g[d] + bb[d];
        g_xs[((long)(b << 10) + n0 + nn2) * DM + d] = v;
    }
}

// ---------------- causal depthwise conv (width 4) + silu, 16 t per thread ----------------
__global__ __launch_bounds__(256) void conv_silu_kernel(
    const float* __restrict__ cw, const float* __restrict__ cb)
{
    const int gi = blockIdx.x * 256 + threadIdx.x;      // < 16*64*384
    const int c = gi % DI;
    const int rest = gi / DI;                           // 0..1023
    const int tb = rest & 63;
    const int db = rest >> 6;                           // 0..15 (d*4+b)
    const int d = db >> 2;
    const int t0 = tb << 4;

    const float* w = cw + ((long)d * DI + c) * 4;
    const float w0 = w[0], w1 = w[1], w2 = w[2], w3 = w[3];
    const float bias = cb[d * DI + c];
    const float* src = g_xz + ((long)db * NSEQ) * (2 * DI) + c;
    float* dst = g_xsm + ((long)db * NSEQ) * DI + c;

    float r0 = (t0 >= 3) ? src[(long)(t0 - 3) * (2 * DI)] : 0.f;
    float r1 = (t0 >= 2) ? src[(long)(t0 - 2) * (2 * DI)] : 0.f;
    float r2 = (t0 >= 1) ? src[(long)(t0 - 1) * (2 * DI)] : 0.f;
#pragma unroll
    for (int i = 0; i < 16; i++) {
        const int t = t0 + i;
        const float cur = src[(long)t * (2 * DI)];
        float a = bias;
        a = fmaf(w0, r0, a);
        a = fmaf(w1, r1, a);
        a = fmaf(w2, r2, a);
        a = fmaf(w3, cur, a);
        dst[(long)t * DI] = a / (1.f + __expf(-a));
        r0 = r1; r1 = r2; r2 = cur;
    }
}

// ---------------- selective scan with fused dt-projection ----------------
// grid (12, BATCH, NDIR), 128 threads: 32 channels x 4 state-groups of 4 states.
#define SCH 16
__global__ __launch_bounds__(128) void scan_kernel(
    const float* __restrict__ Alog, const float* __restrict__ Dp,
    const float* __restrict__ Wdt, const float* __restrict__ bdt)
{
    const int d = blockIdx.z, b = blockIdx.y;
    const int c0 = blockIdx.x << 5;
    const int tid = threadIdx.x;
    const int cl = tid >> 2;        // 0..31 local channel
    const int sg = tid & 3;         // states sg*4 .. sg*4+3
    const int c = c0 + cl;
    const long baseI = ((long)d * BATCH + b) * NSEQ;

    const float* xb   = g_xsm + baseI * DI       + c0;
    const float* zb   = g_xz  + baseI * (2 * DI) + DI + c0;
    const float* dblp = g_dbl + baseI * DBL_W;
    float* yb         = g_y   + baseI * DI       + c0;

    __shared__ float s_wdt[32 * 13];
    __shared__ float s_bdt[32];
    __shared__ float s_raw[SCH * 12];
    __shared__ float s_bc [SCH * 32];
    __shared__ float s_dt [SCH * 32];
    __shared__ float s_x  [SCH * 32];
    __shared__ float s_z  [SCH * 32];

    for (int i = tid; i < 32 * DR; i += 128)
        s_wdt[(i / DR) * 13 + (i % DR)] = Wdt[((long)(d * DI + c0) + i / DR) * DR + (i % DR)];
    if (tid < 32) s_bdt[tid] = bdt[d * DI + c0 + tid];

    float Aa[4];
#pragma unroll
    for (int s = 0; s < 4; s++)
        Aa[s] = -expf(Alog[((long)(d * DI + c)) * DS + (sg << 2) + s]);
    const float Dv = Dp[d * DI + c];

    float h[4];
#pragma unroll
    for (int s = 0; s < 4; s++) h[s] = 0.f;

    __syncthreads();

    for (int t0 = 0; t0 < NSEQ; t0 += SCH) {
        __syncthreads();
        for (int i = tid; i < SCH * DR; i += 128)
            s_raw[i] = dblp[(long)(t0 + i / DR) * DBL_W + (i % DR)];
#pragma unroll
        for (int k = 0; k < 4; k++) {
            const int idx = tid + (k << 7);
            const int row = idx >> 5, col = idx & 31;
            s_bc[idx] = dblp[(long)(t0 + row) * DBL_W + DR + col];
            s_x [idx] = xb[(long)(t0 + row) * DI + col];
            s_z [idx] = zb[(long)(t0 + row) * (2 * DI) + col];
        }
        __syncthreads();
#pragma unroll
        for (int k = 0; k < 4; k++) {
            const int idx = tid + (k << 7);
            const int row = idx >> 5, col = idx & 31;
            float v = s_bdt[col];
#pragma unroll
            for (int j = 0; j < DR; j++)
                v = fmaf(s_raw[row * DR + j], s_wdt[col * 13 + j], v);
            s_dt[idx] = (v > 20.f) ? v : log1pf(__expf(v));
        }
        __syncthreads();

        for (int tt = 0; tt < SCH; tt++) {
            const float dt_v = s_dt[(tt << 5) + cl];
            const float x_v  = s_x [(tt << 5) + cl];
            const float* bc = s_bc + (tt << 5);
            const float dtx = dt_v * x_v;
            float accv = 0.f;
#pragma unroll
            for (int s = 0; s < 4; s++) {
                const float dA = __expf(dt_v * Aa[s]);
                h[s] = fmaf(dA, h[s], dtx * bc[(sg << 2) + s]);
                accv = fmaf(h[s], bc[16 + (sg << 2) + s], accv);
            }
            accv += __shfl_down_sync(0xffffffffu, accv, 2, 4);
            accv += __shfl_down_sync(0xffffffffu, accv, 1, 4);
            if (sg == 0) {
                const float z_v = s_z[(tt << 5) + cl];
                float yv = fmaf(x_v, Dv, accv);
                yv *= z_v / (1.f + __expf(-z_v));
                yb[(long)(t0 + tt) * DI + cl] = yv;
            }
        }
    }
}

// ---------------- combine o_proj into ffn2:  Wc = o_w @ f_w2, bc = o_w @ f_b2 + o_b ----------------
__global__ __launch_bounds__(256) void combine_w_kernel(
    const float* __restrict__ o_w, const float* __restrict__ o_b,
    const float* __restrict__ f_w2, const float* __restrict__ f_b2)
{
    const int i = blockIdx.x;           // output row 0..191
    __shared__ float s_ow[DM];
    __shared__ float red[256];
    for (int j = threadIdx.x; j < DM; j += 256) s_ow[j] = o_w[i * DM + j];
    __syncthreads();

    for (int k = threadIdx.x; k < 2 * DM; k += 256) {
        float acc = 0.f;
        for (int j = 0; j < DM; j++)
            acc = fmaf(s_ow[j], f_w2[j * (2 * DM) + k], acc);
        g_cw[i * (2 * DM) + k] = acc;
    }
    float pb = 0.f;
    for (int j = threadIdx.x; j < DM; j += 256) pb = fmaf(s_ow[j], f_b2[j], pb);
    red[threadIdx.x] = pb;
    __syncthreads();
    for (int st = 128; st > 0; st >>= 1) {
        if (threadIdx.x < st) red[threadIdx.x] += red[threadIdx.x + st];
        __syncthreads();
    }
    if (threadIdx.x == 0) g_cb[i] = red[0] + o_b[i];
}

// ---------------- final layernorm + residual + transpose-out ----------------
__global__ __launch_bounds__(256) void ln2_kernel(
    const float* __restrict__ g, const float* __restrict__ bb, float* __restrict__ out)
{
    __shared__ float t1[16][193];
    __shared__ float t2[16][193];
    __shared__ float s_mean[16], s_rstd[16];
    const int b = blockIdx.y, n0 = blockIdx.x << 4;
    const int tid = threadIdx.x;

    for (int i = tid; i < 16 * DM; i += 256) {
        int nn = i / DM, dd = i % DM;
        long adr = ((long)(b << 10) + n0 + nn) * DM + dd;
        t1[nn][dd] = g_h3[adr];
        t2[nn][dd] = g_xs[adr];
    }
    __syncthreads();

    const int nn = tid >> 4, l = tid & 15;
    float s = 0.f, s2 = 0.f;
    for (int dd = l; dd < DM; dd += 16) { float v = t1[nn][dd]; s += v; s2 = fmaf(v, v, s2); }
    s  += __shfl_down_sync(0xffffffffu, s,  8, 16);
    s2 += __shfl_down_sync(0xffffffffu, s2, 8, 16);
    s  += __shfl_down_sync(0xffffffffu, s,  4, 16);
    s2 += __shfl_down_sync(0xffffffffu, s2, 4, 16);
    s  += __shfl_down_sync(0xffffffffu, s,  2, 16);
    s2 += __shfl_down_sync(0xffffffffu, s2, 2, 16);
    s  += __shfl_down_sync(0xffffffffu, s,  1, 16);
    s2 += __shfl_down_sync(0xffffffffu, s2, 1, 16);
    if (l == 0) {
        float m = s * (1.f / DM);
        float var = s2 * (1.f / DM) - m * m;
        s_mean[nn] = m;
        s_rstd[nn] = rsqrtf(var + 1e-5f);
    }
    __syncthreads();

    for (int i = tid; i < DM * 16; i += 256) {
        int dd = i >> 4, nn2 = i & 15;
        float v = (t1[nn2][dd] - s_mean[nn2]) * s_rstd[nn2] * g[dd] + bb[dd] + t2[nn2][dd];
        out[((long)(b * DM + dd) << 10) + n0 + nn2] = v;
    }
}

// ---------------- launcher ----------------
extern "C" void kernel_launch(void* const* d_in, const int* in_sizes, int n_in,
                              void* d_out, int out_size)
{
    const float* x        = (const float*)d_in[0];
    const float* norm_g   = (const float*)d_in[1];
    const float* norm_b   = (const float*)d_in[2];
    const float* in_w     = (const float*)d_in[3];
    const float* in_b     = (const float*)d_in[4];
    const float* m_in_w   = (const float*)d_in[5];
    const float* m_conv_w = (const float*)d_in[6];
    const float* m_conv_b = (const float*)d_in[7];
    const float* m_xp_w   = (const float*)d_in[8];
    const float* m_dt_w   = (const float*)d_in[9];
    const float* m_dt_b   = (const float*)d_in[10];
    const float* m_Alog   = (const float*)d_in[11];
    const float* m_D      = (const float*)d_in[12];
    const float* m_out_w  = (const float*)d_in[13];
    const float* f_w1     = (const float*)d_in[14];
    const float* f_b1     = (const float*)d_in[15];
    const float* f_w2     = (const float*)d_in[16];
    const float* f_b2     = (const float*)d_in[17];
    const float* o_w      = (const float*)d_in[18];
    const float* o_b      = (const float*)d_in[19];
    const float* on_g     = (const float*)d_in[20];
    const float* on_b     = (const float*)d_in[21];
    float* out = (float*)d_out;

    float *p_xs, *p_xp, *p_xz, *p_xsm, *p_dbl, *p_y, *p_fused, *p_hdn, *p_h3, *p_cw, *p_cb;
    cudaGetSymbolAddress((void**)&p_xs, g_xs);
    cudaGetSymbolAddress((void**)&p_xp, g_xp);
    cudaGetSymbolAddress((void**)&p_xz, g_xz);
    cudaGetSymbolAddress((void**)&p_xsm, g_xsm);
    cudaGetSymbolAddress((void**)&p_dbl, g_dbl);
    cudaGetSymbolAddress((void**)&p_y, g_y);
    cudaGetSymbolAddress((void**)&p_fused, g_fused);
    cudaGetSymbolAddress((void**)&p_hdn, g_hdn);
    cudaGetSymbolAddress((void**)&p_h3, g_h3);
    cudaGetSymbolAddress((void**)&p_cw, g_cw);
    cudaGetSymbolAddress((void**)&p_cb, g_cb);

    // 1) dummy (aims the ncu capture slot at the xz GEMM)
    dummy_kernel<<<1, 32>>>();

    // 2) layernorm + transpose
    ln1_kernel<<<dim3(32, 4), 256>>>(x, norm_g, norm_b);

    // 3) xp = xs @ in_w^T + in_b   (4096 x 192 x 192)
    gemm_tf32_kernel<2><<<dim3(3, 32, 1), 256>>>(p_xs, in_w, in_b, p_xp,
        LROWS, DM, DM, DM, DM, 0, 0, 0, 0, 0, 0);

    // 4) xz[d] = gather_d(xp) @ m_in_w[d]^T   (4 x 4096 x 768 x 192), A-gather fused
    gemm_tf32_kernel<4><<<dim3(6, 32, 4), 256>>>(p_xp, m_in_w, nullptr, p_xz,
        LROWS, 2 * DI, DM, DM, 2 * DI,
        0, (long)2 * DI * DM, 0, (long)LROWS * 2 * DI, 0, 1);

    // 5) causal depthwise conv + silu (16 t per thread)
    conv_silu_kernel<<<1536, 256>>>(m_conv_w, m_conv_b);

    // 6) dbl[d] = xsm[d] @ m_xp_w[d]^T   (Nn=44)
    gemm_tf32_kernel<2><<<dim3(1, 32, 4), 256>>>(p_xsm, m_xp_w, nullptr, p_dbl,
        LROWS, DBL_W, DI, DI, DBL_W,
        (long)LROWS * DI, (long)DBL_W * DI, 0, (long)LROWS * DBL_W, 0, 0);

    // 7) selective scan (fused dt-proj + softplus + D skip + silu(z) gate)
    scan_kernel<<<dim3(12, BATCH, NDIR), 128>>>(m_Alog, m_D, m_dt_w, m_dt_b);

    // 8) fused[:, d*DM:(d+1)*DM] = scatter_d(y[d] @ m_out_w[d]^T)
    gemm_tf32_kernel<2><<<dim3(3, 32, 4), 256>>>(p_y, m_out_w, nullptr, p_fused,
        LROWS, DM, DI, DI, 4 * DM,
        (long)LROWS * DI, (long)DM * DI, 0, (long)DM, 0, 2);

    // 9) hdn = gelu(fused @ f_w1^T + f_b1)   (4096 x 384 x 768)
    gemm_tf32_kernel<4><<<dim3(3, 32, 1), 256>>>(p_fused, f_w1, f_b1, p_hdn,
        LROWS, 2 * DM, 4 * DM, 4 * DM, 2 * DM, 0, 0, 0, 0, 2, 0);

    // 10) combined weight: Wc = o_w @ f_w2, bc = o_w @ f_b2 + o_b
    combine_w_kernel<<<DM, 256>>>(o_w, o_b, f_w2, f_b2);

    // 11) h3 = hdn @ Wc^T + bc   (4096 x 192 x 384)
    gemm_tf32_kernel<2><<<dim3(3, 32, 1), 256>>>(p_hdn, p_cw, p_cb, p_h3,
        LROWS, DM, 2 * DM, 2 * DM, DM, 0, 0, 0, 0, 0, 0);

    // 12) final layernorm + residual + transpose out
    ln2_kernel<<<dim3(64, 4), 256>>>(on_g, on_b, out);
}

// round 6
// speedup vs baseline: 2.0758x; 1.1021x over previous
#include <cuda_runtime.h>
#include <cuda_bf16.h>
#include <math.h>
#include <stdint.h>

// ---------------- problem constants ----------------
#define BATCH 4
#define DM    192          // d_model
#define DI    384          // d_inner
#define DS    16           // d_state
#define DR    12           // dt_rank
#define NSEQ  1024         // H*W
#define LROWS 4096         // BATCH*NSEQ
#define NDIR  4
#define DBL_W 44           // DR + 2*DS

// ---------------- scratch (static device memory: allocation-free) ----------------
__device__ float g_xs  [LROWS*DM];
__device__ float g_xp  [LROWS*DM];
__device__ float g_xz  [(long)NDIR*LROWS*2*DI];
__device__ float g_xsm [NDIR*LROWS*DI];
__device__ float g_dbl [NDIR*LROWS*DBL_W];
__device__ float g_y   [NDIR*LROWS*DI];
__device__ float g_fused[LROWS*4*DM];
__device__ float g_hdn [LROWS*2*DM];
__device__ float g_h3  [LROWS*DM];
__device__ float g_cw  [DM*2*DM];
__device__ float g_cb  [DM];

// ---------------- helpers ----------------
__device__ __forceinline__ float apply_act(float v, int act) {
    if (act == 1) {
        v = (v > 20.f) ? v : log1pf(__expf(v));
    } else if (act == 2) {
        v = 0.5f * v * (1.f + erff(v * 0.70710678118654752f));
    }
    return v;
}

__device__ __forceinline__ int seq_src_n(int d, int t) {
    if (d == 0) return t;
    if (d == 1) return NSEQ - 1 - t;
    if (d == 2) return ((t & 31) << 5) + (t >> 5);
    int u = NSEQ - 1 - t;
    return ((u & 31) << 5) + (u >> 5);
}

__device__ __forceinline__ unsigned f2tf(float f) {
    unsigned u;
    asm("cvt.rna.tf32.f32 %0, %1;" : "=r"(u) : "f"(f));
    return u;
}

__device__ __forceinline__ void mma_tf32(float4& c, const uint4& a, const uint2& b) {
    asm volatile(
        "mma.sync.aligned.m16n8k8.row.col.f32.tf32.tf32.f32 "
        "{%0,%1,%2,%3}, {%4,%5,%6,%7}, {%8,%9}, {%0,%1,%2,%3};\n"
        : "+f"(c.x), "+f"(c.y), "+f"(c.z), "+f"(c.w)
        : "r"(a.x), "r"(a.y), "r"(a.z), "r"(a.w), "r"(b.x), "r"(b.y));
}

__device__ __forceinline__ void mma_bf16(float4& c,
    uint32_t a0, uint32_t a1, uint32_t a2, uint32_t a3, uint32_t b0, uint32_t b1) {
    asm volatile(
        "mma.sync.aligned.m16n8k16.row.col.f32.bf16.bf16.f32 "
        "{%0,%1,%2,%3}, {%4,%5,%6,%7}, {%8,%9}, {%0,%1,%2,%3};\n"
        : "+f"(c.x), "+f"(c.y), "+f"(c.z), "+f"(c.w)
        : "r"(a0), "r"(a1), "r"(a2), "r"(a3), "r"(b0), "r"(b1));
}

__device__ __forceinline__ void ldsm_x4(uint32_t addr,
    uint32_t& r0, uint32_t& r1, uint32_t& r2, uint32_t& r3) {
    asm volatile("ldmatrix.sync.aligned.m8n8.x4.shared.b16 {%0,%1,%2,%3}, [%4];"
        : "=r"(r0), "=r"(r1), "=r"(r2), "=r"(r3) : "r"(addr));
}

__device__ __forceinline__ uint32_t pack_bf2(float lo, float hi) {
    __nv_bfloat162 p = __floats2bfloat162_rn(lo, hi);
    return *(uint32_t*)&p;
}

// ---------------- dummy (aims the ncu capture slot at the xz GEMM) ----------------
__global__ void dummy_kernel() {}

// ---------------- bf16 tensor-core GEMM:  C = act(A @ W^T + bias) ----------------
// Block tile: 128 x (NFRAG*32), BK=16, 256 threads (8 warps as 2x4, warp tile 64 x NFRAG*8).
// Smem: [row][24] bf16 (16 k + 8 pad, 48B pitch) -> STS.128 staging, conflict-free ldmatrix.
// Requirements: M % 128 == 0, K % 16 == 0 and K >= 32, Nn even.
// mode: 0 = plain, 1 = gather A rows via seq_src_n(z,.), 2 = scatter C rows via seq_src_n(z,.)
template<int NFRAG>
__global__ __launch_bounds__(256) void gemm_bf16_kernel(
    const float* __restrict__ A, const float* __restrict__ W,
    const float* __restrict__ bias, float* __restrict__ C,
    int M, int Nn, int K, int lda, int ldc,
    long sA_, long sW_, long sB_, long sC_, int act, int mode)
{
    constexpr int TN = NFRAG * 32;
    const int z = blockIdx.z;
    A += z * sA_; W += z * sW_; C += z * sC_;
    const float* bz = bias ? (bias + z * sB_) : (const float*)0;

    __shared__ __align__(16) __nv_bfloat16 sA[2][128][24];
    __shared__ __align__(16) __nv_bfloat16 sB[2][TN][24];

    const int bm = blockIdx.y << 7, bn = blockIdx.x * TN;
    const int tid = threadIdx.x;

    // ---- staging geometry: 2 threads per row, 8 floats each ----
    const int r     = tid >> 1;        // 0..127 tile row
    const int slice = tid & 1;         // k8 slice of the 16-wide stage
    long arow;
    if (mode == 1) {
        int gm = bm + r;
        arow = (long)(((gm >> 10) << 10) + seq_src_n(z, gm & 1023)) * lda;
    } else {
        arow = (long)(bm + r) * lda;
    }
    const bool bload = (r < TN);
    const int  gw_n = bn + r;
    const bool wv = bload && (gw_n < Nn);
    const long wrow = (long)gw_n * K;

    float4 acc[4][NFRAG];
#pragma unroll
    for (int i = 0; i < 4; i++)
#pragma unroll
        for (int j = 0; j < NFRAG; j++) acc[i][j] = make_float4(0.f, 0.f, 0.f, 0.f);

    const int lane = tid & 31, wid = tid >> 5;
    const int wm = wid >> 2, wn = wid & 3;
    const int nkt = K >> 4;

    // ldmatrix lane addresses (bytes)
    const int a_row = (wm << 6) + (lane & 7) + (((lane >> 3) & 1) << 3);
    const int a_kc  = (lane >> 4) << 3;
    const uint32_t aAddr0 = (uint32_t)__cvta_generic_to_shared(&sA[0][a_row][a_kc]);
    const int b_row = wn * (NFRAG * 8) + (lane & 7) + ((lane >> 4) << 3);
    const int b_kc  = ((lane >> 3) & 1) << 3;
    const uint32_t bAddr0 = (uint32_t)__cvta_generic_to_shared(&sB[0][b_row][b_kc]);
    constexpr uint32_t A_STAGE = 128 * 24 * 2;
    constexpr uint32_t B_STAGE = TN * 24 * 2;

    float4 fa0, fa1, fw0, fw1;
    {
        const int gk = slice << 3;
        fa0 = *(const float4*)(A + arow + gk);
        fa1 = *(const float4*)(A + arow + gk + 4);
        if (wv) {
            fw0 = *(const float4*)(W + wrow + gk);
            fw1 = *(const float4*)(W + wrow + gk + 4);
        } else {
            fw0 = make_float4(0.f, 0.f, 0.f, 0.f);
            fw1 = fw0;
        }
    }
    {
        uint4 va = make_uint4(pack_bf2(fa0.x, fa0.y), pack_bf2(fa0.z, fa0.w),
                              pack_bf2(fa1.x, fa1.y), pack_bf2(fa1.z, fa1.w));
        *(uint4*)&sA[0][r][slice << 3] = va;
        if (bload) {
            uint4 vb = make_uint4(pack_bf2(fw0.x, fw0.y), pack_bf2(fw0.z, fw0.w),
                                  pack_bf2(fw1.x, fw1.y), pack_bf2(fw1.z, fw1.w));
            *(uint4*)&sB[0][r][slice << 3] = vb;
        }
    }
    __syncthreads();

    for (int kt = 0; kt < nkt; kt++) {
        const int cur = kt & 1;
        if (kt + 1 < nkt) {
            const int gk = ((kt + 1) << 4) + (slice << 3);
            fa0 = *(const float4*)(A + arow + gk);
            fa1 = *(const float4*)(A + arow + gk + 4);
            if (wv) {
                fw0 = *(const float4*)(W + wrow + gk);
                fw1 = *(const float4*)(W + wrow + gk + 4);
            } else {
                fw0 = make_float4(0.f, 0.f, 0.f, 0.f);
                fw1 = fw0;
            }
        }
        // ---- compute from current stage ----
        {
            const uint32_t aA = aAddr0 + cur * A_STAGE;
            const uint32_t bA = bAddr0 + cur * B_STAGE;
            uint32_t ra[4][4];
#pragma unroll
            for (int i = 0; i < 4; i++)
                ldsm_x4(aA + i * (16 * 48), ra[i][0], ra[i][1], ra[i][2], ra[i][3]);
            uint32_t rb[NFRAG][2];
#pragma unroll
            for (int jp = 0; jp < NFRAG / 2; jp++) {
                uint32_t b0, b1, b2, b3;
                ldsm_x4(bA + jp * (16 * 48), b0, b1, b2, b3);
                rb[2 * jp][0] = b0; rb[2 * jp][1] = b1;
                rb[2 * jp + 1][0] = b2; rb[2 * jp + 1][1] = b3;
            }
#pragma unroll
            for (int i = 0; i < 4; i++)
#pragma unroll
                for (int j = 0; j < NFRAG; j++)
                    mma_bf16(acc[i][j], ra[i][0], ra[i][1], ra[i][2], ra[i][3],
                             rb[j][0], rb[j][1]);
        }
        if (kt + 1 < nkt) {
            const int nxt = cur ^ 1;
            uint4 va = make_uint4(pack_bf2(fa0.x, fa0.y), pack_bf2(fa0.z, fa0.w),
                                  pack_bf2(fa1.x, fa1.y), pack_bf2(fa1.z, fa1.w));
            *(uint4*)&sA[nxt][r][slice << 3] = va;
            if (bload) {
                uint4 vb = make_uint4(pack_bf2(fw0.x, fw0.y), pack_bf2(fw0.z, fw0.w),
                                      pack_bf2(fw1.x, fw1.y), pack_bf2(fw1.z, fw1.w));
                *(uint4*)&sB[nxt][r][slice << 3] = vb;
            }
            __syncthreads();
        }
    }

    // ---- epilogue ----
    const int row0 = lane >> 2;
    const int col0 = (lane & 3) << 1;
#pragma unroll
    for (int i = 0; i < 4; i++) {
        const int gmA = bm + (wm << 6) + (i << 4) + row0;
        const int gmB = gmA + 8;
        long rA, rB;
        if (mode == 2) {
            rA = ((gmA >> 10) << 10) + seq_src_n(z, gmA & 1023);
            rB = ((gmB >> 10) << 10) + seq_src_n(z, gmB & 1023);
        } else { rA = gmA; rB = gmB; }
#pragma unroll
        for (int j = 0; j < NFRAG; j++) {
            const int gn = bn + wn * (NFRAG * 8) + (j << 3) + col0;
            if (gn < Nn) {
                float4 v = acc[i][j];
                if (bz) {
                    const float b0 = bz[gn], b1 = bz[gn + 1];
                    v.x += b0; v.y += b1; v.z += b0; v.w += b1;
                }
                if (act) {
                    v.x = apply_act(v.x, act); v.y = apply_act(v.y, act);
                    v.z = apply_act(v.z, act); v.w = apply_act(v.w, act);
                }
                *(float2*)&C[rA * (long)ldc + gn] = make_float2(v.x, v.y);
                *(float2*)&C[rB * (long)ldc + gn] = make_float2(v.z, v.w);
            }
        }
    }
}

// ---------------- tf32 GEMM (kept for the dbl projection feeding the scan) ----------------
template<int NFRAG>
__global__ __launch_bounds__(256) void gemm_tf32_kernel(
    const float* __restrict__ A, const float* __restrict__ W,
    const float* __restrict__ bias, float* __restrict__ C,
    int M, int Nn, int K, int lda, int ldc,
    long sA_, long sW_, long sB_, long sC_, int act, int mode)
{
    constexpr int TN = NFRAG * 32;
    const int z = blockIdx.z;
    A += z * sA_; W += z * sW_; C += z * sC_;
    const float* bz = bias ? (bias + z * sB_) : (const float*)0;

    __shared__ unsigned sA[2][128][20];
    __shared__ unsigned sB[2][TN][20];

    const int bm = blockIdx.y << 7, bn = blockIdx.x * TN;
    const int tid = threadIdx.x;

    const int r     = tid >> 1;
    const int slice = tid & 1;
    long arow = (long)(bm + r) * lda;
    const bool bload = (r < TN);
    const int  gw_n = bn + r;
    const bool wv = bload && (gw_n < Nn);
    const long wrow = (long)gw_n * K;

    float4 acc[4][NFRAG];
#pragma unroll
    for (int i = 0; i < 4; i++)
#pragma unroll
        for (int j = 0; j < NFRAG; j++) acc[i][j] = make_float4(0.f, 0.f, 0.f, 0.f);

    const int lane = tid & 31, wid = tid >> 5;
    const int wm = wid >> 2, wn = wid & 3;
    const int nkt = K >> 4;

    float4 fa0, fa1, fw0, fw1;
    {
        const int gk = slice << 3;
        fa0 = *(const float4*)(A + arow + gk);
        fa1 = *(const float4*)(A + arow + gk + 4);
        if (wv) {
            fw0 = *(const float4*)(W + wrow + gk);
            fw1 = *(const float4*)(W + wrow + gk + 4);
        } else {
            fw0 = make_float4(0.f, 0.f, 0.f, 0.f);
            fw1 = fw0;
        }
    }
    {
        uint4 va0 = make_uint4(f2tf(fa0.x), f2tf(fa0.y), f2tf(fa0.z), f2tf(fa0.w));
        uint4 va1 = make_uint4(f2tf(fa1.x), f2tf(fa1.y), f2tf(fa1.z), f2tf(fa1.w));
        *(uint4*)&sA[0][r][(slice << 3) + 0] = va0;
        *(uint4*)&sA[0][r][(slice << 3) + 4] = va1;
        if (bload) {
            uint4 vb0 = make_uint4(f2tf(fw0.x), f2tf(fw0.y), f2tf(fw0.z), f2tf(fw0.w));
            uint4 vb1 = make_uint4(f2tf(fw1.x), f2tf(fw1.y), f2tf(fw1.z), f2tf(fw1.w));
            *(uint4*)&sB[0][r][(slice << 3) + 0] = vb0;
            *(uint4*)&sB[0][r][(slice << 3) + 4] = vb1;
        }
    }
    __syncthreads();

    const int a_r0 = (wm << 6) + (lane >> 2);
    const int b_r0 = wn * (NFRAG * 8) + (lane >> 2);
    const int k_l  = lane & 3;

    for (int kt = 0; kt < nkt; kt++) {
        const int cur = kt & 1;
        if (kt + 1 < nkt) {
            const int gk = ((kt + 1) << 4) + (slice << 3);
            fa0 = *(const float4*)(A + arow + gk);
            fa1 = *(const float4*)(A + arow + gk + 4);
            if (wv) {
                fw0 = *(const float4*)(W + wrow + gk);
                fw1 = *(const float4*)(W + wrow + gk + 4);
            } else {
                fw0 = make_float4(0.f, 0.f, 0.f, 0.f);
                fw1 = fw0;
            }
        }
#pragma unroll
        for (int s2 = 0; s2 < 2; s2++) {
            const int ak = (s2 << 3) + k_l;
            uint4 av[4];
#pragma unroll
            for (int i = 0; i < 4; i++) {
                const int m0 = a_r0 + (i << 4);
                av[i].x = sA[cur][m0][ak];
                av[i].y = sA[cur][m0 + 8][ak];
                av[i].z = sA[cur][m0][ak + 4];
                av[i].w = sA[cur][m0 + 8][ak + 4];
            }
            uint2 bv[NFRAG];
#pragma unroll
            for (int j = 0; j < NFRAG; j++) {
                const int n0 = b_r0 + (j << 3);
                bv[j].x = sB[cur][n0][ak];
                bv[j].y = sB[cur][n0][ak + 4];
            }
#pragma unroll
            for (int i = 0; i < 4; i++)
#pragma unroll
                for (int j = 0; j < NFRAG; j++)
                    mma_tf32(acc[i][j], av[i], bv[j]);
        }
        if (kt + 1 < nkt) {
            const int nxt = cur ^ 1;
            uint4 va0 = make_uint4(f2tf(fa0.x), f2tf(fa0.y), f2tf(fa0.z), f2tf(fa0.w));
            uint4 va1 = make_uint4(f2tf(fa1.x), f2tf(fa1.y), f2tf(fa1.z), f2tf(fa1.w));
            *(uint4*)&sA[nxt][r][(slice << 3) + 0] = va0;
            *(uint4*)&sA[nxt][r][(slice << 3) + 4] = va1;
            if (bload) {
                uint4 vb0 = make_uint4(f2tf(fw0.x), f2tf(fw0.y), f2tf(fw0.z), f2tf(fw0.w));
                uint4 vb1 = make_uint4(f2tf(fw1.x), f2tf(fw1.y), f2tf(fw1.z), f2tf(fw1.w));
                *(uint4*)&sB[nxt][r][(slice << 3) + 0] = vb0;
                *(uint4*)&sB[nxt][r][(slice << 3) + 4] = vb1;
            }
            __syncthreads();
        }
    }

    const int row0 = lane >> 2;
    const int col0 = (lane & 3) << 1;
#pragma unroll
    for (int i = 0; i < 4; i++) {
        const int gmA = bm + (wm << 6) + (i << 4) + row0;
        const int gmB = gmA + 8;
#pragma unroll
        for (int j = 0; j < NFRAG; j++) {
            const int gn = bn + wn * (NFRAG * 8) + (j << 3) + col0;
            if (gn < Nn) {
                float4 v = acc[i][j];
                if (bz) {
                    const float b0 = bz[gn], b1 = bz[gn + 1];
                    v.x += b0; v.y += b1; v.z += b0; v.w += b1;
                }
                if (act) {
                    v.x = apply_act(v.x, act); v.y = apply_act(v.y, act);
                    v.z = apply_act(v.z, act); v.w = apply_act(v.w, act);
                }
                *(float2*)&C[(long)gmA * ldc + gn] = make_float2(v.x, v.y);
                *(float2*)&C[(long)gmB * ldc + gn] = make_float2(v.z, v.w);
            }
        }
    }
}

// ---------------- kernel 1: transpose + layernorm ----------------
__global__ __launch_bounds__(256) void ln1_kernel(
    const float* __restrict__ x, const float* __restrict__ g, const float* __restrict__ bb)
{
    __shared__ float tile[DM][33];
    __shared__ float s_mean[32], s_rstd[32];
    const int b = blockIdx.y, n0 = blockIdx.x << 5;
    const int tid = threadIdx.x;

    for (int i = tid; i < DM * 32; i += 256) {
        int d = i >> 5, nn = i & 31;
        tile[d][nn] = x[((long)(b * DM + d) << 10) + n0 + nn];
    }
    __syncthreads();

    const int nn = tid >> 3, l = tid & 7;
    float s = 0.f, s2 = 0.f;
    for (int d = l; d < DM; d += 8) { float v = tile[d][nn]; s += v; s2 = fmaf(v, v, s2); }
    s  += __shfl_down_sync(0xffffffffu, s,  4, 8);
    s2 += __shfl_down_sync(0xffffffffu, s2, 4, 8);
    s  += __shfl_down_sync(0xffffffffu, s,  2, 8);
    s2 += __shfl_down_sync(0xffffffffu, s2, 2, 8);
    s  += __shfl_down_sync(0xffffffffu, s,  1, 8);
    s2 += __shfl_down_sync(0xffffffffu, s2, 1, 8);
    if (l == 0) {
        float m = s * (1.f / DM);
        float var = s2 * (1.f / DM) - m * m;
        s_mean[nn] = m;
        s_rstd[nn] = rsqrtf(var + 1e-5f);
    }
    __syncthreads();

    for (int i = tid; i < DM * 32; i += 256) {
        int nn2 = i / DM, d = i % DM;
        float v = (tile[d][nn2] - s_mean[nn2]) * s_rstd[nn2] * g[d] + bb[d];
        g_xs[((long)(b << 10) + n0 + nn2) * DM + d] = v;
    }
}

// ---------------- causal depthwise conv (width 4) + silu, 16 t per thread ----------------
__global__ __launch_bounds__(256) void conv_silu_kernel(
    const float* __restrict__ cw, const float* __restrict__ cb)
{
    const int gi = blockIdx.x * 256 + threadIdx.x;
    const int c = gi % DI;
    const int rest = gi / DI;
    const int tb = rest & 63;
    const int db = rest >> 6;
    const int d = db >> 2;
    const int t0 = tb << 4;

    const float* w = cw + ((long)d * DI + c) * 4;
    const float w0 = w[0], w1 = w[1], w2 = w[2], w3 = w[3];
    const float bias = cb[d * DI + c];
    const float* src = g_xz + ((long)db * NSEQ) * (2 * DI) + c;
    float* dst = g_xsm + ((long)db * NSEQ) * DI + c;

    float r0 = (t0 >= 3) ? src[(long)(t0 - 3) * (2 * DI)] : 0.f;
    float r1 = (t0 >= 2) ? src[(long)(t0 - 2) * (2 * DI)] : 0.f;
    float r2 = (t0 >= 1) ? src[(long)(t0 - 1) * (2 * DI)] : 0.f;
#pragma unroll
    for (int i = 0; i < 16; i++) {
        const int t = t0 + i;
        const float cur = src[(long)t * (2 * DI)];
        float a = bias;
        a = fmaf(w0, r0, a);
        a = fmaf(w1, r1, a);
        a = fmaf(w2, r2, a);
        a = fmaf(w3, cur, a);
        dst[(long)t * DI] = a / (1.f + __expf(-a));
        r0 = r1; r1 = r2; r2 = cur;
    }
}

// ---------------- selective scan with fused dt-projection ----------------
#define SCH 16
__global__ __launch_bounds__(128) void scan_kernel(
    const float* __restrict__ Alog, const float* __restrict__ Dp,
    const float* __restrict__ Wdt, const float* __restrict__ bdt)
{
    const int d = blockIdx.z, b = blockIdx.y;
    const int c0 = blockIdx.x << 5;
    const int tid = threadIdx.x;
    const int cl = tid >> 2;
    const int sg = tid & 3;
    const int c = c0 + cl;
    const long baseI = ((long)d * BATCH + b) * NSEQ;

    const float* xb   = g_xsm + baseI * DI       + c0;
    const float* zb   = g_xz  + baseI * (2 * DI) + DI + c0;
    const float* dblp = g_dbl + baseI * DBL_W;
    float* yb         = g_y   + baseI * DI       + c0;

    __shared__ float s_wdt[32 * 13];
    __shared__ float s_bdt[32];
    __shared__ float s_raw[SCH * 12];
    __shared__ float s_bc [SCH * 32];
    __shared__ float s_dt [SCH * 32];
    __shared__ float s_x  [SCH * 32];
    __shared__ float s_z  [SCH * 32];

    for (int i = tid; i < 32 * DR; i += 128)
        s_wdt[(i / DR) * 13 + (i % DR)] = Wdt[((long)(d * DI + c0) + i / DR) * DR + (i % DR)];
    if (tid < 32) s_bdt[tid] = bdt[d * DI + c0 + tid];

    float Aa[4];
#pragma unroll
    for (int s = 0; s < 4; s++)
        Aa[s] = -expf(Alog[((long)(d * DI + c)) * DS + (sg << 2) + s]);
    const float Dv = Dp[d * DI + c];

    float h[4];
#pragma unroll
    for (int s = 0; s < 4; s++) h[s] = 0.f;

    __syncthreads();

    for (int t0 = 0; t0 < NSEQ; t0 += SCH) {
        __syncthreads();
        for (int i = tid; i < SCH * DR; i += 128)
            s_raw[i] = dblp[(long)(t0 + i / DR) * DBL_W + (i % DR)];
#pragma unroll
        for (int k = 0; k < 4; k++) {
            const int idx = tid + (k << 7);
            const int row = idx >> 5, col = idx & 31;
            s_bc[idx] = dblp[(long)(t0 + row) * DBL_W + DR + col];
            s_x [idx] = xb[(long)(t0 + row) * DI + col];
            s_z [idx] = zb[(long)(t0 + row) * (2 * DI) + col];
        }
        __syncthreads();
#pragma unroll
        for (int k = 0; k < 4; k++) {
            const int idx = tid + (k << 7);
            const int row = idx >> 5, col = idx & 31;
            float v = s_bdt[col];
#pragma unroll
            for (int j = 0; j < DR; j++)
                v = fmaf(s_raw[row * DR + j], s_wdt[col * 13 + j], v);
            s_dt[idx] = (v > 20.f) ? v : log1pf(__expf(v));
        }
        __syncthreads();

        for (int tt = 0; tt < SCH; tt++) {
            const float dt_v = s_dt[(tt << 5) + cl];
            const float x_v  = s_x [(tt << 5) + cl];
            const float* bc = s_bc + (tt << 5);
            const float dtx = dt_v * x_v;
            float accv = 0.f;
#pragma unroll
            for (int s = 0; s < 4; s++) {
                const float dA = __expf(dt_v * Aa[s]);
                h[s] = fmaf(dA, h[s], dtx * bc[(sg << 2) + s]);
                accv = fmaf(h[s], bc[16 + (sg << 2) + s], accv);
            }
            accv += __shfl_down_sync(0xffffffffu, accv, 2, 4);
            accv += __shfl_down_sync(0xffffffffu, accv, 1, 4);
            if (sg == 0) {
                const float z_v = s_z[(tt << 5) + cl];
                float yv = fmaf(x_v, Dv, accv);
                yv *= z_v / (1.f + __expf(-z_v));
                yb[(long)(t0 + tt) * DI + cl] = yv;
            }
        }
    }
}

// ---------------- combine o_proj into ffn2 ----------------
__global__ __launch_bounds__(256) void combine_w_kernel(
    const float* __restrict__ o_w, const float* __restrict__ o_b,
    const float* __restrict__ f_w2, const float* __restrict__ f_b2)
{
    const int i = blockIdx.x;
    __shared__ float s_ow[DM];
    __shared__ float red[256];
    for (int j = threadIdx.x; j < DM; j += 256) s_ow[j] = o_w[i * DM + j];
    __syncthreads();

    for (int k = threadIdx.x; k < 2 * DM; k += 256) {
        float acc = 0.f;
        for (int j = 0; j < DM; j++)
            acc = fmaf(s_ow[j], f_w2[j * (2 * DM) + k], acc);
        g_cw[i * (2 * DM) + k] = acc;
    }
    float pb = 0.f;
    for (int j = threadIdx.x; j < DM; j += 256) pb = fmaf(s_ow[j], f_b2[j], pb);
    red[threadIdx.x] = pb;
    __syncthreads();
    for (int st = 128; st > 0; st >>= 1) {
        if (threadIdx.x < st) red[threadIdx.x] += red[threadIdx.x + st];
        __syncthreads();
    }
    if (threadIdx.x == 0) g_cb[i] = red[0] + o_b[i];
}

// ---------------- final layernorm + residual + transpose-out ----------------
__global__ __launch_bounds__(256) void ln2_kernel(
    const float* __restrict__ g, const float* __restrict__ bb, float* __restrict__ out)
{
    __shared__ float t1[16][193];
    __shared__ float t2[16][193];
    __shared__ float s_mean[16], s_rstd[16];
    const int b = blockIdx.y, n0 = blockIdx.x << 4;
    const int tid = threadIdx.x;

    for (int i = tid; i < 16 * DM; i += 256) {
        int nn = i / DM, dd = i % DM;
        long adr = ((long)(b << 10) + n0 + nn) * DM + dd;
        t1[nn][dd] = g_h3[adr];
        t2[nn][dd] = g_xs[adr];
    }
    __syncthreads();

    const int nn = tid >> 4, l = tid & 15;
    float s = 0.f, s2 = 0.f;
    for (int dd = l; dd < DM; dd += 16) { float v = t1[nn][dd]; s += v; s2 = fmaf(v, v, s2); }
    s  += __shfl_down_sync(0xffffffffu, s,  8, 16);
    s2 += __shfl_down_sync(0xffffffffu, s2, 8, 16);
    s  += __shfl_down_sync(0xffffffffu, s,  4, 16);
    s2 += __shfl_down_sync(0xffffffffu, s2, 4, 16);
    s  += __shfl_down_sync(0xffffffffu, s,  2, 16);
    s2 += __shfl_down_sync(0xffffffffu, s2, 2, 16);
    s  += __shfl_down_sync(0xffffffffu, s,  1, 16);
    s2 += __shfl_down_sync(0xffffffffu, s2, 1, 16);
    if (l == 0) {
        float m = s * (1.f / DM);
        float var = s2 * (1.f / DM) - m * m;
        s_mean[nn] = m;
        s_rstd[nn] = rsqrtf(var + 1e-5f);
    }
    __syncthreads();

    for (int i = tid; i < DM * 16; i += 256) {
        int dd = i >> 4, nn2 = i & 15;
        float v = (t1[nn2][dd] - s_mean[nn2]) * s_rstd[nn2] * g[dd] + bb[dd] + t2[nn2][dd];
        out[((long)(b * DM + dd) << 10) + n0 + nn2] = v;
    }
}

// ---------------- launcher ----------------
extern "C" void kernel_launch(void* const* d_in, const int* in_sizes, int n_in,
                              void* d_out, int out_size)
{
    const float* x        = (const float*)d_in[0];
    const float* norm_g   = (const float*)d_in[1];
    const float* norm_b   = (const float*)d_in[2];
    const float* in_w     = (const float*)d_in[3];
    const float* in_b     = (const float*)d_in[4];
    const float* m_in_w   = (const float*)d_in[5];
    const float* m_conv_w = (const float*)d_in[6];
    const float* m_conv_b = (const float*)d_in[7];
    const float* m_xp_w   = (const float*)d_in[8];
    const float* m_dt_w   = (const float*)d_in[9];
    const float* m_dt_b   = (const float*)d_in[10];
    const float* m_Alog   = (const float*)d_in[11];
    const float* m_D      = (const float*)d_in[12];
    const float* m_out_w  = (const float*)d_in[13];
    const float* f_w1     = (const float*)d_in[14];
    const float* f_b1     = (const float*)d_in[15];
    const float* f_w2     = (const float*)d_in[16];
    const float* f_b2     = (const float*)d_in[17];
    const float* o_w      = (const float*)d_in[18];
    const float* o_b      = (const float*)d_in[19];
    const float* on_g     = (const float*)d_in[20];
    const float* on_b     = (const float*)d_in[21];
    float* out = (float*)d_out;

    float *p_xs, *p_xp, *p_xz, *p_xsm, *p_dbl, *p_y, *p_fused, *p_hdn, *p_h3, *p_cw, *p_cb;
    cudaGetSymbolAddress((void**)&p_xs, g_xs);
    cudaGetSymbolAddress((void**)&p_xp, g_xp);
    cudaGetSymbolAddress((void**)&p_xz, g_xz);
    cudaGetSymbolAddress((void**)&p_xsm, g_xsm);
    cudaGetSymbolAddress((void**)&p_dbl, g_dbl);
    cudaGetSymbolAddress((void**)&p_y, g_y);
    cudaGetSymbolAddress((void**)&p_fused, g_fused);
    cudaGetSymbolAddress((void**)&p_hdn, g_hdn);
    cudaGetSymbolAddress((void**)&p_h3, g_h3);
    cudaGetSymbolAddress((void**)&p_cw, g_cw);
    cudaGetSymbolAddress((void**)&p_cb, g_cb);

    // 1) dummy (aims the ncu capture slot at the xz GEMM)
    dummy_kernel<<<1, 32>>>();

    // 2) layernorm + transpose
    ln1_kernel<<<dim3(32, 4), 256>>>(x, norm_g, norm_b);

    // 3) xp = xs @ in_w^T + in_b   (4096 x 192 x 192)
    gemm_bf16_kernel<2><<<dim3(3, 32, 1), 256>>>(p_xs, in_w, in_b, p_xp,
        LROWS, DM, DM, DM, DM, 0, 0, 0, 0, 0, 0);

    // 4) xz[d] = gather_d(xp) @ m_in_w[d]^T   (4 x 4096 x 768 x 192), A-gather fused
    gemm_bf16_kernel<4><<<dim3(6, 32, 4), 256>>>(p_xp, m_in_w, nullptr, p_xz,
        LROWS, 2 * DI, DM, DM, 2 * DI,
        0, (long)2 * DI * DM, 0, (long)LROWS * 2 * DI, 0, 1);

    // 5) causal depthwise conv + silu
    conv_silu_kernel<<<1536, 256>>>(m_conv_w, m_conv_b);

    // 6) dbl[d] = xsm[d] @ m_xp_w[d]^T   (Nn=44) — tf32 for precision in the scan path
    gemm_tf32_kernel<2><<<dim3(1, 32, 4), 256>>>(p_xsm, m_xp_w, nullptr, p_dbl,
        LROWS, DBL_W, DI, DI, DBL_W,
        (long)LROWS * DI, (long)DBL_W * DI, 0, (long)LROWS * DBL_W, 0, 0);

    // 7) selective scan (fused dt-proj + softplus + D skip + silu(z) gate)
    scan_kernel<<<dim3(12, BATCH, NDIR), 128>>>(m_Alog, m_D, m_dt_w, m_dt_b);

    // 8) fused[:, d*DM:(d+1)*DM] = scatter_d(y[d] @ m_out_w[d]^T)
    gemm_bf16_kernel<2><<<dim3(3, 32, 4), 256>>>(p_y, m_out_w, nullptr, p_fused,
        LROWS, DM, DI, DI, 4 * DM,
        (long)LROWS * DI, (long)DM * DI, 0, (long)DM, 0, 2);

    // 9) hdn = gelu(fused @ f_w1^T + f_b1)   (4096 x 384 x 768)
    gemm_bf16_kernel<4><<<dim3(3, 32, 1), 256>>>(p_fused, f_w1, f_b1, p_hdn,
        LROWS, 2 * DM, 4 * DM, 4 * DM, 2 * DM, 0, 0, 0, 0, 2, 0);

    // 10) combined weight: Wc = o_w @ f_w2, bc = o_w @ f_b2 + o_b
    combine_w_kernel<<<DM, 256>>>(o_w, o_b, f_w2, f_b2);

    // 11) h3 = hdn @ Wc^T + bc   (4096 x 192 x 384)
    gemm_bf16_kernel<2><<<dim3(3, 32, 1), 256>>>(p_hdn, p_cw, p_cb, p_h3,
        LROWS, DM, 2 * DM, 2 * DM, DM, 0, 0, 0, 0, 0, 0);

    // 12) final layernorm + residual + transpose out
    ln2_kernel<<<dim3(64, 4), 256>>>(on_g, on_b, out);
}

// round 7
// speedup vs baseline: 2.3971x; 1.1548x over previous
#include <cuda_runtime.h>
#include <cuda_bf16.h>
#include <math.h>
#include <stdint.h>

// ---------------- problem constants ----------------
#define BATCH 4
#define DM    192
#define DI    384
#define DS    16
#define DR    12
#define NSEQ  1024
#define LROWS 4096
#define NDIR  4
#define DBL_W 44

typedef __nv_bfloat16 bf16;

// ---------------- scratch ----------------
__device__ float g_xs  [LROWS*DM];            // fp32 residual
__device__ float g_dbl [NDIR*LROWS*DBL_W];    // fp32: feeds scan
__device__ float g_h3  [LROWS*DM];            // fp32: feeds ln2
__device__ float g_cb  [DM];

__device__ bf16 g_xs_h  [LROWS*DM];
__device__ bf16 g_xp_h  [LROWS*DM];
__device__ bf16 g_xz_h  [(long)NDIR*LROWS*2*DI];
__device__ bf16 g_xsm_h [NDIR*LROWS*DI];
__device__ bf16 g_y_h   [NDIR*LROWS*DI];
__device__ bf16 g_fused_h[LROWS*4*DM];
__device__ bf16 g_hdn_h [LROWS*2*DM];

// bf16 weights
__device__ bf16 g_w_in_h    [DM*DM];
__device__ bf16 g_w_inproj_h[NDIR*2*DI*DM];
__device__ bf16 g_w_xp_h    [NDIR*DBL_W*DI];
__device__ bf16 g_w_out_h   [NDIR*DM*DI];
__device__ bf16 g_w_f1_h    [2*DM*4*DM];
__device__ bf16 g_cw_h      [DM*2*DM];

// ---------------- helpers ----------------
__device__ __forceinline__ float apply_act(float v, int act) {
    if (act == 1) {
        v = (v > 20.f) ? v : log1pf(__expf(v));
    } else if (act == 2) {
        v = 0.5f * v * (1.f + erff(v * 0.70710678118654752f));
    }
    return v;
}

__device__ __forceinline__ int seq_src_n(int d, int t) {
    if (d == 0) return t;
    if (d == 1) return NSEQ - 1 - t;
    if (d == 2) return ((t & 31) << 5) + (t >> 5);
    int u = NSEQ - 1 - t;
    return ((u & 31) << 5) + (u >> 5);
}

__device__ __forceinline__ void mma_bf16(float4& c,
    uint32_t a0, uint32_t a1, uint32_t a2, uint32_t a3, uint32_t b0, uint32_t b1) {
    asm volatile(
        "mma.sync.aligned.m16n8k16.row.col.f32.bf16.bf16.f32 "
        "{%0,%1,%2,%3}, {%4,%5,%6,%7}, {%8,%9}, {%0,%1,%2,%3};\n"
        : "+f"(c.x), "+f"(c.y), "+f"(c.z), "+f"(c.w)
        : "r"(a0), "r"(a1), "r"(a2), "r"(a3), "r"(b0), "r"(b1));
}

__device__ __forceinline__ void ldsm_x4(uint32_t addr,
    uint32_t& r0, uint32_t& r1, uint32_t& r2, uint32_t& r3) {
    asm volatile("ldmatrix.sync.aligned.m8n8.x4.shared.b16 {%0,%1,%2,%3}, [%4];"
        : "=r"(r0), "=r"(r1), "=r"(r2), "=r"(r3) : "r"(addr));
}

__device__ __forceinline__ uint32_t pack_bf2(float lo, float hi) {
    __nv_bfloat162 p = __floats2bfloat162_rn(lo, hi);
    return *(uint32_t*)&p;
}

__device__ __forceinline__ void cp16(uint32_t saddr, const void* gptr, int src_bytes) {
    asm volatile("cp.async.cg.shared.global [%0], [%1], 16, %2;\n"
        :: "r"(saddr), "l"(gptr), "r"(src_bytes));
}
__device__ __forceinline__ void cp_commit() {
    asm volatile("cp.async.commit_group;\n");
}
__device__ __forceinline__ void cp_wait2() {
    asm volatile("cp.async.wait_group 2;\n");
}

// ---------------- weight conversion (fp32 -> bf16), 6 segments ----------------
__global__ __launch_bounds__(256) void convert_w_kernel(
    const float* s0, const float* s1, const float* s2, const float* s3, const float* s4)
{
    const int n0 = DM*DM, n1 = NDIR*2*DI*DM, n2 = NDIR*DBL_W*DI, n3 = NDIR*DM*DI, n4 = 2*DM*4*DM;
    long i = (long)blockIdx.x * 256 + threadIdx.x;
    long off = 0;
    if (i < off + n0) { g_w_in_h[i - off] = __float2bfloat16(s0[i - off]); return; } off += n0;
    if (i < off + n1) { g_w_inproj_h[i - off] = __float2bfloat16(s1[i - off]); return; } off += n1;
    if (i < off + n2) { g_w_xp_h[i - off] = __float2bfloat16(s2[i - off]); return; } off += n2;
    if (i < off + n3) { g_w_out_h[i - off] = __float2bfloat16(s3[i - off]); return; } off += n3;
    if (i < off + n4) { g_w_f1_h[i - off] = __float2bfloat16(s4[i - off]); return; }
}

// ---------------- bf16 cp.async GEMM:  C = act(A @ W^T + bias) ----------------
// A: M x K bf16 (row stride lda), W: Nn x K bf16, C: fp32 (cbf=0) or bf16 (cbf=1).
// Block tile 128 x (NFRAG*32), BK=16, 4-stage cp.async pipeline, 256 threads.
// Requirements: M % 128 == 0, K % 16 == 0, K >= 48, Nn even, lda*2 % 16 == 0.
// mode: 0 plain, 1 gather A rows via seq_src_n(z,.), 2 scatter C rows via seq_src_n(z,.)
template<int NFRAG>
__global__ __launch_bounds__(256) void gemm_bf16_kernel(
    const bf16* __restrict__ A, const bf16* __restrict__ W,
    const float* __restrict__ bias, void* __restrict__ Cv,
    int M, int Nn, int K, int lda, int ldc,
    long sA_, long sW_, long sB_, long sC_, int act, int mode, int cbf)
{
    constexpr int TN = NFRAG * 32;
    constexpr int NST = 4;
    const int z = blockIdx.z;
    A += z * sA_; W += z * sW_;
    const float* bz = bias ? (bias + z * sB_) : (const float*)0;

    __shared__ __align__(16) bf16 sA[NST][128][24];
    __shared__ __align__(16) bf16 sB[NST][TN][24];
    constexpr uint32_t A_ST = 128 * 48;
    constexpr uint32_t B_ST = TN * 48;

    const int bm = blockIdx.y << 7, bn = blockIdx.x * TN;
    const int tid = threadIdx.x;

    // staging: 2 threads per row, 16B (8 bf16) each
    const int r     = tid >> 1;
    const int slice = tid & 1;
    long arowi;
    if (mode == 1) {
        int gm = bm + r;
        arowi = (long)(((gm >> 10) << 10) + seq_src_n(z, gm & 1023));
    } else {
        arowi = bm + r;
    }
    const bf16* aPtr = A + arowi * lda + (slice << 3);
    const bool bactive = (r < TN);
    const int gw_n = bn + r;
    const bool wv = bactive && (gw_n < Nn);
    const bf16* wPtr = W + (wv ? (long)gw_n * K : 0) + (slice << 3);

    const uint32_t aDst0 = (uint32_t)__cvta_generic_to_shared(&sA[0][r][slice << 3]);
    const uint32_t bDst0 = bactive ?
        (uint32_t)__cvta_generic_to_shared(&sB[0][r & (TN - 1)][slice << 3]) : 0u;

    const int nkt = K >> 4;

    // issue one stage
    auto issue = [&](int kt) {
        const int s = kt & (NST - 1);
        cp16(aDst0 + s * A_ST, aPtr + (kt << 4), 16);
        if (bactive) cp16(bDst0 + s * B_ST, wPtr + (kt << 4), wv ? 16 : 0);
        cp_commit();
    };

    // prologue: 3 stages
    issue(0); issue(1); issue(2);

    float4 acc[4][NFRAG];
#pragma unroll
    for (int i = 0; i < 4; i++)
#pragma unroll
        for (int j = 0; j < NFRAG; j++) acc[i][j] = make_float4(0.f, 0.f, 0.f, 0.f);

    const int lane = tid & 31, wid = tid >> 5;
    const int wm = wid >> 2, wn = wid & 3;

    // ldmatrix lane addressing (same fragment scheme as validated round-6 kernel)
    const int a_row = (wm << 6) + (lane & 7) + (((lane >> 3) & 1) << 3);
    const int a_kc  = (lane >> 4) << 3;
    const uint32_t aAddr0 = (uint32_t)__cvta_generic_to_shared(&sA[0][a_row][a_kc]);
    const int b_row = wn * (NFRAG * 8) + (lane & 7) + ((lane >> 4) << 3);
    const int b_kc  = ((lane >> 3) & 1) << 3;
    const uint32_t bAddr0 = (uint32_t)__cvta_generic_to_shared(&sB[0][b_row][b_kc]);

    for (int kt = 0; kt < nkt; kt++) {
        cp_wait2();
        __syncthreads();
        if (kt + NST - 1 < nkt) issue(kt + NST - 1);

        const int s = kt & (NST - 1);
        const uint32_t aA = aAddr0 + s * A_ST;
        const uint32_t bA = bAddr0 + s * B_ST;
        uint32_t ra[4][4];
#pragma unroll
        for (int i = 0; i < 4; i++)
            ldsm_x4(aA + i * (16 * 48), ra[i][0], ra[i][1], ra[i][2], ra[i][3]);
        uint32_t rb[NFRAG][2];
#pragma unroll
        for (int jp = 0; jp < NFRAG / 2; jp++) {
            uint32_t b0, b1, b2, b3;
            ldsm_x4(bA + jp * (16 * 48), b0, b1, b2, b3);
            rb[2 * jp][0] = b0; rb[2 * jp][1] = b1;
            rb[2 * jp + 1][0] = b2; rb[2 * jp + 1][1] = b3;
        }
#pragma unroll
        for (int i = 0; i < 4; i++)
#pragma unroll
            for (int j = 0; j < NFRAG; j++)
                mma_bf16(acc[i][j], ra[i][0], ra[i][1], ra[i][2], ra[i][3],
                         rb[j][0], rb[j][1]);
    }

    // ---- epilogue ----
    const int row0 = lane >> 2;
    const int col0 = (lane & 3) << 1;
    float* Cf = (float*)Cv + z * sC_;
    bf16*  Ch = (bf16*)Cv + z * sC_;
#pragma unroll
    for (int i = 0; i < 4; i++) {
        const int gmA = bm + (wm << 6) + (i << 4) + row0;
        const int gmB = gmA + 8;
        long rA, rB;
        if (mode == 2) {
            rA = ((gmA >> 10) << 10) + seq_src_n(z, gmA & 1023);
            rB = ((gmB >> 10) << 10) + seq_src_n(z, gmB & 1023);
        } else { rA = gmA; rB = gmB; }
#pragma unroll
        for (int j = 0; j < NFRAG; j++) {
            const int gn = bn + wn * (NFRAG * 8) + (j << 3) + col0;
            if (gn < Nn) {
                float4 v = acc[i][j];
                if (bz) {
                    const float b0 = bz[gn], b1 = bz[gn + 1];
                    v.x += b0; v.y += b1; v.z += b0; v.w += b1;
                }
                if (act) {
                    v.x = apply_act(v.x, act); v.y = apply_act(v.y, act);
                    v.z = apply_act(v.z, act); v.w = apply_act(v.w, act);
                }
                if (cbf) {
                    *(uint32_t*)&Ch[rA * (long)ldc + gn] = pack_bf2(v.x, v.y);
                    *(uint32_t*)&Ch[rB * (long)ldc + gn] = pack_bf2(v.z, v.w);
                } else {
                    *(float2*)&Cf[rA * (long)ldc + gn] = make_float2(v.x, v.y);
                    *(float2*)&Cf[rB * (long)ldc + gn] = make_float2(v.z, v.w);
                }
            }
        }
    }
}

// ---------------- kernel 1: transpose + layernorm (writes fp32 residual + bf16) ----------------
__global__ __launch_bounds__(256) void ln1_kernel(
    const float* __restrict__ x, const float* __restrict__ g, const float* __restrict__ bb)
{
    __shared__ float tile[DM][33];
    __shared__ float s_mean[32], s_rstd[32];
    const int b = blockIdx.y, n0 = blockIdx.x << 5;
    const int tid = threadIdx.x;

    for (int i = tid; i < DM * 32; i += 256) {
        int d = i >> 5, nn = i & 31;
        tile[d][nn] = x[((long)(b * DM + d) << 10) + n0 + nn];
    }
    __syncthreads();

    const int nn = tid >> 3, l = tid & 7;
    float s = 0.f, s2 = 0.f;
    for (int d = l; d < DM; d += 8) { float v = tile[d][nn]; s += v; s2 = fmaf(v, v, s2); }
    s  += __shfl_down_sync(0xffffffffu, s,  4, 8);
    s2 += __shfl_down_sync(0xffffffffu, s2, 4, 8);
    s  += __shfl_down_sync(0xffffffffu, s,  2, 8);
    s2 += __shfl_down_sync(0xffffffffu, s2, 2, 8);
    s  += __shfl_down_sync(0xffffffffu, s,  1, 8);
    s2 += __shfl_down_sync(0xffffffffu, s2, 1, 8);
    if (l == 0) {
        float m = s * (1.f / DM);
        float var = s2 * (1.f / DM) - m * m;
        s_mean[nn] = m;
        s_rstd[nn] = rsqrtf(var + 1e-5f);
    }
    __syncthreads();

    for (int i = tid; i < DM * 32; i += 256) {
        int nn2 = i / DM, d = i % DM;
        float v = (tile[d][nn2] - s_mean[nn2]) * s_rstd[nn2] * g[d] + bb[d];
        long adr = ((long)(b << 10) + n0 + nn2) * DM + d;
        g_xs[adr] = v;
        g_xs_h[adr] = __float2bfloat16(v);
    }
}

// ---------------- causal depthwise conv (width 4) + silu, bf16 io ----------------
__global__ __launch_bounds__(256) void conv_silu_kernel(
    const float* __restrict__ cw, const float* __restrict__ cb)
{
    const int gi = blockIdx.x * 256 + threadIdx.x;
    const int c = gi % DI;
    const int rest = gi / DI;
    const int tb = rest & 63;
    const int db = rest >> 6;
    const int d = db >> 2;
    const int t0 = tb << 4;

    const float* w = cw + ((long)d * DI + c) * 4;
    const float w0 = w[0], w1 = w[1], w2 = w[2], w3 = w[3];
    const float bias = cb[d * DI + c];
    const bf16* src = g_xz_h + ((long)db * NSEQ) * (2 * DI) + c;
    bf16* dst = g_xsm_h + ((long)db * NSEQ) * DI + c;

    float r0 = (t0 >= 3) ? __bfloat162float(src[(long)(t0 - 3) * (2 * DI)]) : 0.f;
    float r1 = (t0 >= 2) ? __bfloat162float(src[(long)(t0 - 2) * (2 * DI)]) : 0.f;
    float r2 = (t0 >= 1) ? __bfloat162float(src[(long)(t0 - 1) * (2 * DI)]) : 0.f;
#pragma unroll
    for (int i = 0; i < 16; i++) {
        const int t = t0 + i;
        const float cur = __bfloat162float(src[(long)t * (2 * DI)]);
        float a = bias;
        a = fmaf(w0, r0, a);
        a = fmaf(w1, r1, a);
        a = fmaf(w2, r2, a);
        a = fmaf(w3, cur, a);
        dst[(long)t * DI] = __float2bfloat16(a / (1.f + __expf(-a)));
        r0 = r1; r1 = r2; r2 = cur;
    }
}

// ---------------- selective scan with fused dt-projection ----------------
#define SCH 16
__global__ __launch_bounds__(128) void scan_kernel(
    const float* __restrict__ Alog, const float* __restrict__ Dp,
    const float* __restrict__ Wdt, const float* __restrict__ bdt)
{
    const int d = blockIdx.z, b = blockIdx.y;
    const int c0 = blockIdx.x << 5;
    const int tid = threadIdx.x;
    const int cl = tid >> 2;
    const int sg = tid & 3;
    const int c = c0 + cl;
    const long baseI = ((long)d * BATCH + b) * NSEQ;

    const bf16* xb   = g_xsm_h + baseI * DI       + c0;
    const bf16* zb   = g_xz_h  + baseI * (2 * DI) + DI + c0;
    const float* dblp = g_dbl + baseI * DBL_W;
    bf16* yb          = g_y_h + baseI * DI        + c0;

    __shared__ float s_wdt[32 * 13];
    __shared__ float s_bdt[32];
    __shared__ float s_raw[SCH * 12];
    __shared__ float s_bc [SCH * 32];
    __shared__ float s_dt [SCH * 32];
    __shared__ float s_x  [SCH * 32];
    __shared__ float s_z  [SCH * 32];

    for (int i = tid; i < 32 * DR; i += 128)
        s_wdt[(i / DR) * 13 + (i % DR)] = Wdt[((long)(d * DI + c0) + i / DR) * DR + (i % DR)];
    if (tid < 32) s_bdt[tid] = bdt[d * DI + c0 + tid];

    float Aa[4];
#pragma unroll
    for (int s = 0; s < 4; s++)
        Aa[s] = -expf(Alog[((long)(d * DI + c)) * DS + (sg << 2) + s]);
    const float Dv = Dp[d * DI + c];

    float h[4];
#pragma unroll
    for (int s = 0; s < 4; s++) h[s] = 0.f;

    __syncthreads();

    for (int t0 = 0; t0 < NSEQ; t0 += SCH) {
        __syncthreads();
        for (int i = tid; i < SCH * DR; i += 128)
            s_raw[i] = dblp[(long)(t0 + i / DR) * DBL_W + (i % DR)];
#pragma unroll
        for (int k = 0; k < 4; k++) {
            const int idx = tid + (k << 7);
            const int row = idx >> 5, col = idx & 31;
            s_bc[idx] = dblp[(long)(t0 + row) * DBL_W + DR + col];
            s_x [idx] = __bfloat162float(xb[(long)(t0 + row) * DI + col]);
            s_z [idx] = __bfloat162float(zb[(long)(t0 + row) * (2 * DI) + col]);
        }
        __syncthreads();
#pragma unroll
        for (int k = 0; k < 4; k++) {
            const int idx = tid + (k << 7);
            const int row = idx >> 5, col = idx & 31;
            float v = s_bdt[col];
#pragma unroll
            for (int j = 0; j < DR; j++)
                v = fmaf(s_raw[row * DR + j], s_wdt[col * 13 + j], v);
            s_dt[idx] = (v > 20.f) ? v : log1pf(__expf(v));
        }
        __syncthreads();

        for (int tt = 0; tt < SCH; tt++) {
            const float dt_v = s_dt[(tt << 5) + cl];
            const float x_v  = s_x [(tt << 5) + cl];
            const float* bc = s_bc + (tt << 5);
            const float dtx = dt_v * x_v;
            float accv = 0.f;
#pragma unroll
            for (int s = 0; s < 4; s++) {
                const float dA = __expf(dt_v * Aa[s]);
                h[s] = fmaf(dA, h[s], dtx * bc[(sg << 2) + s]);
                accv = fmaf(h[s], bc[16 + (sg << 2) + s], accv);
            }
            accv += __shfl_down_sync(0xffffffffu, accv, 2, 4);
            accv += __shfl_down_sync(0xffffffffu, accv, 1, 4);
            if (sg == 0) {
                const float z_v = s_z[(tt << 5) + cl];
                float yv = fmaf(x_v, Dv, accv);
                yv *= z_v / (1.f + __expf(-z_v));
                yb[(long)(t0 + tt) * DI + cl] = __float2bfloat16(yv);
            }
        }
    }
}

// ---------------- combine o_proj into ffn2 (bf16 weight out) ----------------
__global__ __launch_bounds__(256) void combine_w_kernel(
    const float* __restrict__ o_w, const float* __restrict__ o_b,
    const float* __restrict__ f_w2, const float* __restrict__ f_b2)
{
    const int i = blockIdx.x;
    __shared__ float s_ow[DM];
    __shared__ float red[256];
    for (int j = threadIdx.x; j < DM; j += 256) s_ow[j] = o_w[i * DM + j];
    __syncthreads();

    for (int k = threadIdx.x; k < 2 * DM; k += 256) {
        float acc = 0.f;
        for (int j = 0; j < DM; j++)
            acc = fmaf(s_ow[j], f_w2[j * (2 * DM) + k], acc);
        g_cw_h[i * (2 * DM) + k] = __float2bfloat16(acc);
    }
    float pb = 0.f;
    for (int j = threadIdx.x; j < DM; j += 256) pb = fmaf(s_ow[j], f_b2[j], pb);
    red[threadIdx.x] = pb;
    __syncthreads();
    for (int st = 128; st > 0; st >>= 1) {
        if (threadIdx.x < st) red[threadIdx.x] += red[threadIdx.x + st];
        __syncthreads();
    }
    if (threadIdx.x == 0) g_cb[i] = red[0] + o_b[i];
}

// ---------------- final layernorm + residual + transpose-out ----------------
__global__ __launch_bounds__(256) void ln2_kernel(
    const float* __restrict__ g, const float* __restrict__ bb, float* __restrict__ out)
{
    __shared__ float t1[16][193];
    __shared__ float t2[16][193];
    __shared__ float s_mean[16], s_rstd[16];
    const int b = blockIdx.y, n0 = blockIdx.x << 4;
    const int tid = threadIdx.x;

    for (int i = tid; i < 16 * DM; i += 256) {
        int nn = i / DM, dd = i % DM;
        long adr = ((long)(b << 10) + n0 + nn) * DM + dd;
        t1[nn][dd] = g_h3[adr];
        t2[nn][dd] = g_xs[adr];
    }
    __syncthreads();

    const int nn = tid >> 4, l = tid & 15;
    float s = 0.f, s2 = 0.f;
    for (int dd = l; dd < DM; dd += 16) { float v = t1[nn][dd]; s += v; s2 = fmaf(v, v, s2); }
    s  += __shfl_down_sync(0xffffffffu, s,  8, 16);
    s2 += __shfl_down_sync(0xffffffffu, s2, 8, 16);
    s  += __shfl_down_sync(0xffffffffu, s,  4, 16);
    s2 += __shfl_down_sync(0xffffffffu, s2, 4, 16);
    s  += __shfl_down_sync(0xffffffffu, s,  2, 16);
    s2 += __shfl_down_sync(0xffffffffu, s2, 2, 16);
    s  += __shfl_down_sync(0xffffffffu, s,  1, 16);
    s2 += __shfl_down_sync(0xffffffffu, s2, 1, 16);
    if (l == 0) {
        float m = s * (1.f / DM);
        float var = s2 * (1.f / DM) - m * m;
        s_mean[nn] = m;
        s_rstd[nn] = rsqrtf(var + 1e-5f);
    }
    __syncthreads();

    for (int i = tid; i < DM * 16; i += 256) {
        int dd = i >> 4, nn2 = i & 15;
        float v = (t1[nn2][dd] - s_mean[nn2]) * s_rstd[nn2] * g[dd] + bb[dd] + t2[nn2][dd];
        out[((long)(b * DM + dd) << 10) + n0 + nn2] = v;
    }
}

// ---------------- launcher ----------------
extern "C" void kernel_launch(void* const* d_in, const int* in_sizes, int n_in,
                              void* d_out, int out_size)
{
    const float* x        = (const float*)d_in[0];
    const float* norm_g   = (const float*)d_in[1];
    const float* norm_b   = (const float*)d_in[2];
    const float* in_w     = (const float*)d_in[3];
    const float* in_b     = (const float*)d_in[4];
    const float* m_in_w   = (const float*)d_in[5];
    const float* m_conv_w = (const float*)d_in[6];
    const float* m_conv_b = (const float*)d_in[7];
    const float* m_xp_w   = (const float*)d_in[8];
    const float* m_dt_w   = (const float*)d_in[9];
    const float* m_dt_b   = (const float*)d_in[10];
    const float* m_Alog   = (const float*)d_in[11];
    const float* m_D      = (const float*)d_in[12];
    const float* m_out_w  = (const float*)d_in[13];
    const float* f_w1     = (const float*)d_in[14];
    const float* f_b1     = (const float*)d_in[15];
    const float* f_w2     = (const float*)d_in[16];
    const float* f_b2     = (const float*)d_in[17];
    const float* o_w      = (const float*)d_in[18];
    const float* o_b      = (const float*)d_in[19];
    const float* on_g     = (const float*)d_in[20];
    const float* on_b     = (const float*)d_in[21];
    float* out = (float*)d_out;

    float *p_dbl, *p_h3, *p_cb;
    bf16 *p_xs_h, *p_xp_h, *p_xz_h, *p_xsm_h, *p_y_h, *p_fused_h, *p_hdn_h;
    bf16 *p_w_in, *p_w_inproj, *p_w_xp, *p_w_out, *p_w_f1, *p_cw_h;
    cudaGetSymbolAddress((void**)&p_dbl, g_dbl);
    cudaGetSymbolAddress((void**)&p_h3, g_h3);
    cudaGetSymbolAddress((void**)&p_cb, g_cb);
    cudaGetSymbolAddress((void**)&p_xs_h, g_xs_h);
    cudaGetSymbolAddress((void**)&p_xp_h, g_xp_h);
    cudaGetSymbolAddress((void**)&p_xz_h, g_xz_h);
    cudaGetSymbolAddress((void**)&p_xsm_h, g_xsm_h);
    cudaGetSymbolAddress((void**)&p_y_h, g_y_h);
    cudaGetSymbolAddress((void**)&p_fused_h, g_fused_h);
    cudaGetSymbolAddress((void**)&p_hdn_h, g_hdn_h);
    cudaGetSymbolAddress((void**)&p_w_in, g_w_in_h);
    cudaGetSymbolAddress((void**)&p_w_inproj, g_w_inproj_h);
    cudaGetSymbolAddress((void**)&p_w_xp, g_w_xp_h);
    cudaGetSymbolAddress((void**)&p_w_out, g_w_out_h);
    cudaGetSymbolAddress((void**)&p_w_f1, g_w_f1_h);
    cudaGetSymbolAddress((void**)&p_cw_h, g_cw_h);

    const int n_w = DM*DM + NDIR*2*DI*DM + NDIR*DBL_W*DI + NDIR*DM*DI + 2*DM*4*DM;

    // 1) weight conversion (also occupies the pre-capture launch slot)
    convert_w_kernel<<<(n_w + 255) / 256, 256>>>(in_w, m_in_w, m_xp_w, m_out_w, f_w1);

    // 2) layernorm + transpose
    ln1_kernel<<<dim3(32, 4), 256>>>(x, norm_g, norm_b);

    // 3) xp = xs @ in_w^T + in_b
    gemm_bf16_kernel<2><<<dim3(3, 32, 1), 256>>>(p_xs_h, p_w_in, in_b, p_xp_h,
        LROWS, DM, DM, DM, DM, 0, 0, 0, 0, 0, 0, 1);

    // 4) xz[d] = gather_d(xp) @ m_in_w[d]^T
    gemm_bf16_kernel<4><<<dim3(6, 32, 4), 256>>>(p_xp_h, p_w_inproj, nullptr, p_xz_h,
        LROWS, 2 * DI, DM, DM, 2 * DI,
        0, (long)2 * DI * DM, 0, (long)LROWS * 2 * DI, 0, 1, 1);

    // 5) causal depthwise conv + silu
    conv_silu_kernel<<<1536, 256>>>(m_conv_w, m_conv_b);

    // 6) dbl[d] = xsm[d] @ m_xp_w[d]^T  (fp32 out for the scan)
    gemm_bf16_kernel<2><<<dim3(1, 32, 4), 256>>>(p_xsm_h, p_w_xp, nullptr, p_dbl,
        LROWS, DBL_W, DI, DI, DBL_W,
        (long)LROWS * DI, (long)DBL_W * DI, 0, (long)LROWS * DBL_W, 0, 0, 0);

    // 7) selective scan
    scan_kernel<<<dim3(12, BATCH, NDIR), 128>>>(m_Alog, m_D, m_dt_w, m_dt_b);

    // 8) fused[:, d*DM:(d+1)*DM] = scatter_d(y[d] @ m_out_w[d]^T)
    gemm_bf16_kernel<2><<<dim3(3, 32, 4), 256>>>(p_y_h, p_w_out, nullptr, p_fused_h,
        LROWS, DM, DI, DI, 4 * DM,
        (long)LROWS * DI, (long)DM * DI, 0, (long)DM, 0, 2, 1);

    // 9) hdn = gelu(fused @ f_w1^T + f_b1)
    gemm_bf16_kernel<4><<<dim3(3, 32, 1), 256>>>(p_fused_h, p_w_f1, f_b1, p_hdn_h,
        LROWS, 2 * DM, 4 * DM, 4 * DM, 2 * DM, 0, 0, 0, 0, 2, 0, 1);

    // 10) combined weight: Wc = o_w @ f_w2 (bf16), bc = o_w @ f_b2 + o_b
    combine_w_kernel<<<DM, 256>>>(o_w, o_b, f_w2, f_b2);

    // 11) h3 = hdn @ Wc^T + bc  (fp32 out)
    gemm_bf16_kernel<2><<<dim3(3, 32, 1), 256>>>(p_hdn_h, p_cw_h, p_cb, p_h3,
        LROWS, DM, 2 * DM, 2 * DM, DM, 0, 0, 0, 0, 0, 0, 0);

    // 12) final layernorm + residual + transpose out
    ln2_kernel<<<dim3(64, 4), 256>>>(on_g, on_b, out);
}

// round 8
// speedup vs baseline: 2.7012x; 1.1269x over previous
#include <cuda_runtime.h>
#include <cuda_bf16.h>
#include <math.h>
#include <stdint.h>

// ---------------- problem constants ----------------
#define BATCH 4
#define DM    192
#define DI    384
#define DS    16
#define DR    12
#define NSEQ  1024
#define LROWS 4096
#define NDIR  4
#define DBL_W 44

typedef __nv_bfloat16 bf16;

// ---------------- scratch ----------------
__device__ float g_xs  [LROWS*DM];            // fp32 residual
__device__ float g_dbl [NDIR*LROWS*DBL_W];    // fp32: feeds scan
__device__ float g_h3  [LROWS*DM];            // fp32: feeds ln2
__device__ float g_cb  [DM];

__device__ bf16 g_xs_h  [LROWS*DM];
__device__ bf16 g_xp_h  [LROWS*DM];
__device__ bf16 g_xz_h  [(long)NDIR*LROWS*2*DI];
__device__ bf16 g_xsm_h [NDIR*LROWS*DI];
__device__ bf16 g_y_h   [NDIR*LROWS*DI];
__device__ bf16 g_fused_h[LROWS*4*DM];
__device__ bf16 g_hdn_h [LROWS*2*DM];

// bf16 weights
__device__ bf16 g_w_in_h    [DM*DM];
__device__ bf16 g_w_inproj_h[NDIR*2*DI*DM];
__device__ bf16 g_w_xp_h    [NDIR*DBL_W*DI];
__device__ bf16 g_w_out_h   [NDIR*DM*DI];
__device__ bf16 g_w_f1_h    [2*DM*4*DM];
__device__ bf16 g_cw_h      [DM*2*DM];

// ---------------- helpers ----------------
__device__ __forceinline__ float apply_act(float v, int act) {
    if (act == 1) {
        v = (v > 20.f) ? v : log1pf(__expf(v));
    } else if (act == 2) {
        v = 0.5f * v * (1.f + erff(v * 0.70710678118654752f));
    }
    return v;
}

__device__ __forceinline__ int seq_src_n(int d, int t) {
    if (d == 0) return t;
    if (d == 1) return NSEQ - 1 - t;
    if (d == 2) return ((t & 31) << 5) + (t >> 5);
    int u = NSEQ - 1 - t;
    return ((u & 31) << 5) + (u >> 5);
}

__device__ __forceinline__ void mma_bf16(float4& c,
    uint32_t a0, uint32_t a1, uint32_t a2, uint32_t a3, uint32_t b0, uint32_t b1) {
    asm volatile(
        "mma.sync.aligned.m16n8k16.row.col.f32.bf16.bf16.f32 "
        "{%0,%1,%2,%3}, {%4,%5,%6,%7}, {%8,%9}, {%0,%1,%2,%3};\n"
        : "+f"(c.x), "+f"(c.y), "+f"(c.z), "+f"(c.w)
        : "r"(a0), "r"(a1), "r"(a2), "r"(a3), "r"(b0), "r"(b1));
}

__device__ __forceinline__ void ldsm_x4(uint32_t addr,
    uint32_t& r0, uint32_t& r1, uint32_t& r2, uint32_t& r3) {
    asm volatile("ldmatrix.sync.aligned.m8n8.x4.shared.b16 {%0,%1,%2,%3}, [%4];"
        : "=r"(r0), "=r"(r1), "=r"(r2), "=r"(r3) : "r"(addr));
}

__device__ __forceinline__ uint32_t pack_bf2(float lo, float hi) {
    __nv_bfloat162 p = __floats2bfloat162_rn(lo, hi);
    return *(uint32_t*)&p;
}

__device__ __forceinline__ void cp16(uint32_t saddr, const void* gptr, int src_bytes) {
    asm volatile("cp.async.cg.shared.global [%0], [%1], 16, %2;\n"
        :: "r"(saddr), "l"(gptr), "r"(src_bytes));
}
__device__ __forceinline__ void cp_commit() {
    asm volatile("cp.async.commit_group;\n");
}
__device__ __forceinline__ void cp_wait2() {
    asm volatile("cp.async.wait_group 2;\n");
}

// ---------------- weight conversion (fp32 -> bf16) ----------------
__global__ __launch_bounds__(256) void convert_w_kernel(
    const float* s0, const float* s1, const float* s2, const float* s3, const float* s4)
{
    const int n0 = DM*DM, n1 = NDIR*2*DI*DM, n2 = NDIR*DBL_W*DI, n3 = NDIR*DM*DI, n4 = 2*DM*4*DM;
    long i = (long)blockIdx.x * 256 + threadIdx.x;
    long off = 0;
    if (i < off + n0) { g_w_in_h[i - off] = __float2bfloat16(s0[i - off]); return; } off += n0;
    if (i < off + n1) { g_w_inproj_h[i - off] = __float2bfloat16(s1[i - off]); return; } off += n1;
    if (i < off + n2) { g_w_xp_h[i - off] = __float2bfloat16(s2[i - off]); return; } off += n2;
    if (i < off + n3) { g_w_out_h[i - off] = __float2bfloat16(s3[i - off]); return; } off += n3;
    if (i < off + n4) { g_w_f1_h[i - off] = __float2bfloat16(s4[i - off]); return; }
}

// ---------------- bf16 cp.async GEMM:  C = act(A @ W^T + bias) ----------------
// Block tile (MFRAG*32) x (NFRAG*32), BK=16, 4-stage cp.async pipeline, 256 threads
// (8 warps as 2x4; warp tile = MFRAG*16 rows x NFRAG*8 cols).
// Requirements: M % (MFRAG*32) == 0, K % 16 == 0, K >= 48, Nn even.
// mode: 0 plain, 1 gather A rows via seq_src_n(z,.), 2 scatter C rows via seq_src_n(z,.)
template<int MFRAG, int NFRAG>
__global__ __launch_bounds__(256) void gemm_bf16_kernel(
    const bf16* __restrict__ A, const bf16* __restrict__ W,
    const float* __restrict__ bias, void* __restrict__ Cv,
    int M, int Nn, int K, int lda, int ldc,
    long sA_, long sW_, long sB_, long sC_, int act, int mode, int cbf)
{
    constexpr int TM = MFRAG * 32;
    constexpr int TN = NFRAG * 32;
    constexpr int NST = 4;
    const int z = blockIdx.z;
    A += z * sA_; W += z * sW_;
    const float* bz = bias ? (bias + z * sB_) : (const float*)0;

    __shared__ __align__(16) bf16 sA[NST][TM][24];
    __shared__ __align__(16) bf16 sB[NST][TN][24];
    constexpr uint32_t A_ST = TM * 48;
    constexpr uint32_t B_ST = TN * 48;

    const int bm = blockIdx.y * TM, bn = blockIdx.x * TN;
    const int tid = threadIdx.x;

    // staging: 2 threads per row, 16B (8 bf16) each
    const int r     = tid >> 1;
    const int slice = tid & 1;
    const bool aactive = (r < TM);
    long arowi;
    if (mode == 1) {
        int gm = bm + (aactive ? r : 0);
        arowi = (long)(((gm >> 10) << 10) + seq_src_n(z, gm & 1023));
    } else {
        arowi = bm + (aactive ? r : 0);
    }
    const bf16* aPtr = A + arowi * lda + (slice << 3);
    const bool bactive = (r < TN);
    const int gw_n = bn + r;
    const bool wv = bactive && (gw_n < Nn);
    const bf16* wPtr = W + (wv ? (long)gw_n * K : 0) + (slice << 3);

    const uint32_t aDst0 = aactive ?
        (uint32_t)__cvta_generic_to_shared(&sA[0][r][slice << 3]) : 0u;
    const uint32_t bDst0 = bactive ?
        (uint32_t)__cvta_generic_to_shared(&sB[0][r][slice << 3]) : 0u;

    const int nkt = K >> 4;

    auto issue = [&](int kt) {
        const int s = kt & (NST - 1);
        if (aactive) cp16(aDst0 + s * A_ST, aPtr + (kt << 4), 16);
        if (bactive) cp16(bDst0 + s * B_ST, wPtr + (kt << 4), wv ? 16 : 0);
        cp_commit();
    };

    issue(0); issue(1); issue(2);

    float4 acc[MFRAG][NFRAG];
#pragma unroll
    for (int i = 0; i < MFRAG; i++)
#pragma unroll
        for (int j = 0; j < NFRAG; j++) acc[i][j] = make_float4(0.f, 0.f, 0.f, 0.f);

    const int lane = tid & 31, wid = tid >> 5;
    const int wm = wid >> 2, wn = wid & 3;

    const int a_row = wm * (MFRAG * 16) + (lane & 7) + (((lane >> 3) & 1) << 3);
    const int a_kc  = (lane >> 4) << 3;
    const uint32_t aAddr0 = (uint32_t)__cvta_generic_to_shared(&sA[0][a_row][a_kc]);
    const int b_row = wn * (NFRAG * 8) + (lane & 7) + ((lane >> 4) << 3);
    const int b_kc  = ((lane >> 3) & 1) << 3;
    const uint32_t bAddr0 = (uint32_t)__cvta_generic_to_shared(&sB[0][b_row][b_kc]);

    for (int kt = 0; kt < nkt; kt++) {
        cp_wait2();
        __syncthreads();
        if (kt + NST - 1 < nkt) issue(kt + NST - 1);

        const int s = kt & (NST - 1);
        const uint32_t aA = aAddr0 + s * A_ST;
        const uint32_t bA = bAddr0 + s * B_ST;
        uint32_t ra[MFRAG][4];
#pragma unroll
        for (int i = 0; i < MFRAG; i++)
            ldsm_x4(aA + i * (16 * 48), ra[i][0], ra[i][1], ra[i][2], ra[i][3]);
        uint32_t rb[NFRAG][2];
#pragma unroll
        for (int jp = 0; jp < NFRAG / 2; jp++) {
            uint32_t b0, b1, b2, b3;
            ldsm_x4(bA + jp * (16 * 48), b0, b1, b2, b3);
            rb[2 * jp][0] = b0; rb[2 * jp][1] = b1;
            rb[2 * jp + 1][0] = b2; rb[2 * jp + 1][1] = b3;
        }
#pragma unroll
        for (int i = 0; i < MFRAG; i++)
#pragma unroll
            for (int j = 0; j < NFRAG; j++)
                mma_bf16(acc[i][j], ra[i][0], ra[i][1], ra[i][2], ra[i][3],
                         rb[j][0], rb[j][1]);
    }

    // ---- epilogue ----
    const int row0 = lane >> 2;
    const int col0 = (lane & 3) << 1;
    float* Cf = (float*)Cv + z * sC_;
    bf16*  Ch = (bf16*)Cv + z * sC_;
#pragma unroll
    for (int i = 0; i < MFRAG; i++) {
        const int gmA = bm + wm * (MFRAG * 16) + (i << 4) + row0;
        const int gmB = gmA + 8;
        long rA, rB;
        if (mode == 2) {
            rA = ((gmA >> 10) << 10) + seq_src_n(z, gmA & 1023);
            rB = ((gmB >> 10) << 10) + seq_src_n(z, gmB & 1023);
        } else { rA = gmA; rB = gmB; }
#pragma unroll
        for (int j = 0; j < NFRAG; j++) {
            const int gn = bn + wn * (NFRAG * 8) + (j << 3) + col0;
            if (gn < Nn) {
                float4 v = acc[i][j];
                if (bz) {
                    const float b0 = bz[gn], b1 = bz[gn + 1];
                    v.x += b0; v.y += b1; v.z += b0; v.w += b1;
                }
                if (act) {
                    v.x = apply_act(v.x, act); v.y = apply_act(v.y, act);
                    v.z = apply_act(v.z, act); v.w = apply_act(v.w, act);
                }
                if (cbf) {
                    *(uint32_t*)&Ch[rA * (long)ldc + gn] = pack_bf2(v.x, v.y);
                    *(uint32_t*)&Ch[rB * (long)ldc + gn] = pack_bf2(v.z, v.w);
                } else {
                    *(float2*)&Cf[rA * (long)ldc + gn] = make_float2(v.x, v.y);
                    *(float2*)&Cf[rB * (long)ldc + gn] = make_float2(v.z, v.w);
                }
            }
        }
    }
}

// ---------------- kernel 1: transpose + layernorm ----------------
__global__ __launch_bounds__(256) void ln1_kernel(
    const float* __restrict__ x, const float* __restrict__ g, const float* __restrict__ bb)
{
    __shared__ float tile[DM][33];
    __shared__ float s_mean[32], s_rstd[32];
    const int b = blockIdx.y, n0 = blockIdx.x << 5;
    const int tid = threadIdx.x;

    for (int i = tid; i < DM * 32; i += 256) {
        int d = i >> 5, nn = i & 31;
        tile[d][nn] = x[((long)(b * DM + d) << 10) + n0 + nn];
    }
    __syncthreads();

    const int nn = tid >> 3, l = tid & 7;
    float s = 0.f, s2 = 0.f;
    for (int d = l; d < DM; d += 8) { float v = tile[d][nn]; s += v; s2 = fmaf(v, v, s2); }
    s  += __shfl_down_sync(0xffffffffu, s,  4, 8);
    s2 += __shfl_down_sync(0xffffffffu, s2, 4, 8);
    s  += __shfl_down_sync(0xffffffffu, s,  2, 8);
    s2 += __shfl_down_sync(0xffffffffu, s2, 2, 8);
    s  += __shfl_down_sync(0xffffffffu, s,  1, 8);
    s2 += __shfl_down_sync(0xffffffffu, s2, 1, 8);
    if (l == 0) {
        float m = s * (1.f / DM);
        float var = s2 * (1.f / DM) - m * m;
        s_mean[nn] = m;
        s_rstd[nn] = rsqrtf(var + 1e-5f);
    }
    __syncthreads();

    for (int i = tid; i < DM * 32; i += 256) {
        int nn2 = i / DM, d = i % DM;
        float v = (tile[d][nn2] - s_mean[nn2]) * s_rstd[nn2] * g[d] + bb[d];
        long adr = ((long)(b << 10) + n0 + nn2) * DM + d;
        g_xs[adr] = v;
        g_xs_h[adr] = __float2bfloat16(v);
    }
}

// ---------------- causal depthwise conv (width 4) + silu ----------------
__global__ __launch_bounds__(256) void conv_silu_kernel(
    const float* __restrict__ cw, const float* __restrict__ cb)
{
    const int gi = blockIdx.x * 256 + threadIdx.x;
    const int c = gi % DI;
    const int rest = gi / DI;
    const int tb = rest & 63;
    const int db = rest >> 6;
    const int d = db >> 2;
    const int t0 = tb << 4;

    const float* w = cw + ((long)d * DI + c) * 4;
    const float w0 = w[0], w1 = w[1], w2 = w[2], w3 = w[3];
    const float bias = cb[d * DI + c];
    const bf16* src = g_xz_h + ((long)db * NSEQ) * (2 * DI) + c;
    bf16* dst = g_xsm_h + ((long)db * NSEQ) * DI + c;

    float r0 = (t0 >= 3) ? __bfloat162float(src[(long)(t0 - 3) * (2 * DI)]) : 0.f;
    float r1 = (t0 >= 2) ? __bfloat162float(src[(long)(t0 - 2) * (2 * DI)]) : 0.f;
    float r2 = (t0 >= 1) ? __bfloat162float(src[(long)(t0 - 1) * (2 * DI)]) : 0.f;
#pragma unroll
    for (int i = 0; i < 16; i++) {
        const int t = t0 + i;
        const float cur = __bfloat162float(src[(long)t * (2 * DI)]);
        float a = bias;
        a = fmaf(w0, r0, a);
        a = fmaf(w1, r1, a);
        a = fmaf(w2, r2, a);
        a = fmaf(w3, cur, a);
        dst[(long)t * DI] = __float2bfloat16(a / (1.f + __expf(-a)));
        r0 = r1; r1 = r2; r2 = cur;
    }
}

// ---------------- selective scan with fused dt-projection ----------------
#define SCH 16
__global__ __launch_bounds__(128) void scan_kernel(
    const float* __restrict__ Alog, const float* __restrict__ Dp,
    const float* __restrict__ Wdt, const float* __restrict__ bdt)
{
    const int d = blockIdx.z, b = blockIdx.y;
    const int c0 = blockIdx.x << 5;
    const int tid = threadIdx.x;
    const int cl = tid >> 2;
    const int sg = tid & 3;
    const int c = c0 + cl;
    const long baseI = ((long)d * BATCH + b) * NSEQ;

    const bf16* xb   = g_xsm_h + baseI * DI       + c0;
    const bf16* zb   = g_xz_h  + baseI * (2 * DI) + DI + c0;
    const float* dblp = g_dbl + baseI * DBL_W;
    bf16* yb          = g_y_h + baseI * DI        + c0;

    __shared__ float s_wdt[32 * 13];
    __shared__ float s_bdt[32];
    __shared__ float s_raw[SCH * 12];
    __shared__ float s_bc [SCH * 32];
    __shared__ float s_dt [SCH * 32];
    __shared__ float s_x  [SCH * 32];
    __shared__ float s_g  [SCH * 32];     // precomputed silu(z) gate

    for (int i = tid; i < 32 * DR; i += 128)
        s_wdt[(i / DR) * 13 + (i % DR)] = Wdt[((long)(d * DI + c0) + i / DR) * DR + (i % DR)];
    if (tid < 32) s_bdt[tid] = bdt[d * DI + c0 + tid];

    float Aa[4];
#pragma unroll
    for (int s = 0; s < 4; s++)
        Aa[s] = -expf(Alog[((long)(d * DI + c)) * DS + (sg << 2) + s]);
    const float Dv = Dp[d * DI + c];

    float h[4];
#pragma unroll
    for (int s = 0; s < 4; s++) h[s] = 0.f;

    __syncthreads();

    for (int t0 = 0; t0 < NSEQ; t0 += SCH) {
        __syncthreads();
        for (int i = tid; i < SCH * DR; i += 128)
            s_raw[i] = dblp[(long)(t0 + i / DR) * DBL_W + (i % DR)];
#pragma unroll
        for (int k = 0; k < 4; k++) {
            const int idx = tid + (k << 7);
            const int row = idx >> 5, col = idx & 31;
            s_bc[idx] = dblp[(long)(t0 + row) * DBL_W + DR + col];
            s_x [idx] = __bfloat162float(xb[(long)(t0 + row) * DI + col]);
            const float zv = __bfloat162float(zb[(long)(t0 + row) * (2 * DI) + col]);
            s_g [idx] = zv / (1.f + __expf(-zv));
        }
        __syncthreads();
#pragma unroll
        for (int k = 0; k < 4; k++) {
            const int idx = tid + (k << 7);
            const int row = idx >> 5, col = idx & 31;
            float v = s_bdt[col];
#pragma unroll
            for (int j = 0; j < DR; j++)
                v = fmaf(s_raw[row * DR + j], s_wdt[col * 13 + j], v);
            s_dt[idx] = (v > 20.f) ? v : log1pf(__expf(v));
        }
        __syncthreads();

#pragma unroll
        for (int tt = 0; tt < SCH; tt++) {
            const float dt_v = s_dt[(tt << 5) + cl];
            const float x_v  = s_x [(tt << 5) + cl];
            const float* bc = s_bc + (tt << 5);
            const float dtx = dt_v * x_v;
            float accv = 0.f;
#pragma unroll
            for (int s = 0; s < 4; s++) {
                const float dA = __expf(dt_v * Aa[s]);
                h[s] = fmaf(dA, h[s], dtx * bc[(sg << 2) + s]);
                accv = fmaf(h[s], bc[16 + (sg << 2) + s], accv);
            }
            accv += __shfl_down_sync(0xffffffffu, accv, 2, 4);
            accv += __shfl_down_sync(0xffffffffu, accv, 1, 4);
            if (sg == 0) {
                float yv = fmaf(x_v, Dv, accv);
                yv *= s_g[(tt << 5) + cl];
                yb[(long)(t0 + tt) * DI + cl] = __float2bfloat16(yv);
            }
        }
    }
}

// ---------------- combine o_proj into ffn2 (bf16 weight out) ----------------
__global__ __launch_bounds__(256) void combine_w_kernel(
    const float* __restrict__ o_w, const float* __restrict__ o_b,
    const float* __restrict__ f_w2, const float* __restrict__ f_b2)
{
    const int i = blockIdx.x;
    __shared__ float s_ow[DM];
    __shared__ float red[256];
    for (int j = threadIdx.x; j < DM; j += 256) s_ow[j] = o_w[i * DM + j];
    __syncthreads();

    for (int k = threadIdx.x; k < 2 * DM; k += 256) {
        float acc = 0.f;
        for (int j = 0; j < DM; j++)
            acc = fmaf(s_ow[j], f_w2[j * (2 * DM) + k], acc);
        g_cw_h[i * (2 * DM) + k] = __float2bfloat16(acc);
    }
    float pb = 0.f;
    for (int j = threadIdx.x; j < DM; j += 256) pb = fmaf(s_ow[j], f_b2[j], pb);
    red[threadIdx.x] = pb;
    __syncthreads();
    for (int st = 128; st > 0; st >>= 1) {
        if (threadIdx.x < st) red[threadIdx.x] += red[threadIdx.x + st];
        __syncthreads();
    }
    if (threadIdx.x == 0) g_cb[i] = red[0] + o_b[i];
}

// ---------------- final layernorm + residual + transpose-out ----------------
__global__ __launch_bounds__(256) void ln2_kernel(
    const float* __restrict__ g, const float* __restrict__ bb, float* __restrict__ out)
{
    __shared__ float t1[16][193];
    __shared__ float t2[16][193];
    __shared__ float s_mean[16], s_rstd[16];
    const int b = blockIdx.y, n0 = blockIdx.x << 4;
    const int tid = threadIdx.x;

    for (int i = tid; i < 16 * DM; i += 256) {
        int nn = i / DM, dd = i % DM;
        long adr = ((long)(b << 10) + n0 + nn) * DM + dd;
        t1[nn][dd] = g_h3[adr];
        t2[nn][dd] = g_xs[adr];
    }
    __syncthreads();

    const int nn = tid >> 4, l = tid & 15;
    float s = 0.f, s2 = 0.f;
    for (int dd = l; dd < DM; dd += 16) { float v = t1[nn][dd]; s += v; s2 = fmaf(v, v, s2); }
    s  += __shfl_down_sync(0xffffffffu, s,  8, 16);
    s2 += __shfl_down_sync(0xffffffffu, s2, 8, 16);
    s  += __shfl_down_sync(0xffffffffu, s,  4, 16);
    s2 += __shfl_down_sync(0xffffffffu, s2, 4, 16);
    s  += __shfl_down_sync(0xffffffffu, s,  2, 16);
    s2 += __shfl_down_sync(0xffffffffu, s2, 2, 16);
    s  += __shfl_down_sync(0xffffffffu, s,  1, 16);
    s2 += __shfl_down_sync(0xffffffffu, s2, 1, 16);
    if (l == 0) {
        float m = s * (1.f / DM);
        float var = s2 * (1.f / DM) - m * m;
        s_mean[nn] = m;
        s_rstd[nn] = rsqrtf(var + 1e-5f);
    }
    __syncthreads();

    for (int i = tid; i < DM * 16; i += 256) {
        int dd = i >> 4, nn2 = i & 15;
        float v = (t1[nn2][dd] - s_mean[nn2]) * s_rstd[nn2] * g[dd] + bb[dd] + t2[nn2][dd];
        out[((long)(b * DM + dd) << 10) + n0 + nn2] = v;
    }
}

// ---------------- launcher ----------------
extern "C" void kernel_launch(void* const* d_in, const int* in_sizes, int n_in,
                              void* d_out, int out_size)
{
    const float* x        = (const float*)d_in[0];
    const float* norm_g   = (const float*)d_in[1];
    const float* norm_b   = (const float*)d_in[2];
    const float* in_w     = (const float*)d_in[3];
    const float* in_b     = (const float*)d_in[4];
    const float* m_in_w   = (const float*)d_in[5];
    const float* m_conv_w = (const float*)d_in[6];
    const float* m_conv_b = (const float*)d_in[7];
    const float* m_xp_w   = (const float*)d_in[8];
    const float* m_dt_w   = (const float*)d_in[9];
    const float* m_dt_b   = (const float*)d_in[10];
    const float* m_Alog   = (const float*)d_in[11];
    const float* m_D      = (const float*)d_in[12];
    const float* m_out_w  = (const float*)d_in[13];
    const float* f_w1     = (const float*)d_in[14];
    const float* f_b1     = (const float*)d_in[15];
    const float* f_w2     = (const float*)d_in[16];
    const float* f_b2     = (const float*)d_in[17];
    const float* o_w      = (const float*)d_in[18];
    const float* o_b      = (const float*)d_in[19];
    const float* on_g     = (const float*)d_in[20];
    const float* on_b     = (const float*)d_in[21];
    float* out = (float*)d_out;

    float *p_dbl, *p_h3, *p_cb;
    bf16 *p_xs_h, *p_xp_h, *p_xz_h, *p_xsm_h, *p_y_h, *p_fused_h, *p_hdn_h;
    bf16 *p_w_in, *p_w_inproj, *p_w_xp, *p_w_out, *p_w_f1, *p_cw_h;
    cudaGetSymbolAddress((void**)&p_dbl, g_dbl);
    cudaGetSymbolAddress((void**)&p_h3, g_h3);
    cudaGetSymbolAddress((void**)&p_cb, g_cb);
    cudaGetSymbolAddress((void**)&p_xs_h, g_xs_h);
    cudaGetSymbolAddress((void**)&p_xp_h, g_xp_h);
    cudaGetSymbolAddress((void**)&p_xz_h, g_xz_h);
    cudaGetSymbolAddress((void**)&p_xsm_h, g_xsm_h);
    cudaGetSymbolAddress((void**)&p_y_h, g_y_h);
    cudaGetSymbolAddress((void**)&p_fused_h, g_fused_h);
    cudaGetSymbolAddress((void**)&p_hdn_h, g_hdn_h);
    cudaGetSymbolAddress((void**)&p_w_in, g_w_in_h);
    cudaGetSymbolAddress((void**)&p_w_inproj, g_w_inproj_h);
    cudaGetSymbolAddress((void**)&p_w_xp, g_w_xp_h);
    cudaGetSymbolAddress((void**)&p_w_out, g_w_out_h);
    cudaGetSymbolAddress((void**)&p_w_f1, g_w_f1_h);
    cudaGetSymbolAddress((void**)&p_cw_h, g_cw_h);

    const int n_w = DM*DM + NDIR*2*DI*DM + NDIR*DBL_W*DI + NDIR*DM*DI + 2*DM*4*DM;

    // 1) weight conversion
    convert_w_kernel<<<(n_w + 255) / 256, 256>>>(in_w, m_in_w, m_xp_w, m_out_w, f_w1);

    // 2) layernorm + transpose
    ln1_kernel<<<dim3(32, 4), 256>>>(x, norm_g, norm_b);

    // 3) xp = xs @ in_w^T + in_b  (64-row tiles -> 192 blocks)
    gemm_bf16_kernel<2, 2><<<dim3(3, 64, 1), 256>>>(p_xs_h, p_w_in, in_b, p_xp_h,
        LROWS, DM, DM, DM, DM, 0, 0, 0, 0, 0, 0, 1);

    // 4) xz[d] = gather_d(xp) @ m_in_w[d]^T  (128x128 tiles, 768 blocks)
    gemm_bf16_kernel<4, 4><<<dim3(6, 32, 4), 256>>>(p_xp_h, p_w_inproj, nullptr, p_xz_h,
        LROWS, 2 * DI, DM, DM, 2 * DI,
        0, (long)2 * DI * DM, 0, (long)LROWS * 2 * DI, 0, 1, 1);

    // 5) causal depthwise conv + silu
    conv_silu_kernel<<<1536, 256>>>(m_conv_w, m_conv_b);

    // 6) dbl[d] = xsm[d] @ m_xp_w[d]^T  (64-row tiles -> 256 blocks)
    gemm_bf16_kernel<2, 2><<<dim3(1, 64, 4), 256>>>(p_xsm_h, p_w_xp, nullptr, p_dbl,
        LROWS, DBL_W, DI, DI, DBL_W,
        (long)LROWS * DI, (long)DBL_W * DI, 0, (long)LROWS * DBL_W, 0, 0, 0);

    // 7) selective scan
    scan_kernel<<<dim3(12, BATCH, NDIR), 128>>>(m_Alog, m_D, m_dt_w, m_dt_b);

    // 8) fused[:, d*DM:(d+1)*DM] = scatter_d(y[d] @ m_out_w[d]^T)  (768 blocks)
    gemm_bf16_kernel<2, 2><<<dim3(3, 64, 4), 256>>>(p_y_h, p_w_out, nullptr, p_fused_h,
        LROWS, DM, DI, DI, 4 * DM,
        (long)LROWS * DI, (long)DM * DI, 0, (long)DM, 0, 2, 1);

    // 9) hdn = gelu(fused @ f_w1^T + f_b1)  (64-row tiles -> 384 blocks)
    gemm_bf16_kernel<2, 2><<<dim3(6, 64, 1), 256>>>(p_fused_h, p_w_f1, f_b1, p_hdn_h,
        LROWS, 2 * DM, 4 * DM, 4 * DM, 2 * DM, 0, 0, 0, 0, 2, 0, 1);

    // 10) combined weight: Wc = o_w @ f_w2 (bf16), bc = o_w @ f_b2 + o_b
    combine_w_kernel<<<DM, 256>>>(o_w, o_b, f_w2, f_b2);

    // 11) h3 = hdn @ Wc^T + bc  (64-row tiles -> 192 blocks)
    gemm_bf16_kernel<2, 2><<<dim3(3, 64, 1), 256>>>(p_hdn_h, p_cw_h, p_cb, p_h3,
        LROWS, DM, 2 * DM, 2 * DM, DM, 0, 0, 0, 0, 0, 0, 0);

    // 12) final layernorm + residual + transpose out
    ln2_kernel<<<dim3(64, 4), 256>>>(on_g, on_b, out);
}

// round 9
// speedup vs baseline: 2.9552x; 1.0940x over previous
#include <cuda_runtime.h>
#include <cuda_bf16.h>
#include <math.h>
#include <stdint.h>

// ---------------- problem constants ----------------
#define BATCH 4
#define DM    192
#define DI    384
#define DS    16
#define DR    12
#define NSEQ  1024
#define LROWS 4096
#define NDIR  4
#define DBL_W 44

typedef __nv_bfloat16 bf16;

// ---------------- scratch ----------------
__device__ float g_xs  [LROWS*DM];
__device__ float g_dbl [NDIR*LROWS*DBL_W];
__device__ float g_h3  [LROWS*DM];
__device__ float g_cb  [DM];

__device__ bf16 g_xs_h  [LROWS*DM];
__device__ bf16 g_xp_h  [LROWS*DM];
__device__ bf16 g_xz_h  [(long)NDIR*LROWS*2*DI];
__device__ bf16 g_xsm_h [NDIR*LROWS*DI];
__device__ bf16 g_y_h   [NDIR*LROWS*DI];
__device__ bf16 g_fused_h[LROWS*4*DM];
__device__ bf16 g_hdn_h [LROWS*2*DM];

__device__ bf16 g_w_in_h    [DM*DM];
__device__ bf16 g_w_inproj_h[NDIR*2*DI*DM];
__device__ bf16 g_w_xp_h    [NDIR*DBL_W*DI];
__device__ bf16 g_w_out_h   [NDIR*DM*DI];
__device__ bf16 g_w_f1_h    [2*DM*4*DM];
__device__ bf16 g_cw_h      [DM*2*DM];

// ---------------- helpers ----------------
__device__ __forceinline__ float apply_act(float v, int act) {
    if (act == 1) {
        v = (v > 20.f) ? v : log1pf(__expf(v));
    } else if (act == 2) {
        v = 0.5f * v * (1.f + erff(v * 0.70710678118654752f));
    }
    return v;
}

__device__ __forceinline__ int seq_src_n(int d, int t) {
    if (d == 0) return t;
    if (d == 1) return NSEQ - 1 - t;
    if (d == 2) return ((t & 31) << 5) + (t >> 5);
    int u = NSEQ - 1 - t;
    return ((u & 31) << 5) + (u >> 5);
}

__device__ __forceinline__ void mma_bf16(float4& c,
    uint32_t a0, uint32_t a1, uint32_t a2, uint32_t a3, uint32_t b0, uint32_t b1) {
    asm volatile(
        "mma.sync.aligned.m16n8k16.row.col.f32.bf16.bf16.f32 "
        "{%0,%1,%2,%3}, {%4,%5,%6,%7}, {%8,%9}, {%0,%1,%2,%3};\n"
        : "+f"(c.x), "+f"(c.y), "+f"(c.z), "+f"(c.w)
        : "r"(a0), "r"(a1), "r"(a2), "r"(a3), "r"(b0), "r"(b1));
}

__device__ __forceinline__ void ldsm_x4(uint32_t addr,
    uint32_t& r0, uint32_t& r1, uint32_t& r2, uint32_t& r3) {
    asm volatile("ldmatrix.sync.aligned.m8n8.x4.shared.b16 {%0,%1,%2,%3}, [%4];"
        : "=r"(r0), "=r"(r1), "=r"(r2), "=r"(r3) : "r"(addr));
}

__device__ __forceinline__ uint32_t pack_bf2(float lo, float hi) {
    __nv_bfloat162 p = __floats2bfloat162_rn(lo, hi);
    return *(uint32_t*)&p;
}

__device__ __forceinline__ void cp16(uint32_t saddr, const void* gptr, int src_bytes) {
    asm volatile("cp.async.cg.shared.global [%0], [%1], 16, %2;\n"
        :: "r"(saddr), "l"(gptr), "r"(src_bytes));
}
__device__ __forceinline__ void cp_commit() {
    asm volatile("cp.async.commit_group;\n");
}
__device__ __forceinline__ void cp_wait2() {
    asm volatile("cp.async.wait_group 2;\n");
}

// ---------------- weight conversion (fp32 -> bf16) ----------------
__global__ __launch_bounds__(256) void convert_w_kernel(
    const float* s0, const float* s1, const float* s2, const float* s3, const float* s4)
{
    const int n0 = DM*DM, n1 = NDIR*2*DI*DM, n2 = NDIR*DBL_W*DI, n3 = NDIR*DM*DI, n4 = 2*DM*4*DM;
    long i = (long)blockIdx.x * 256 + threadIdx.x;
    long off = 0;
    if (i < off + n0) { g_w_in_h[i - off] = __float2bfloat16(s0[i - off]); return; } off += n0;
    if (i < off + n1) { g_w_inproj_h[i - off] = __float2bfloat16(s1[i - off]); return; } off += n1;
    if (i < off + n2) { g_w_xp_h[i - off] = __float2bfloat16(s2[i - off]); return; } off += n2;
    if (i < off + n3) { g_w_out_h[i - off] = __float2bfloat16(s3[i - off]); return; } off += n3;
    if (i < off + n4) { g_w_f1_h[i - off] = __float2bfloat16(s4[i - off]); return; }
}

// ---------------- bf16 cp.async GEMM, BK=32 stages ----------------
// Block tile (MFRAG*32) x (NFRAG*32), BK=32 (2 k16 sub-steps per stage),
// 4-stage cp.async pipeline, 256 threads (8 warps as 2x4).
// Requirements: M % (MFRAG*32) == 0, K % 32 == 0, K >= 128 ok (nkt>=3), Nn even.
// mode: 0 plain, 1 gather A rows via seq_src_n(z,.), 2 scatter C rows via seq_src_n(z,.)
template<int MFRAG, int NFRAG>
__global__ __launch_bounds__(256) void gemm_bf16_kernel(
    const bf16* __restrict__ A, const bf16* __restrict__ W,
    const float* __restrict__ bias, void* __restrict__ Cv,
    int M, int Nn, int K, int lda, int ldc,
    long sA_, long sW_, long sB_, long sC_, int act, int mode, int cbf)
{
    constexpr int TM = MFRAG * 32;
    constexpr int TN = NFRAG * 32;
    constexpr int NST = 4;
    constexpr int PITCH = 40;                 // 32 k + 8 pad (elements)
    const int z = blockIdx.z;
    A += z * sA_; W += z * sW_;
    const float* bz = bias ? (bias + z * sB_) : (const float*)0;

    __shared__ __align__(16) bf16 sA[NST][TM][PITCH];
    __shared__ __align__(16) bf16 sB[NST][TN][PITCH];
    constexpr uint32_t A_ST = TM * PITCH * 2;
    constexpr uint32_t B_ST = TN * PITCH * 2;

    const int bm = blockIdx.y * TM, bn = blockIdx.x * TN;
    const int tid = threadIdx.x;

    // ---- staging geometry: thread covers (64/tpr) bytes of one row per stage ----
    constexpr int TPR_A = 256 / TM;           // threads per A row (2 or 4)
    constexpr int NCP_A = 4 / TPR_A;          // cp16 per thread for A (2 or 1)
    constexpr int TPR_B = 256 / TN;
    constexpr int NCP_B = 4 / TPR_B;

    const int rA = tid / TPR_A;               // A row
    const int kA = (tid % TPR_A) * (NCP_A * 8); // element offset within 32-wide k
    long arowi;
    if (mode == 1) {
        int gm = bm + rA;
        arowi = (long)(((gm >> 10) << 10) + seq_src_n(z, gm & 1023));
    } else {
        arowi = bm + rA;
    }
    const bf16* aPtr = A + arowi * lda + kA;
    const int rB = tid / TPR_B;
    const int kB = (tid % TPR_B) * (NCP_B * 8);
    const int gw_n = bn + rB;
    const bool wv = (gw_n < Nn);
    const bf16* wPtr = W + (wv ? (long)gw_n * K : 0) + kB;

    const uint32_t aDst0 = (uint32_t)__cvta_generic_to_shared(&sA[0][rA][kA]);
    const uint32_t bDst0 = (uint32_t)__cvta_generic_to_shared(&sB[0][rB][kB]);

    const int nkt = K >> 5;

    auto issue = [&](int kt) {
        const int s = kt & (NST - 1);
#pragma unroll
        for (int q = 0; q < NCP_A; q++)
            cp16(aDst0 + s * A_ST + q * 16, aPtr + (kt << 5) + q * 8, 16);
#pragma unroll
        for (int q = 0; q < NCP_B; q++)
            cp16(bDst0 + s * B_ST + q * 16, wPtr + (kt << 5) + q * 8, wv ? 16 : 0);
        cp_commit();
    };

    issue(0); issue(1); issue(2);

    float4 acc[MFRAG][NFRAG];
#pragma unroll
    for (int i = 0; i < MFRAG; i++)
#pragma unroll
        for (int j = 0; j < NFRAG; j++) acc[i][j] = make_float4(0.f, 0.f, 0.f, 0.f);

    const int lane = tid & 31, wid = tid >> 5;
    const int wm = wid >> 2, wn = wid & 3;

    const int a_row = wm * (MFRAG * 16) + (lane & 7) + (((lane >> 3) & 1) << 3);
    const int a_kc  = (lane >> 4) << 3;
    const uint32_t aAddr0 = (uint32_t)__cvta_generic_to_shared(&sA[0][a_row][a_kc]);
    const int b_row = wn * (NFRAG * 8) + (lane & 7) + ((lane >> 4) << 3);
    const int b_kc  = ((lane >> 3) & 1) << 3;
    const uint32_t bAddr0 = (uint32_t)__cvta_generic_to_shared(&sB[0][b_row][b_kc]);

    for (int kt = 0; kt < nkt; kt++) {
        cp_wait2();
        __syncthreads();
        if (kt + NST - 1 < nkt) issue(kt + NST - 1);

        const int s = kt & (NST - 1);
#pragma unroll
        for (int s2 = 0; s2 < 2; s2++) {
            const uint32_t aA = aAddr0 + s * A_ST + s2 * 32;
            const uint32_t bA = bAddr0 + s * B_ST + s2 * 32;
            uint32_t ra[MFRAG][4];
#pragma unroll
            for (int i = 0; i < MFRAG; i++)
                ldsm_x4(aA + i * (16 * PITCH * 2), ra[i][0], ra[i][1], ra[i][2], ra[i][3]);
            uint32_t rb[NFRAG][2];
#pragma unroll
            for (int jp = 0; jp < NFRAG / 2; jp++) {
                uint32_t b0, b1, b2, b3;
                ldsm_x4(bA + jp * (16 * PITCH * 2), b0, b1, b2, b3);
                rb[2 * jp][0] = b0; rb[2 * jp][1] = b1;
                rb[2 * jp + 1][0] = b2; rb[2 * jp + 1][1] = b3;
            }
#pragma unroll
            for (int i = 0; i < MFRAG; i++)
#pragma unroll
                for (int j = 0; j < NFRAG; j++)
                    mma_bf16(acc[i][j], ra[i][0], ra[i][1], ra[i][2], ra[i][3],
                             rb[j][0], rb[j][1]);
        }
    }

    // ---- epilogue ----
    const int row0 = lane >> 2;
    const int col0 = (lane & 3) << 1;
    float* Cf = (float*)Cv + z * sC_;
    bf16*  Ch = (bf16*)Cv + z * sC_;
#pragma unroll
    for (int i = 0; i < MFRAG; i++) {
        const int gmA = bm + wm * (MFRAG * 16) + (i << 4) + row0;
        const int gmB = gmA + 8;
        long rAo, rBo;
        if (mode == 2) {
            rAo = ((gmA >> 10) << 10) + seq_src_n(z, gmA & 1023);
            rBo = ((gmB >> 10) << 10) + seq_src_n(z, gmB & 1023);
        } else { rAo = gmA; rBo = gmB; }
#pragma unroll
        for (int j = 0; j < NFRAG; j++) {
            const int gn = bn + wn * (NFRAG * 8) + (j << 3) + col0;
            if (gn < Nn) {
                float4 v = acc[i][j];
                if (bz) {
                    const float b0 = bz[gn], b1 = bz[gn + 1];
                    v.x += b0; v.y += b1; v.z += b0; v.w += b1;
                }
                if (act) {
                    v.x = apply_act(v.x, act); v.y = apply_act(v.y, act);
                    v.z = apply_act(v.z, act); v.w = apply_act(v.w, act);
                }
                if (cbf) {
                    *(uint32_t*)&Ch[rAo * (long)ldc + gn] = pack_bf2(v.x, v.y);
                    *(uint32_t*)&Ch[rBo * (long)ldc + gn] = pack_bf2(v.z, v.w);
                } else {
                    *(float2*)&Cf[rAo * (long)ldc + gn] = make_float2(v.x, v.y);
                    *(float2*)&Cf[rBo * (long)ldc + gn] = make_float2(v.z, v.w);
                }
            }
        }
    }
}

// ---------------- kernel 1: transpose + layernorm ----------------
__global__ __launch_bounds__(256) void ln1_kernel(
    const float* __restrict__ x, const float* __restrict__ g, const float* __restrict__ bb)
{
    __shared__ float tile[DM][33];
    __shared__ float s_mean[32], s_rstd[32];
    const int b = blockIdx.y, n0 = blockIdx.x << 5;
    const int tid = threadIdx.x;

    for (int i = tid; i < DM * 32; i += 256) {
        int d = i >> 5, nn = i & 31;
        tile[d][nn] = x[((long)(b * DM + d) << 10) + n0 + nn];
    }
    __syncthreads();

    const int nn = tid >> 3, l = tid & 7;
    float s = 0.f, s2 = 0.f;
    for (int d = l; d < DM; d += 8) { float v = tile[d][nn]; s += v; s2 = fmaf(v, v, s2); }
    s  += __shfl_down_sync(0xffffffffu, s,  4, 8);
    s2 += __shfl_down_sync(0xffffffffu, s2, 4, 8);
    s  += __shfl_down_sync(0xffffffffu, s,  2, 8);
    s2 += __shfl_down_sync(0xffffffffu, s2, 2, 8);
    s  += __shfl_down_sync(0xffffffffu, s,  1, 8);
    s2 += __shfl_down_sync(0xffffffffu, s2, 1, 8);
    if (l == 0) {
        float m = s * (1.f / DM);
        float var = s2 * (1.f / DM) - m * m;
        s_mean[nn] = m;
        s_rstd[nn] = rsqrtf(var + 1e-5f);
    }
    __syncthreads();

    for (int i = tid; i < DM * 32; i += 256) {
        int nn2 = i / DM, d = i % DM;
        float v = (tile[d][nn2] - s_mean[nn2]) * s_rstd[nn2] * g[d] + bb[d];
        long adr = ((long)(b << 10) + n0 + nn2) * DM + d;
        g_xs[adr] = v;
        g_xs_h[adr] = __float2bfloat16(v);
    }
}

// ---------------- causal depthwise conv (width 4) + silu ----------------
__global__ __launch_bounds__(256) void conv_silu_kernel(
    const float* __restrict__ cw, const float* __restrict__ cb)
{
    const int gi = blockIdx.x * 256 + threadIdx.x;
    const int c = gi % DI;
    const int rest = gi / DI;
    const int tb = rest & 63;
    const int db = rest >> 6;
    const int d = db >> 2;
    const int t0 = tb << 4;

    const float* w = cw + ((long)d * DI + c) * 4;
    const float w0 = w[0], w1 = w[1], w2 = w[2], w3 = w[3];
    const float bias = cb[d * DI + c];
    const bf16* src = g_xz_h + ((long)db * NSEQ) * (2 * DI) + c;
    bf16* dst = g_xsm_h + ((long)db * NSEQ) * DI + c;

    float r0 = (t0 >= 3) ? __bfloat162float(src[(long)(t0 - 3) * (2 * DI)]) : 0.f;
    float r1 = (t0 >= 2) ? __bfloat162float(src[(long)(t0 - 2) * (2 * DI)]) : 0.f;
    float r2 = (t0 >= 1) ? __bfloat162float(src[(long)(t0 - 1) * (2 * DI)]) : 0.f;
#pragma unroll
    for (int i = 0; i < 16; i++) {
        const int t = t0 + i;
        const float cur = __bfloat162float(src[(long)t * (2 * DI)]);
        float a = bias;
        a = fmaf(w0, r0, a);
        a = fmaf(w1, r1, a);
        a = fmaf(w2, r2, a);
        a = fmaf(w3, cur, a);
        dst[(long)t * DI] = __float2bfloat16(a / (1.f + __expf(-a)));
        r0 = r1; r1 = r2; r2 = cur;
    }
}

// ---------------- selective scan with fused dt-projection ----------------
// grid (6, BATCH, NDIR) = 96 blocks, 256 threads: 64 channels x 4 state-groups of 4.
#define SCH 16
__global__ __launch_bounds__(256) void scan_kernel(
    const float* __restrict__ Alog, const float* __restrict__ Dp,
    const float* __restrict__ Wdt, const float* __restrict__ bdt)
{
    const int d = blockIdx.z, b = blockIdx.y;
    const int c0 = blockIdx.x << 6;
    const int tid = threadIdx.x;
    const int cl = tid >> 2;        // 0..63 local channel
    const int sg = tid & 3;         // states sg*4..sg*4+3
    const int c = c0 + cl;
    const long baseI = ((long)d * BATCH + b) * NSEQ;

    const bf16* xb   = g_xsm_h + baseI * DI       + c0;
    const bf16* zb   = g_xz_h  + baseI * (2 * DI) + DI + c0;
    const float* dblp = g_dbl + baseI * DBL_W;
    bf16* yb          = g_y_h + baseI * DI        + c0;

    __shared__ float s_wdt[64 * 13];
    __shared__ float s_bdt[64];
    __shared__ float s_raw[SCH * 12];
    __shared__ float s_bc [SCH * 32];
    __shared__ float s_dt [SCH * 64];
    __shared__ float s_x  [SCH * 64];
    __shared__ float s_g  [SCH * 64];

    for (int i = tid; i < 64 * DR; i += 256)
        s_wdt[(i / DR) * 13 + (i % DR)] = Wdt[((long)(d * DI + c0) + i / DR) * DR + (i % DR)];
    if (tid < 64) s_bdt[tid] = bdt[d * DI + c0 + tid];

    const float LOG2E = 1.44269504088896340736f;
    float Aa[4];
#pragma unroll
    for (int s = 0; s < 4; s++)
        Aa[s] = -expf(Alog[((long)(d * DI + c)) * DS + (sg << 2) + s]) * LOG2E;
    const float Dv = Dp[d * DI + c];

    float h[4];
#pragma unroll
    for (int s = 0; s < 4; s++) h[s] = 0.f;

    __syncthreads();

    for (int t0 = 0; t0 < NSEQ; t0 += SCH) {
        __syncthreads();
        if (tid < SCH * DR) s_raw[tid] = dblp[(long)(t0 + tid / DR) * DBL_W + (tid % DR)];
#pragma unroll
        for (int k = 0; k < 2; k++) {      // B,C: 16x32 = 512
            const int idx = tid + (k << 8);
            const int row = idx >> 5, col = idx & 31;
            s_bc[idx] = dblp[(long)(t0 + row) * DBL_W + DR + col];
        }
#pragma unroll
        for (int k = 0; k < 4; k++) {      // x, gate: 16x64 = 1024
            const int idx = tid + (k << 8);
            const int row = idx >> 6, col = idx & 63;
            s_x[idx] = __bfloat162float(xb[(long)(t0 + row) * DI + col]);
            const float zv = __bfloat162float(zb[(long)(t0 + row) * (2 * DI) + col]);
            s_g[idx] = zv / (1.f + __expf(-zv));
        }
        __syncthreads();
#pragma unroll
        for (int k = 0; k < 4; k++) {      // dt: 16x64
            const int idx = tid + (k << 8);
            const int row = idx >> 6, col = idx & 63;
            float v = s_bdt[col];
#pragma unroll
            for (int j = 0; j < DR; j++)
                v = fmaf(s_raw[row * DR + j], s_wdt[col * 13 + j], v);
            s_dt[idx] = (v > 20.f) ? v : log1pf(__expf(v));
        }
        __syncthreads();

#pragma unroll
        for (int tt = 0; tt < SCH; tt++) {
            const float dt_v = s_dt[(tt << 6) + cl];
            const float x_v  = s_x [(tt << 6) + cl];
            const float* bc = s_bc + (tt << 5);
            const float dtx = dt_v * x_v;
            float accv = 0.f;
#pragma unroll
            for (int s = 0; s < 4; s++) {
                const float dA = exp2f(dt_v * Aa[s]);
                h[s] = fmaf(dA, h[s], dtx * bc[(sg << 2) + s]);
                accv = fmaf(h[s], bc[16 + (sg << 2) + s], accv);
            }
            accv += __shfl_down_sync(0xffffffffu, accv, 2, 4);
            accv += __shfl_down_sync(0xffffffffu, accv, 1, 4);
            if (sg == 0) {
                float yv = fmaf(x_v, Dv, accv);
                yv *= s_g[(tt << 6) + cl];
                yb[(long)(t0 + tt) * DI + cl] = __float2bfloat16(yv);
            }
        }
    }
}

// ---------------- combine o_proj into ffn2 ----------------
__global__ __launch_bounds__(256) void combine_w_kernel(
    const float* __restrict__ o_w, const float* __restrict__ o_b,
    const float* __restrict__ f_w2, const float* __restrict__ f_b2)
{
    const int i = blockIdx.x;
    __shared__ float s_ow[DM];
    __shared__ float red[256];
    for (int j = threadIdx.x; j < DM; j += 256) s_ow[j] = o_w[i * DM + j];
    __syncthreads();

    for (int k = threadIdx.x; k < 2 * DM; k += 256) {
        float acc = 0.f;
        for (int j = 0; j < DM; j++)
            acc = fmaf(s_ow[j], f_w2[j * (2 * DM) + k], acc);
        g_cw_h[i * (2 * DM) + k] = __float2bfloat16(acc);
    }
    float pb = 0.f;
    for (int j = threadIdx.x; j < DM; j += 256) pb = fmaf(s_ow[j], f_b2[j], pb);
    red[threadIdx.x] = pb;
    __syncthreads();
    for (int st = 128; st > 0; st >>= 1) {
        if (threadIdx.x < st) red[threadIdx.x] += red[threadIdx.x + st];
        __syncthreads();
    }
    if (threadIdx.x == 0) g_cb[i] = red[0] + o_b[i];
}

// ---------------- final layernorm + residual + transpose-out ----------------
__global__ __launch_bounds__(256) void ln2_kernel(
    const float* __restrict__ g, const float* __restrict__ bb, float* __restrict__ out)
{
    __shared__ float t1[16][193];
    __shared__ float t2[16][193];
    __shared__ float s_mean[16], s_rstd[16];
    const int b = blockIdx.y, n0 = blockIdx.x << 4;
    const int tid = threadIdx.x;

    for (int i = tid; i < 16 * DM; i += 256) {
        int nn = i / DM, dd = i % DM;
        long adr = ((long)(b << 10) + n0 + nn) * DM + dd;
        t1[nn][dd] = g_h3[adr];
        t2[nn][dd] = g_xs[adr];
    }
    __syncthreads();

    const int nn = tid >> 4, l = tid & 15;
    float s = 0.f, s2 = 0.f;
    for (int dd = l; dd < DM; dd += 16) { float v = t1[nn][dd]; s += v; s2 = fmaf(v, v, s2); }
    s  += __shfl_down_sync(0xffffffffu, s,  8, 16);
    s2 += __shfl_down_sync(0xffffffffu, s2, 8, 16);
    s  += __shfl_down_sync(0xffffffffu, s,  4, 16);
    s2 += __shfl_down_sync(0xffffffffu, s2, 4, 16);
    s  += __shfl_down_sync(0xffffffffu, s,  2, 16);
    s2 += __shfl_down_sync(0xffffffffu, s2, 2, 16);
    s  += __shfl_down_sync(0xffffffffu, s,  1, 16);
    s2 += __shfl_down_sync(0xffffffffu, s2, 1, 16);
    if (l == 0) {
        float m = s * (1.f / DM);
        float var = s2 * (1.f / DM) - m * m;
        s_mean[nn] = m;
        s_rstd[nn] = rsqrtf(var + 1e-5f);
    }
    __syncthreads();

    for (int i = tid; i < DM * 16; i += 256) {
        int dd = i >> 4, nn2 = i & 15;
        float v = (t1[nn2][dd] - s_mean[nn2]) * s_rstd[nn2] * g[dd] + bb[dd] + t2[nn2][dd];
        out[((long)(b * DM + dd) << 10) + n0 + nn2] = v;
    }
}

// ---------------- launcher ----------------
extern "C" void kernel_launch(void* const* d_in, const int* in_sizes, int n_in,
                              void* d_out, int out_size)
{
    const float* x        = (const float*)d_in[0];
    const float* norm_g   = (const float*)d_in[1];
    const float* norm_b   = (const float*)d_in[2];
    const float* in_w     = (const float*)d_in[3];
    const float* in_b     = (const float*)d_in[4];
    const float* m_in_w   = (const float*)d_in[5];
    const float* m_conv_w = (const float*)d_in[6];
    const float* m_conv_b = (const float*)d_in[7];
    const float* m_xp_w   = (const float*)d_in[8];
    const float* m_dt_w   = (const float*)d_in[9];
    const float* m_dt_b   = (const float*)d_in[10];
    const float* m_Alog   = (const float*)d_in[11];
    const float* m_D      = (const float*)d_in[12];
    const float* m_out_w  = (const float*)d_in[13];
    const float* f_w1     = (const float*)d_in[14];
    const float* f_b1     = (const float*)d_in[15];
    const float* f_w2     = (const float*)d_in[16];
    const float* f_b2     = (const float*)d_in[17];
    const float* o_w      = (const float*)d_in[18];
    const float* o_b      = (const float*)d_in[19];
    const float* on_g     = (const float*)d_in[20];
    const float* on_b     = (const float*)d_in[21];
    float* out = (float*)d_out;

    float *p_dbl, *p_h3, *p_cb;
    bf16 *p_xs_h, *p_xp_h, *p_xz_h, *p_xsm_h, *p_y_h, *p_fused_h, *p_hdn_h;
    bf16 *p_w_in, *p_w_inproj, *p_w_xp, *p_w_out, *p_w_f1, *p_cw_h;
    cudaGetSymbolAddress((void**)&p_dbl, g_dbl);
    cudaGetSymbolAddress((void**)&p_h3, g_h3);
    cudaGetSymbolAddress((void**)&p_cb, g_cb);
    cudaGetSymbolAddress((void**)&p_xs_h, g_xs_h);
    cudaGetSymbolAddress((void**)&p_xp_h, g_xp_h);
    cudaGetSymbolAddress((void**)&p_xz_h, g_xz_h);
    cudaGetSymbolAddress((void**)&p_xsm_h, g_xsm_h);
    cudaGetSymbolAddress((void**)&p_y_h, g_y_h);
    cudaGetSymbolAddress((void**)&p_fused_h, g_fused_h);
    cudaGetSymbolAddress((void**)&p_hdn_h, g_hdn_h);
    cudaGetSymbolAddress((void**)&p_w_in, g_w_in_h);
    cudaGetSymbolAddress((void**)&p_w_inproj, g_w_inproj_h);
    cudaGetSymbolAddress((void**)&p_w_xp, g_w_xp_h);
    cudaGetSymbolAddress((void**)&p_w_out, g_w_out_h);
    cudaGetSymbolAddress((void**)&p_w_f1, g_w_f1_h);
    cudaGetSymbolAddress((void**)&p_cw_h, g_cw_h);

    const int n_w = DM*DM + NDIR*2*DI*DM + NDIR*DBL_W*DI + NDIR*DM*DI + 2*DM*4*DM;

    // 1) weight conversion
    convert_w_kernel<<<(n_w + 255) / 256, 256>>>(in_w, m_in_w, m_xp_w, m_out_w, f_w1);

    // 2) layernorm + transpose
    ln1_kernel<<<dim3(32, 4), 256>>>(x, norm_g, norm_b);

    // 3) xp = xs @ in_w^T + in_b  (64x64 tiles, 192 blocks)
    gemm_bf16_kernel<2, 2><<<dim3(3, 64, 1), 256>>>(p_xs_h, p_w_in, in_b, p_xp_h,
        LROWS, DM, DM, DM, DM, 0, 0, 0, 0, 0, 0, 1);

    // 4) xz[d] = gather_d(xp) @ m_in_w[d]^T  (128x128 tiles, 768 blocks)
    gemm_bf16_kernel<4, 4><<<dim3(6, 32, 4), 256>>>(p_xp_h, p_w_inproj, nullptr, p_xz_h,
        LROWS, 2 * DI, DM, DM, 2 * DI,
        0, (long)2 * DI * DM, 0, (long)LROWS * 2 * DI, 0, 1, 1);

    // 5) causal depthwise conv + silu
    conv_silu_kernel<<<1536, 256>>>(m_conv_w, m_conv_b);

    // 6) dbl[d] = xsm[d] @ m_xp_w[d]^T  (64x64 tiles, 256 blocks)
    gemm_bf16_kernel<2, 2><<<dim3(1, 64, 4), 256>>>(p_xsm_h, p_w_xp, nullptr, p_dbl,
        LROWS, DBL_W, DI, DI, DBL_W,
        (long)LROWS * DI, (long)DBL_W * DI, 0, (long)LROWS * DBL_W, 0, 0, 0);

    // 7) selective scan (96 blocks x 256 threads)
    scan_kernel<<<dim3(6, BATCH, NDIR), 256>>>(m_Alog, m_D, m_dt_w, m_dt_b);

    // 8) fused[:, d*DM:(d+1)*DM] = scatter_d(y[d] @ m_out_w[d]^T)  (128x64 tiles, 384 blocks)
    gemm_bf16_kernel<4, 2><<<dim3(3, 32, 4), 256>>>(p_y_h, p_w_out, nullptr, p_fused_h,
        LROWS, DM, DI, DI, 4 * DM,
        (long)LROWS * DI, (long)DM * DI, 0, (long)DM, 0, 2, 1);

    // 9) hdn = gelu(fused @ f_w1^T + f_b1)  (128x64 tiles, 192 blocks)
    gemm_bf16_kernel<4, 2><<<dim3(6, 32, 1), 256>>>(p_fused_h, p_w_f1, f_b1, p_hdn_h,
        LROWS, 2 * DM, 4 * DM, 4 * DM, 2 * DM, 0, 0, 0, 0, 2, 0, 1);

    // 10) combined weight: Wc = o_w @ f_w2 (bf16), bc = o_w @ f_b2 + o_b
    combine_w_kernel<<<DM, 256>>>(o_w, o_b, f_w2, f_b2);

    // 11) h3 = hdn @ Wc^T + bc  (64x64 tiles, 192 blocks)
    gemm_bf16_kernel<2, 2><<<dim3(3, 64, 1), 256>>>(p_hdn_h, p_cw_h, p_cb, p_h3,
        LROWS, DM, 2 * DM, 2 * DM, DM, 0, 0, 0, 0, 0, 0, 0);

    // 12) final layernorm + residual + transpose out
    ln2_kernel<<<dim3(64, 4), 256>>>(on_g, on_b, out);
}